// round 2
// baseline (speedup 1.0000x reference)
#include <cuda_runtime.h>
#include <math.h>

#define TPB 256

namespace {

constexpr int N  = 64;    // nodes
constexpr int F  = 128;   // features
constexpr int H  = 2;     // heads
constexpr int DH = 64;    // feats per head
constexpr int QP = 132;   // padded row length for q/k/v (bank-conflict mitigation)
constexpr float NEGV = -1e9f;
constexpr float INV_SQRT_DH = 0.125f;   // 1/sqrt(64)

struct __align__(16) Smem {
  float h [N][F];      // node features
  float hn[N][F];      // layernorm output / msg buffer
  float q [N][QP];
  float k [N][QP];
  float v [N][QP];
  float att[H][N][N];  // logits -> attn
  float wbuf[16][F];   // staged weight K-slice
  float coords[N][3];
  float mrow[N];       // mask as 0/1 float
  float bf_l[F];
  float We_l[7][2];
};

// C[64][128] (+)= A[64][128] @ W[128][128], A in smem, W in global (staged to smem).
// Thread (rg, cg): rows r0..r0+3, cols cg*4..+3 and cg*4+64..+3.
__device__ __forceinline__ void gemm_64x128x128(
    const float (*A)[F], const float* __restrict__ Wg,
    float (*wbuf)[F], int tid, float acc[4][8])
{
  const int rg = tid >> 4;
  const int cg = tid & 15;
  const int r0 = rg << 2;
  const int cA = cg << 2;
  const int cB = cA + 64;

#pragma unroll
  for (int i = 0; i < 4; ++i)
#pragma unroll
    for (int j = 0; j < 8; ++j) acc[i][j] = 0.f;

  const float4* __restrict__ Wg4 = (const float4*)Wg;
  float4* wb4 = (float4*)&wbuf[0][0];

  for (int k0 = 0; k0 < F; k0 += 16) {
    __syncthreads();   // protect wbuf readers from previous slice
    {
      int idx = tid;                                   // 0..255
      wb4[idx] = Wg4[(k0 + (idx >> 5)) * 32 + (idx & 31)];
      idx += TPB;                                      // 256..511
      wb4[idx] = Wg4[(k0 + (idx >> 5)) * 32 + (idx & 31)];
    }
    __syncthreads();
#pragma unroll
    for (int kk = 0; kk < 16; ++kk) {
      float av[4];
      av[0] = A[r0 + 0][k0 + kk];
      av[1] = A[r0 + 1][k0 + kk];
      av[2] = A[r0 + 2][k0 + kk];
      av[3] = A[r0 + 3][k0 + kk];
      float bv[8];
      *(float4*)&bv[0] = *(const float4*)&wbuf[kk][cA];
      *(float4*)&bv[4] = *(const float4*)&wbuf[kk][cB];
#pragma unroll
      for (int i = 0; i < 4; ++i)
#pragma unroll
        for (int j = 0; j < 8; ++j)
          acc[i][j] += av[i] * bv[j];
    }
  }
}

__device__ __forceinline__ void layer_norm_smem(
    const float (*src)[F], float (*dst)[F], int tid)
{
  const int w = tid >> 5, lane = tid & 31;
  for (int n = w; n < N; n += 8) {
    float x0 = src[n][lane], x1 = src[n][lane + 32];
    float x2 = src[n][lane + 64], x3 = src[n][lane + 96];
    float sm = x0 + x1 + x2 + x3;
#pragma unroll
    for (int o = 16; o; o >>= 1) sm += __shfl_xor_sync(0xffffffffu, sm, o);
    float mean = sm * (1.f / 128.f);
    float d0 = x0 - mean, d1 = x1 - mean, d2 = x2 - mean, d3 = x3 - mean;
    float ss = d0 * d0 + d1 * d1 + d2 * d2 + d3 * d3;
#pragma unroll
    for (int o = 16; o; o >>= 1) ss += __shfl_xor_sync(0xffffffffu, ss, o);
    float inv = rsqrtf(ss * (1.f / 128.f) + 1e-5f);
    dst[n][lane]      = d0 * inv;
    dst[n][lane + 32] = d1 * inv;
    dst[n][lane + 64] = d2 * inv;
    dst[n][lane + 96] = d3 * inv;
  }
}

__global__ void __launch_bounds__(TPB, 1) gnn_kernel(
    const float* __restrict__ g_coords,          // [B,N,3]
    const int*   __restrict__ g_species,         // [B,N]
    const int*   __restrict__ g_mask,            // [B,N] bool widened to int32
    const float* __restrict__ g_embed,           // [100,F]
    const float* __restrict__ g_Wq,              // [3,F,F]
    const float* __restrict__ g_Wk,
    const float* __restrict__ g_Wv,
    const float* __restrict__ g_Wo,
    const float* __restrict__ g_We,              // [3,7,2]
    const float* __restrict__ g_Wf,
    const float* __restrict__ g_bf,              // [3,F]
    float* __restrict__ g_out)                   // [B,N,F]
{
  extern __shared__ unsigned char smem_raw[];
  Smem& s = *reinterpret_cast<Smem*>(smem_raw);
  const int b = blockIdx.x;
  const int tid = threadIdx.x;

  // ---- load per-batch inputs ----
  if (tid < N) {
    s.mrow[tid] = (g_mask[b * N + tid] != 0) ? 1.f : 0.f;
    s.coords[tid][0] = g_coords[(b * N + tid) * 3 + 0];
    s.coords[tid][1] = g_coords[(b * N + tid) * 3 + 1];
    s.coords[tid][2] = g_coords[(b * N + tid) * 3 + 2];
  }
  for (int i = tid; i < N * F; i += TPB) {
    int n = i >> 7, f = i & (F - 1);
    int sp = g_species[b * N + n] - 1;
    float hv = g_embed[sp * F + f];
    s.h[n][f] = (g_mask[b * N + n] != 0) ? hv : 0.f;
  }
  __syncthreads();

  const int rg = tid >> 4;
  const int cg = tid & 15;
  const int r0 = rg << 2;
  const int cA = cg << 2;
  const int cB = cA + 64;

  float acc[4][8];

  for (int l = 0; l < 3; ++l) {
    // per-layer small constants
    if (tid < F) s.bf_l[tid] = g_bf[l * F + tid];
    if (tid >= 128 && tid < 128 + 14)
      ((float*)s.We_l)[tid - 128] = g_We[l * 14 + (tid - 128)];

    // hn = LN(h)
    layer_norm_smem(s.h, s.hn, tid);
    __syncthreads();

    // q, k, v = hn @ Wq/Wk/Wv
    gemm_64x128x128(s.hn, g_Wq + l * F * F, s.wbuf, tid, acc);
#pragma unroll
    for (int i = 0; i < 4; ++i)
#pragma unroll
      for (int j = 0; j < 4; ++j) {
        s.q[r0 + i][cA + j] = acc[i][j];
        s.q[r0 + i][cB + j] = acc[i][4 + j];
      }
    gemm_64x128x128(s.hn, g_Wk + l * F * F, s.wbuf, tid, acc);
#pragma unroll
    for (int i = 0; i < 4; ++i)
#pragma unroll
      for (int j = 0; j < 4; ++j) {
        s.k[r0 + i][cA + j] = acc[i][j];
        s.k[r0 + i][cB + j] = acc[i][4 + j];
      }
    gemm_64x128x128(s.hn, g_Wv + l * F * F, s.wbuf, tid, acc);
#pragma unroll
    for (int i = 0; i < 4; ++i)
#pragma unroll
      for (int j = 0; j < 4; ++j) {
        s.v[r0 + i][cA + j] = acc[i][j];
        s.v[r0 + i][cB + j] = acc[i][4 + j];
      }
    __syncthreads();

    // logits[h][n][m] = q_h(n) . k_h(m)   (scale+bias applied in next pass)
    for (int task = tid; task < H * N * 16; task += TPB) {
      int hh = task >> 10;
      int n  = (task >> 4) & 63;
      int mg = task & 15;
      const float* qn = &s.q[n][hh * DH];
      float a0 = 0.f, a1 = 0.f, a2 = 0.f, a3 = 0.f;
#pragma unroll 16
      for (int d = 0; d < DH; ++d) {
        float a = qn[d];
        a0 += a * s.k[mg +  0][hh * DH + d];
        a1 += a * s.k[mg + 16][hh * DH + d];
        a2 += a * s.k[mg + 32][hh * DH + d];
        a3 += a * s.k[mg + 48][hh * DH + d];
      }
      s.att[hh][n][mg +  0] = a0;
      s.att[hh][n][mg + 16] = a1;
      s.att[hh][n][mg + 32] = a2;
      s.att[hh][n][mg + 48] = a3;
    }
    __syncthreads();

    // scale + edge bias + mask (edge features recomputed from coords)
    for (int p = tid; p < N * N; p += TPB) {
      int n = p >> 6, m = p & 63;
      float dx = s.coords[n][0] - s.coords[m][0];
      float dy = s.coords[n][1] - s.coords[m][1];
      float dz = s.coords[n][2] - s.coords[m][2];
      float d = sqrtf(dx * dx + dy * dy + dz * dz + 1e-12f);
      float s1 = 1.f / (1.f + __expf(2.f - d));   // sigmoid(d-2)
      float s2 = 1.f / (1.f + __expf(4.f - d));
      float s3 = 1.f / (1.f + __expf(6.f - d));
      bool ok = (s.mrow[n] > 0.f) && (s.mrow[m] > 0.f);
#pragma unroll
      for (int hh = 0; hh < H; ++hh) {
        float bias = dx * s.We_l[0][hh] + dy * s.We_l[1][hh] + dz * s.We_l[2][hh]
                   + d  * s.We_l[3][hh] + s1 * s.We_l[4][hh]
                   + s2 * s.We_l[5][hh] + s3 * s.We_l[6][hh];
        s.att[hh][n][m] = ok ? (s.att[hh][n][m] * INV_SQRT_DH + bias) : NEGV;
      }
    }
    __syncthreads();

    // softmax over m for each (h, n)
    {
      const int w = tid >> 5, lane = tid & 31;
      for (int row = w; row < H * N; row += 8) {
        int hh = row >> 6, n = row & 63;
        float x0 = s.att[hh][n][lane], x1 = s.att[hh][n][lane + 32];
        float mx = fmaxf(x0, x1);
#pragma unroll
        for (int o = 16; o; o >>= 1) mx = fmaxf(mx, __shfl_xor_sync(0xffffffffu, mx, o));
        float e0 = __expf(x0 - mx), e1 = __expf(x1 - mx);
        float sm = e0 + e1;
#pragma unroll
        for (int o = 16; o; o >>= 1) sm += __shfl_xor_sync(0xffffffffu, sm, o);
        float inv = 1.f / sm;
        s.att[hh][n][lane]      = e0 * inv;
        s.att[hh][n][lane + 32] = e1 * inv;
      }
    }
    __syncthreads();

    // msg = attn @ v (per head) -> hn
    {
      const int c0 = cg << 2;   // 0..60
#pragma unroll
      for (int hh = 0; hh < H; ++hh) {
        float macc[4][4];
#pragma unroll
        for (int i = 0; i < 4; ++i)
#pragma unroll
          for (int j = 0; j < 4; ++j) macc[i][j] = 0.f;
        for (int m = 0; m < N; ++m) {
          float av[4];
          av[0] = s.att[hh][r0 + 0][m];
          av[1] = s.att[hh][r0 + 1][m];
          av[2] = s.att[hh][r0 + 2][m];
          av[3] = s.att[hh][r0 + 3][m];
          float bv[4];
          bv[0] = s.v[m][hh * DH + c0 + 0];
          bv[1] = s.v[m][hh * DH + c0 + 1];
          bv[2] = s.v[m][hh * DH + c0 + 2];
          bv[3] = s.v[m][hh * DH + c0 + 3];
#pragma unroll
          for (int i = 0; i < 4; ++i)
#pragma unroll
            for (int j = 0; j < 4; ++j) macc[i][j] += av[i] * bv[j];
        }
#pragma unroll
        for (int i = 0; i < 4; ++i)
#pragma unroll
          for (int j = 0; j < 4; ++j)
            s.hn[r0 + i][hh * DH + c0 + j] = macc[i][j];
      }
    }
    __syncthreads();

    // h += msg @ Wo
    gemm_64x128x128(s.hn, g_Wo + l * F * F, s.wbuf, tid, acc);
#pragma unroll
    for (int i = 0; i < 4; ++i)
#pragma unroll
      for (int j = 0; j < 4; ++j) {
        s.h[r0 + i][cA + j] += acc[i][j];
        s.h[r0 + i][cB + j] += acc[i][4 + j];
      }
    __syncthreads();

    // h = (h + tanh(LN(h) @ Wf + bf)) * mask
    layer_norm_smem(s.h, s.hn, tid);
    __syncthreads();
    gemm_64x128x128(s.hn, g_Wf + l * F * F, s.wbuf, tid, acc);
#pragma unroll
    for (int i = 0; i < 4; ++i) {
      float mr = s.mrow[r0 + i];
#pragma unroll
      for (int j = 0; j < 4; ++j) {
        s.h[r0 + i][cA + j] = (s.h[r0 + i][cA + j] + tanhf(acc[i][j]     + s.bf_l[cA + j])) * mr;
        s.h[r0 + i][cB + j] = (s.h[r0 + i][cB + j] + tanhf(acc[i][4 + j] + s.bf_l[cB + j])) * mr;
      }
    }
    __syncthreads();
  }

  // final layernorm -> global output
  {
    const int w = tid >> 5, lane = tid & 31;
    for (int n = w; n < N; n += 8) {
      float x0 = s.h[n][lane], x1 = s.h[n][lane + 32];
      float x2 = s.h[n][lane + 64], x3 = s.h[n][lane + 96];
      float sm = x0 + x1 + x2 + x3;
#pragma unroll
      for (int o = 16; o; o >>= 1) sm += __shfl_xor_sync(0xffffffffu, sm, o);
      float mean = sm * (1.f / 128.f);
      float d0 = x0 - mean, d1 = x1 - mean, d2 = x2 - mean, d3 = x3 - mean;
      float ss = d0 * d0 + d1 * d1 + d2 * d2 + d3 * d3;
#pragma unroll
      for (int o = 16; o; o >>= 1) ss += __shfl_xor_sync(0xffffffffu, ss, o);
      float inv = rsqrtf(ss * (1.f / 128.f) + 1e-5f);
      float* orow = g_out + (size_t)(b * N + n) * F;
      orow[lane]      = d0 * inv;
      orow[lane + 32] = d1 * inv;
      orow[lane + 64] = d2 * inv;
      orow[lane + 96] = d3 * inv;
    }
  }
}

}  // namespace

extern "C" void kernel_launch(void* const* d_in, const int* in_sizes, int n_in,
                              void* d_out, int out_size)
{
  (void)n_in; (void)out_size;
  const float* coords  = (const float*)d_in[0];
  const int*   species = (const int*)d_in[1];
  const int*   mask    = (const int*)d_in[2];
  const float* embed   = (const float*)d_in[3];
  const float* Wq      = (const float*)d_in[4];
  const float* Wk      = (const float*)d_in[5];
  const float* Wv      = (const float*)d_in[6];
  const float* Wo      = (const float*)d_in[7];
  const float* We      = (const float*)d_in[8];
  const float* Wf      = (const float*)d_in[9];
  const float* bf      = (const float*)d_in[10];

  const int B = in_sizes[0] / (N * 3);   // 2048

  cudaFuncSetAttribute(gnn_kernel, cudaFuncAttributeMaxDynamicSharedMemorySize,
                       (int)sizeof(Smem));
  gnn_kernel<<<B, TPB, sizeof(Smem)>>>(coords, species, mask, embed,
                                       Wq, Wk, Wv, Wo, We, Wf, bf,
                                       (float*)d_out);
}

// round 5
// speedup vs baseline: 1.3860x; 1.3860x over previous
#include <cuda_runtime.h>
#include <cuda_bf16.h>
#include <stdint.h>
#include <math.h>

#define TPB 256

namespace {

constexpr int N  = 64;    // nodes
constexpr int F  = 128;   // features
constexpr int H  = 2;     // heads
constexpr int DH = 64;    // feats per head
constexpr int QP = 132;   // padded row length for q/k/v
constexpr int APAD = 68;  // packed-A row stride (uint32 words, 64 kpairs + pad)
constexpr int WPAD = 136; // staged-W row stride (uint32 words, 128 n + pad)
constexpr float NEGV = -1e9f;
constexpr float INV_SQRT_DH = 0.125f;   // 1/sqrt(64)

// Pre-split weights: [15 matrices][64 kpairs][128 n], bf16x2 (k even in low half)
__device__ uint32_t g_whp[15 * 64 * 128];
__device__ uint32_t g_wlp[15 * 64 * 128];

struct __align__(16) Smem {
  float h [N][F];        // node features
  float q [N][QP];
  float k [N][QP];
  float v [N][QP];
  float att[H][N][N];    // logits -> attn
  uint32_t ahp[N][APAD]; // packed bf16x2 A operand (hi part)
  uint32_t alp[N][APAD]; // packed bf16x2 A operand (lo part)
  uint32_t swh[16][WPAD]; // staged weight slice (hi)
  uint32_t swl[16][WPAD]; // staged weight slice (lo)
  float coords[N][3];
  float mrow[N];
  float bf_l[F];
  float We_l[7][2];
};

__device__ __forceinline__ void mma_bf16(float* d,
    uint32_t a0, uint32_t a1, uint32_t a2, uint32_t a3,
    uint32_t b0, uint32_t b1)
{
  asm volatile(
    "mma.sync.aligned.m16n8k16.row.col.f32.bf16.bf16.f32 "
    "{%0,%1,%2,%3}, {%4,%5,%6,%7}, {%8,%9}, {%0,%1,%2,%3};\n"
    : "+f"(d[0]), "+f"(d[1]), "+f"(d[2]), "+f"(d[3])
    : "r"(a0), "r"(a1), "r"(a2), "r"(a3), "r"(b0), "r"(b1));
}

// Split-pack two fp32 values into bf16x2 hi/lo words (low half = first value).
__device__ __forceinline__ void pack2(float x, float y,
                                      uint32_t* hp, uint32_t* lp)
{
  __nv_bfloat162 h2 = __floats2bfloat162_rn(x, y);
  float hx = __bfloat162float(h2.x), hy = __bfloat162float(h2.y);
  __nv_bfloat162 l2 = __floats2bfloat162_rn(x - hx, y - hy);
  *hp = *reinterpret_cast<uint32_t*>(&h2);
  *lp = *reinterpret_cast<uint32_t*>(&l2);
}

// LN over rows of src (stride F), result split-packed into ahp/alp.
__device__ __forceinline__ void ln_split(const float (*src)[F],
    uint32_t (*ahp)[APAD], uint32_t (*alp)[APAD], int tid)
{
  const int w = tid >> 5, l = tid & 31;
  for (int n = w; n < N; n += 8) {
    float2 p0 = *(const float2*)&src[n][2 * l];
    float2 p1 = *(const float2*)&src[n][64 + 2 * l];
    float sm = p0.x + p0.y + p1.x + p1.y;
#pragma unroll
    for (int o = 16; o; o >>= 1) sm += __shfl_xor_sync(0xffffffffu, sm, o);
    float mean = sm * (1.f / 128.f);
    float d0 = p0.x - mean, d1 = p0.y - mean, d2 = p1.x - mean, d3 = p1.y - mean;
    float ss = d0 * d0 + d1 * d1 + d2 * d2 + d3 * d3;
#pragma unroll
    for (int o = 16; o; o >>= 1) ss += __shfl_xor_sync(0xffffffffu, ss, o);
    float inv = rsqrtf(ss * (1.f / 128.f) + 1e-5f);
    d0 *= inv; d1 *= inv; d2 *= inv; d3 *= inv;
    pack2(d0, d1, &ahp[n][l],      &alp[n][l]);
    pack2(d2, d3, &ahp[n][l + 32], &alp[n][l + 32]);
  }
}

// C[64][128] = A[64][128] @ W[128][128] via bf16-split mma.
// A pre-split in ahp/alp; W pre-split in global gWh/gWl ([64 kpairs][128 n]).
// Warp w: rows (w&3)*16..+15, cols (w>>2)*64..+63 (8 n8-tiles).
__device__ __forceinline__ void gemm_mma(
    const uint32_t (*ahp)[APAD], const uint32_t (*alp)[APAD],
    const uint32_t* __restrict__ gWh, const uint32_t* __restrict__ gWl,
    uint32_t (*swh)[WPAD], uint32_t (*swl)[WPAD],
    int tid, float acc[8][4])
{
  const int warp = tid >> 5, lane = tid & 31;
  const int mb = (warp & 3) << 4;
  const int nb = (warp >> 2) << 6;
  const int lm = lane >> 2, tig = lane & 3;

#pragma unroll
  for (int t = 0; t < 8; ++t)
#pragma unroll
    for (int i = 0; i < 4; ++i) acc[t][i] = 0.f;

  for (int ks = 0; ks < 4; ++ks) {   // 16 kpairs (32 k) per slice
    __syncthreads();
    {
      const uint4* gh = (const uint4*)(gWh + ks * 16 * 128);
      const uint4* gl = (const uint4*)(gWl + ks * 16 * 128);
#pragma unroll
      for (int i = tid; i < 512; i += TPB) {
        int row = i >> 5, c = i & 31;
        ((uint4*)&swh[row][0])[c] = gh[i];
        ((uint4*)&swl[row][0])[c] = gl[i];
      }
    }
    __syncthreads();
#pragma unroll
    for (int half = 0; half < 2; ++half) {
      const int kp0 = ks * 16 + half * 8;   // absolute kpair base for this k-step
      const int kpl = half * 8;             // local row in slice
      uint32_t ah0 = ahp[mb + lm    ][kp0 + tig];
      uint32_t ah1 = ahp[mb + lm + 8][kp0 + tig];
      uint32_t ah2 = ahp[mb + lm    ][kp0 + tig + 4];
      uint32_t ah3 = ahp[mb + lm + 8][kp0 + tig + 4];
      uint32_t al0 = alp[mb + lm    ][kp0 + tig];
      uint32_t al1 = alp[mb + lm + 8][kp0 + tig];
      uint32_t al2 = alp[mb + lm    ][kp0 + tig + 4];
      uint32_t al3 = alp[mb + lm + 8][kp0 + tig + 4];
#pragma unroll
      for (int t = 0; t < 8; ++t) {
        const int n0 = nb + t * 8 + lm;
        uint32_t bh0 = swh[kpl + tig    ][n0];
        uint32_t bh1 = swh[kpl + tig + 4][n0];
        uint32_t bl0 = swl[kpl + tig    ][n0];
        uint32_t bl1 = swl[kpl + tig + 4][n0];
        mma_bf16(acc[t], ah0, ah1, ah2, ah3, bh0, bh1);
        mma_bf16(acc[t], ah0, ah1, ah2, ah3, bl0, bl1);
        mma_bf16(acc[t], al0, al1, al2, al3, bh0, bh1);
      }
    }
  }
}

__global__ void __launch_bounds__(TPB, 1) gnn_kernel(
    const float* __restrict__ g_coords,          // [B,N,3]
    const int*   __restrict__ g_species,         // [B,N]
    const int*   __restrict__ g_mask,            // [B,N] bool widened to int32
    const float* __restrict__ g_embed,           // [100,F]
    const float* __restrict__ g_We,              // [3,7,2]
    const float* __restrict__ g_bf,              // [3,F]
    float* __restrict__ g_out)                   // [B,N,F]
{
  extern __shared__ unsigned char smem_raw[];
  Smem& s = *reinterpret_cast<Smem*>(smem_raw);
  const int b = blockIdx.x;
  const int tid = threadIdx.x;

  // ---- load per-batch inputs ----
  if (tid < N) {
    s.mrow[tid] = (g_mask[b * N + tid] != 0) ? 1.f : 0.f;
    s.coords[tid][0] = g_coords[(b * N + tid) * 3 + 0];
    s.coords[tid][1] = g_coords[(b * N + tid) * 3 + 1];
    s.coords[tid][2] = g_coords[(b * N + tid) * 3 + 2];
  }
  for (int i = tid; i < N * F; i += TPB) {
    int n = i >> 7, f = i & (F - 1);
    int sp = g_species[b * N + n] - 1;
    float hv = g_embed[sp * F + f];
    s.h[n][f] = (g_mask[b * N + n] != 0) ? hv : 0.f;
  }
  __syncthreads();

  const int warp = tid >> 5, lane = tid & 31;
  const int mb = (warp & 3) << 4;
  const int nb = (warp >> 2) << 6;
  const int lm = lane >> 2, tig = lane & 3;

  // FFMA-attention thread mapping (unchanged from round 2)
  const int rg = tid >> 4;
  const int cg = tid & 15;
  const int r0 = rg << 2;

  float acc[8][4];

  for (int l = 0; l < 3; ++l) {
    if (tid < F) s.bf_l[tid] = g_bf[l * F + tid];
    if (tid >= 128 && tid < 128 + 14)
      ((float*)s.We_l)[tid - 128] = g_We[l * 14 + (tid - 128)];

    const uint32_t* wbase_h = g_whp + (size_t)(l * 5) * 64 * 128;
    const uint32_t* wbase_l = g_wlp + (size_t)(l * 5) * 64 * 128;

    // hn = LN(h), split-packed
    ln_split(s.h, s.ahp, s.alp, tid);
    // (gemm's internal first __syncthreads covers ahp/alp visibility)

    // q, k, v
    gemm_mma(s.ahp, s.alp, wbase_h + 0 * 8192, wbase_l + 0 * 8192, s.swh, s.swl, tid, acc);
#pragma unroll
    for (int t = 0; t < 8; ++t) {
      int c = nb + t * 8 + 2 * tig;
      *(float2*)&s.q[mb + lm    ][c] = make_float2(acc[t][0], acc[t][1]);
      *(float2*)&s.q[mb + lm + 8][c] = make_float2(acc[t][2], acc[t][3]);
    }
    gemm_mma(s.ahp, s.alp, wbase_h + 1 * 8192, wbase_l + 1 * 8192, s.swh, s.swl, tid, acc);
#pragma unroll
    for (int t = 0; t < 8; ++t) {
      int c = nb + t * 8 + 2 * tig;
      *(float2*)&s.k[mb + lm    ][c] = make_float2(acc[t][0], acc[t][1]);
      *(float2*)&s.k[mb + lm + 8][c] = make_float2(acc[t][2], acc[t][3]);
    }
    gemm_mma(s.ahp, s.alp, wbase_h + 2 * 8192, wbase_l + 2 * 8192, s.swh, s.swl, tid, acc);
#pragma unroll
    for (int t = 0; t < 8; ++t) {
      int c = nb + t * 8 + 2 * tig;
      *(float2*)&s.v[mb + lm    ][c] = make_float2(acc[t][0], acc[t][1]);
      *(float2*)&s.v[mb + lm + 8][c] = make_float2(acc[t][2], acc[t][3]);
    }
    __syncthreads();

    // logits[h][n][m] = q_h(n) . k_h(m)
    for (int task = tid; task < H * N * 16; task += TPB) {
      int hh = task >> 10;
      int n  = (task >> 4) & 63;
      int mg = task & 15;
      const float* qn = &s.q[n][hh * DH];
      float a0 = 0.f, a1 = 0.f, a2 = 0.f, a3 = 0.f;
#pragma unroll 16
      for (int d = 0; d < DH; ++d) {
        float a = qn[d];
        a0 += a * s.k[mg +  0][hh * DH + d];
        a1 += a * s.k[mg + 16][hh * DH + d];
        a2 += a * s.k[mg + 32][hh * DH + d];
        a3 += a * s.k[mg + 48][hh * DH + d];
      }
      s.att[hh][n][mg +  0] = a0;
      s.att[hh][n][mg + 16] = a1;
      s.att[hh][n][mg + 32] = a2;
      s.att[hh][n][mg + 48] = a3;
    }
    __syncthreads();

    // scale + edge bias + mask
    for (int p = tid; p < N * N; p += TPB) {
      int n = p >> 6, m = p & 63;
      float dx = s.coords[n][0] - s.coords[m][0];
      float dy = s.coords[n][1] - s.coords[m][1];
      float dz = s.coords[n][2] - s.coords[m][2];
      float d = sqrtf(dx * dx + dy * dy + dz * dz + 1e-12f);
      float s1 = 1.f / (1.f + __expf(2.f - d));
      float s2 = 1.f / (1.f + __expf(4.f - d));
      float s3 = 1.f / (1.f + __expf(6.f - d));
      bool ok = (s.mrow[n] > 0.f) && (s.mrow[m] > 0.f);
#pragma unroll
      for (int hh = 0; hh < H; ++hh) {
        float bias = dx * s.We_l[0][hh] + dy * s.We_l[1][hh] + dz * s.We_l[2][hh]
                   + d  * s.We_l[3][hh] + s1 * s.We_l[4][hh]
                   + s2 * s.We_l[5][hh] + s3 * s.We_l[6][hh];
        s.att[hh][n][m] = ok ? (s.att[hh][n][m] * INV_SQRT_DH + bias) : NEGV;
      }
    }
    __syncthreads();

    // softmax
    {
      const int w = tid >> 5, ln = tid & 31;
      for (int row = w; row < H * N; row += 8) {
        int hh = row >> 6, n = row & 63;
        float x0 = s.att[hh][n][ln], x1 = s.att[hh][n][ln + 32];
        float mx = fmaxf(x0, x1);
#pragma unroll
        for (int o = 16; o; o >>= 1) mx = fmaxf(mx, __shfl_xor_sync(0xffffffffu, mx, o));
        float e0 = __expf(x0 - mx), e1 = __expf(x1 - mx);
        float sm = e0 + e1;
#pragma unroll
        for (int o = 16; o; o >>= 1) sm += __shfl_xor_sync(0xffffffffu, sm, o);
        float inv = 1.f / sm;
        s.att[hh][n][ln]      = e0 * inv;
        s.att[hh][n][ln + 32] = e1 * inv;
      }
    }
    __syncthreads();

    // msg = attn @ v, split-packed directly into ahp/alp
    {
      const int c0 = cg << 2;
#pragma unroll
      for (int hh = 0; hh < H; ++hh) {
        float macc[4][4];
#pragma unroll
        for (int i = 0; i < 4; ++i)
#pragma unroll
          for (int j = 0; j < 4; ++j) macc[i][j] = 0.f;
        for (int m = 0; m < N; ++m) {
          float av[4];
          av[0] = s.att[hh][r0 + 0][m];
          av[1] = s.att[hh][r0 + 1][m];
          av[2] = s.att[hh][r0 + 2][m];
          av[3] = s.att[hh][r0 + 3][m];
          float bv[4];
          bv[0] = s.v[m][hh * DH + c0 + 0];
          bv[1] = s.v[m][hh * DH + c0 + 1];
          bv[2] = s.v[m][hh * DH + c0 + 2];
          bv[3] = s.v[m][hh * DH + c0 + 3];
#pragma unroll
          for (int i = 0; i < 4; ++i)
#pragma unroll
            for (int j = 0; j < 4; ++j) macc[i][j] += av[i] * bv[j];
        }
        const int pb = (hh * DH + c0) >> 1;
#pragma unroll
        for (int i = 0; i < 4; ++i) {
          pack2(macc[i][0], macc[i][1], &s.ahp[r0 + i][pb],     &s.alp[r0 + i][pb]);
          pack2(macc[i][2], macc[i][3], &s.ahp[r0 + i][pb + 1], &s.alp[r0 + i][pb + 1]);
        }
      }
    }
    // (gemm's internal first __syncthreads covers ahp/alp)

    // h += msg @ Wo
    gemm_mma(s.ahp, s.alp, wbase_h + 3 * 8192, wbase_l + 3 * 8192, s.swh, s.swl, tid, acc);
#pragma unroll
    for (int t = 0; t < 8; ++t) {
      int c = nb + t * 8 + 2 * tig;
      float2 h0 = *(float2*)&s.h[mb + lm][c];
      h0.x += acc[t][0]; h0.y += acc[t][1];
      *(float2*)&s.h[mb + lm][c] = h0;
      float2 h1 = *(float2*)&s.h[mb + lm + 8][c];
      h1.x += acc[t][2]; h1.y += acc[t][3];
      *(float2*)&s.h[mb + lm + 8][c] = h1;
    }
    __syncthreads();

    // h = (h + tanh(LN(h) @ Wf + bf)) * mask
    ln_split(s.h, s.ahp, s.alp, tid);
    gemm_mma(s.ahp, s.alp, wbase_h + 4 * 8192, wbase_l + 4 * 8192, s.swh, s.swl, tid, acc);
    {
      float mr0 = s.mrow[mb + lm];
      float mr1 = s.mrow[mb + lm + 8];
#pragma unroll
      for (int t = 0; t < 8; ++t) {
        int c = nb + t * 8 + 2 * tig;
        float2 h0 = *(float2*)&s.h[mb + lm][c];
        h0.x = (h0.x + tanhf(acc[t][0] + s.bf_l[c]))     * mr0;
        h0.y = (h0.y + tanhf(acc[t][1] + s.bf_l[c + 1])) * mr0;
        *(float2*)&s.h[mb + lm][c] = h0;
        float2 h1 = *(float2*)&s.h[mb + lm + 8][c];
        h1.x = (h1.x + tanhf(acc[t][2] + s.bf_l[c]))     * mr1;
        h1.y = (h1.y + tanhf(acc[t][3] + s.bf_l[c + 1])) * mr1;
        *(float2*)&s.h[mb + lm + 8][c] = h1;
      }
    }
    __syncthreads();
  }

  // final layernorm -> global output
  {
    const int w = tid >> 5, ln = tid & 31;
    for (int n = w; n < N; n += 8) {
      float x0 = s.h[n][ln], x1 = s.h[n][ln + 32];
      float x2 = s.h[n][ln + 64], x3 = s.h[n][ln + 96];
      float sm = x0 + x1 + x2 + x3;
#pragma unroll
      for (int o = 16; o; o >>= 1) sm += __shfl_xor_sync(0xffffffffu, sm, o);
      float mean = sm * (1.f / 128.f);
      float d0 = x0 - mean, d1 = x1 - mean, d2 = x2 - mean, d3 = x3 - mean;
      float ss = d0 * d0 + d1 * d1 + d2 * d2 + d3 * d3;
#pragma unroll
      for (int o = 16; o; o >>= 1) ss += __shfl_xor_sync(0xffffffffu, ss, o);
      float inv = rsqrtf(ss * (1.f / 128.f) + 1e-5f);
      float* orow = g_out + (size_t)(b * N + n) * F;
      orow[ln]      = d0 * inv;
      orow[ln + 32] = d1 * inv;
      orow[ln + 64] = d2 * inv;
      orow[ln + 96] = d3 * inv;
    }
  }
}

// Split/pack all 15 weight matrices once: g_whp/g_wlp[mat][kpair][n].
__global__ void prep_weights(const float* __restrict__ Wq,
                             const float* __restrict__ Wk,
                             const float* __restrict__ Wv,
                             const float* __restrict__ Wo,
                             const float* __restrict__ Wf)
{
  int idx = blockIdx.x * blockDim.x + threadIdx.x;
  if (idx >= 15 * 64 * 128) return;
  int mat = idx >> 13;          // /8192
  int kp  = (idx >> 7) & 63;
  int n   = idx & 127;
  int l = mat / 5, which = mat % 5;
  const float* W =
      (which == 0 ? Wq : which == 1 ? Wk : which == 2 ? Wv : which == 3 ? Wo : Wf)
      + l * F * F;
  float v0 = W[(2 * kp)     * F + n];
  float v1 = W[(2 * kp + 1) * F + n];
  __nv_bfloat162 h2 = __floats2bfloat162_rn(v0, v1);
  __nv_bfloat162 l2 = __floats2bfloat162_rn(v0 - __bfloat162float(h2.x),
                                            v1 - __bfloat162float(h2.y));
  g_whp[idx] = *reinterpret_cast<uint32_t*>(&h2);
  g_wlp[idx] = *reinterpret_cast<uint32_t*>(&l2);
}

}  // namespace

extern "C" void kernel_launch(void* const* d_in, const int* in_sizes, int n_in,
                              void* d_out, int out_size)
{
  (void)n_in; (void)out_size;
  const float* coords  = (const float*)d_in[0];
  const int*   species = (const int*)d_in[1];
  const int*   mask    = (const int*)d_in[2];
  const float* embed   = (const float*)d_in[3];
  const float* Wq      = (const float*)d_in[4];
  const float* Wk      = (const float*)d_in[5];
  const float* Wv      = (const float*)d_in[6];
  const float* Wo      = (const float*)d_in[7];
  const float* We      = (const float*)d_in[8];
  const float* Wf      = (const float*)d_in[9];
  const float* bf      = (const float*)d_in[10];

  const int B = in_sizes[0] / (N * 3);   // 2048

  prep_weights<<<(15 * 64 * 128 + 255) / 256, 256>>>(Wq, Wk, Wv, Wo, Wf);

  cudaFuncSetAttribute(gnn_kernel, cudaFuncAttributeMaxDynamicSharedMemorySize,
                       (int)sizeof(Smem));
  gnn_kernel<<<B, TPB, sizeof(Smem)>>>(coords, species, mask, embed,
                                       We, bf, (float*)d_out);
}

// round 6
// speedup vs baseline: 1.8447x; 1.3310x over previous
#include <cuda_runtime.h>
#include <cuda_bf16.h>
#include <stdint.h>
#include <math.h>

#define TPB 256

namespace {

constexpr int N  = 64;    // nodes
constexpr int F  = 128;   // features
constexpr int DH = 64;    // feats per head
constexpr int APAD = 68;  // [n][kpair] packed stride (A operands)
constexpr int KPAD = 72;  // [kpair][m] packed stride (logits B operand)
constexpr int TPAD = 36;  // [dh][mpair] / [hh][n][mpair] stride
constexpr int WPAD = 136; // staged weight slice stride
constexpr float NEGV = -1e9f;
constexpr float INV_SQRT_DH = 0.125f;

// Pre-split weights: [15 matrices][64 kpairs][128 n], bf16x2
__device__ uint32_t g_whp[15 * 64 * 128];
__device__ uint32_t g_wlp[15 * 64 * 128];

struct __align__(16) Smem {
  float h[N][F];                            // node features (fp32 residual)
  uint32_t ahp[N][APAD], alp[N][APAD];      // A operand: LN(h) / msg
  uint32_t qhp[N][APAD], qlp[N][APAD];      // q packed [n][kpair]
  uint32_t u1h[64 * KPAD], u1l[64 * KPAD];  // khp [kp][m]  UNION  athp [hh][n][mp]
  uint32_t vth[F][TPAD], vtl[F][TPAD];      // v transposed packed [dh][mpair]
  uint32_t swh[16][WPAD], swl[16][WPAD];    // staged weight K-slice
  float coords[N][3];
  float mrow[N];
  float bf_l[F];
  float We_l[7][2];
};

__device__ __forceinline__ void mma_bf16(float* d,
    uint32_t a0, uint32_t a1, uint32_t a2, uint32_t a3,
    uint32_t b0, uint32_t b1)
{
  asm volatile(
    "mma.sync.aligned.m16n8k16.row.col.f32.bf16.bf16.f32 "
    "{%0,%1,%2,%3}, {%4,%5,%6,%7}, {%8,%9}, {%0,%1,%2,%3};\n"
    : "+f"(d[0]), "+f"(d[1]), "+f"(d[2]), "+f"(d[3])
    : "r"(a0), "r"(a1), "r"(a2), "r"(a3), "r"(b0), "r"(b1));
}

// Split-pack two fp32 values into bf16x2 hi/lo words (low half = first value).
__device__ __forceinline__ void pack2(float x, float y,
                                      uint32_t* hp, uint32_t* lp)
{
  __nv_bfloat162 h2 = __floats2bfloat162_rn(x, y);
  float hx = __bfloat162float(h2.x), hy = __bfloat162float(h2.y);
  __nv_bfloat162 l2 = __floats2bfloat162_rn(x - hx, y - hy);
  *hp = *reinterpret_cast<uint32_t*>(&h2);
  *lp = *reinterpret_cast<uint32_t*>(&l2);
}

// LN over rows of src (stride F), result split-packed into ahp/alp.
__device__ __forceinline__ void ln_split(const float (*src)[F],
    uint32_t (*ahp)[APAD], uint32_t (*alp)[APAD], int tid)
{
  const int w = tid >> 5, l = tid & 31;
  for (int n = w; n < N; n += 8) {
    float2 p0 = *(const float2*)&src[n][2 * l];
    float2 p1 = *(const float2*)&src[n][64 + 2 * l];
    float sm = p0.x + p0.y + p1.x + p1.y;
#pragma unroll
    for (int o = 16; o; o >>= 1) sm += __shfl_xor_sync(0xffffffffu, sm, o);
    float mean = sm * (1.f / 128.f);
    float d0 = p0.x - mean, d1 = p0.y - mean, d2 = p1.x - mean, d3 = p1.y - mean;
    float ss = d0 * d0 + d1 * d1 + d2 * d2 + d3 * d3;
#pragma unroll
    for (int o = 16; o; o >>= 1) ss += __shfl_xor_sync(0xffffffffu, ss, o);
    float inv = rsqrtf(ss * (1.f / 128.f) + 1e-5f);
    d0 *= inv; d1 *= inv; d2 *= inv; d3 *= inv;
    pack2(d0, d1, &ahp[n][l],      &alp[n][l]);
    pack2(d2, d3, &ahp[n][l + 32], &alp[n][l + 32]);
  }
}

// C[64][128] = A[64][128] @ W[128][128] via bf16-split mma (3-mma scheme).
__device__ __forceinline__ void gemm_mma(
    const uint32_t (*ahp)[APAD], const uint32_t (*alp)[APAD],
    const uint32_t* __restrict__ gWh, const uint32_t* __restrict__ gWl,
    uint32_t (*swh)[WPAD], uint32_t (*swl)[WPAD],
    int tid, float acc[8][4])
{
  const int warp = tid >> 5, lane = tid & 31;
  const int mb = (warp & 3) << 4;
  const int nb = (warp >> 2) << 6;
  const int lm = lane >> 2, tig = lane & 3;

#pragma unroll
  for (int t = 0; t < 8; ++t)
#pragma unroll
    for (int i = 0; i < 4; ++i) acc[t][i] = 0.f;

  for (int ks = 0; ks < 4; ++ks) {
    __syncthreads();
    {
      const uint4* gh = (const uint4*)(gWh + ks * 16 * 128);
      const uint4* gl = (const uint4*)(gWl + ks * 16 * 128);
#pragma unroll
      for (int i = tid; i < 512; i += TPB) {
        int row = i >> 5, c = i & 31;
        ((uint4*)&swh[row][0])[c] = gh[i];
        ((uint4*)&swl[row][0])[c] = gl[i];
      }
    }
    __syncthreads();
#pragma unroll
    for (int half = 0; half < 2; ++half) {
      const int kp0 = ks * 16 + half * 8;
      const int kpl = half * 8;
      uint32_t ah0 = ahp[mb + lm    ][kp0 + tig];
      uint32_t ah1 = ahp[mb + lm + 8][kp0 + tig];
      uint32_t ah2 = ahp[mb + lm    ][kp0 + tig + 4];
      uint32_t ah3 = ahp[mb + lm + 8][kp0 + tig + 4];
      uint32_t al0 = alp[mb + lm    ][kp0 + tig];
      uint32_t al1 = alp[mb + lm + 8][kp0 + tig];
      uint32_t al2 = alp[mb + lm    ][kp0 + tig + 4];
      uint32_t al3 = alp[mb + lm + 8][kp0 + tig + 4];
#pragma unroll
      for (int t = 0; t < 8; ++t) {
        const int n0 = nb + t * 8 + lm;
        uint32_t bh0 = swh[kpl + tig    ][n0];
        uint32_t bh1 = swh[kpl + tig + 4][n0];
        uint32_t bl0 = swl[kpl + tig    ][n0];
        uint32_t bl1 = swl[kpl + tig + 4][n0];
        mma_bf16(acc[t], ah0, ah1, ah2, ah3, bh0, bh1);
        mma_bf16(acc[t], ah0, ah1, ah2, ah3, bl0, bl1);
        mma_bf16(acc[t], al0, al1, al2, al3, bh0, bh1);
      }
    }
  }
}

__global__ void __launch_bounds__(TPB, 1) gnn_kernel(
    const float* __restrict__ g_coords,
    const int*   __restrict__ g_species,
    const int*   __restrict__ g_mask,
    const float* __restrict__ g_embed,
    const float* __restrict__ g_We,
    const float* __restrict__ g_bf,
    float* __restrict__ g_out)
{
  extern __shared__ unsigned char smem_raw[];
  Smem& s = *reinterpret_cast<Smem*>(smem_raw);
  const int b = blockIdx.x;
  const int tid = threadIdx.x;

  if (tid < N) {
    s.mrow[tid] = (g_mask[b * N + tid] != 0) ? 1.f : 0.f;
    s.coords[tid][0] = g_coords[(b * N + tid) * 3 + 0];
    s.coords[tid][1] = g_coords[(b * N + tid) * 3 + 1];
    s.coords[tid][2] = g_coords[(b * N + tid) * 3 + 2];
  }
  for (int i = tid; i < N * F; i += TPB) {
    int n = i >> 7, f = i & (F - 1);
    int sp = g_species[b * N + n] - 1;
    float hv = g_embed[sp * F + f];
    s.h[n][f] = (g_mask[b * N + n] != 0) ? hv : 0.f;
  }
  __syncthreads();

  const int warp = tid >> 5, lane = tid & 31;
  const int mb = (warp & 3) << 4;
  const int nb = (warp >> 2) << 6;
  const int lm = lane >> 2, tig = lane & 3;
  const int hh = warp >> 2;          // head for attention phases
  const int rA = mb + lm, rB = mb + lm + 8;

  float acc[8][4];

  for (int l = 0; l < 3; ++l) {
    if (tid < F) s.bf_l[tid] = g_bf[l * F + tid];
    if (tid >= 128 && tid < 128 + 14)
      ((float*)s.We_l)[tid - 128] = g_We[l * 14 + (tid - 128)];

    const uint32_t* wbase_h = g_whp + (size_t)(l * 5) * 64 * 128;
    const uint32_t* wbase_l = g_wlp + (size_t)(l * 5) * 64 * 128;

    // ---- hn = LN(h), split-packed into ahp/alp ----
    ln_split(s.h, s.ahp, s.alp, tid);

    // ---- q = hn @ Wq -> packed [n][kpair] ----
    gemm_mma(s.ahp, s.alp, wbase_h + 0 * 8192, wbase_l + 0 * 8192, s.swh, s.swl, tid, acc);
#pragma unroll
    for (int t = 0; t < 8; ++t) {
      int kp = (nb + t * 8 + 2 * tig) >> 1;
      pack2(acc[t][0], acc[t][1], &s.qhp[rA][kp], &s.qlp[rA][kp]);
      pack2(acc[t][2], acc[t][3], &s.qhp[rB][kp], &s.qlp[rB][kp]);
    }

    // ---- k = hn @ Wk -> transposed packed [kpair][m] ----
    gemm_mma(s.ahp, s.alp, wbase_h + 1 * 8192, wbase_l + 1 * 8192, s.swh, s.swl, tid, acc);
#pragma unroll
    for (int t = 0; t < 8; ++t) {
      int kp = (nb + t * 8 + 2 * tig) >> 1;
      pack2(acc[t][0], acc[t][1], &s.u1h[kp * KPAD + rA], &s.u1l[kp * KPAD + rA]);
      pack2(acc[t][2], acc[t][3], &s.u1h[kp * KPAD + rB], &s.u1l[kp * KPAD + rB]);
    }

    // ---- v = hn @ Wv -> transposed packed [dh][mpair] via lane exchange ----
    gemm_mma(s.ahp, s.alp, wbase_h + 2 * 8192, wbase_l + 2 * 8192, s.swh, s.swl, tid, acc);
#pragma unroll
    for (int t = 0; t < 8; ++t) {
      int c = nb + t * 8 + 2 * tig;
      float p0 = __shfl_xor_sync(0xffffffffu, acc[t][0], 4);
      float p1 = __shfl_xor_sync(0xffffffffu, acc[t][1], 4);
      float p2 = __shfl_xor_sync(0xffffffffu, acc[t][2], 4);
      float p3 = __shfl_xor_sync(0xffffffffu, acc[t][3], 4);
      if ((lm & 1) == 0) {
        int mp = (mb + lm) >> 1;                 // rows (rA, rA+1)
        pack2(acc[t][0], p0, &s.vth[c][mp],     &s.vtl[c][mp]);
        pack2(acc[t][1], p1, &s.vth[c + 1][mp], &s.vtl[c + 1][mp]);
      } else {
        int mp = (mb + lm + 7) >> 1;             // rows (rB-1, rB)
        pack2(p2, acc[t][2], &s.vth[c][mp],     &s.vtl[c][mp]);
        pack2(p3, acc[t][3], &s.vth[c + 1][mp], &s.vtl[c + 1][mp]);
      }
    }

    // ---- logits = q @ k^T per head (split-bf16 mma) ----
#pragma unroll
    for (int t = 0; t < 8; ++t)
#pragma unroll
      for (int i = 0; i < 4; ++i) acc[t][i] = 0.f;
#pragma unroll
    for (int ks = 0; ks < 4; ++ks) {
      const int kb = hh * 32 + ks * 8;
      uint32_t ah0 = s.qhp[rA][kb + tig],     ah1 = s.qhp[rB][kb + tig];
      uint32_t ah2 = s.qhp[rA][kb + tig + 4], ah3 = s.qhp[rB][kb + tig + 4];
      uint32_t al0 = s.qlp[rA][kb + tig],     al1 = s.qlp[rB][kb + tig];
      uint32_t al2 = s.qlp[rA][kb + tig + 4], al3 = s.qlp[rB][kb + tig + 4];
#pragma unroll
      for (int t = 0; t < 8; ++t) {
        const int m0 = t * 8 + lm;
        uint32_t bh0 = s.u1h[(kb + tig)     * KPAD + m0];
        uint32_t bh1 = s.u1h[(kb + tig + 4) * KPAD + m0];
        uint32_t bl0 = s.u1l[(kb + tig)     * KPAD + m0];
        uint32_t bl1 = s.u1l[(kb + tig + 4) * KPAD + m0];
        mma_bf16(acc[t], ah0, ah1, ah2, ah3, bh0, bh1);
        mma_bf16(acc[t], ah0, ah1, ah2, ah3, bl0, bl1);
        mma_bf16(acc[t], al0, al1, al2, al3, bh0, bh1);
      }
    }
    __syncthreads();   // all khp reads done before athp overwrites u1

    // ---- epilogue: scale + edge bias + mask + softmax (registers) -> athp ----
    {
      const float w0 = s.We_l[0][hh], w1 = s.We_l[1][hh], w2 = s.We_l[2][hh],
                  w3 = s.We_l[3][hh], w4 = s.We_l[4][hh], w5 = s.We_l[5][hh],
                  w6 = s.We_l[6][hh];
      const bool okA = s.mrow[rA] > 0.f, okB = s.mrow[rB] > 0.f;
      const float a0 = s.coords[rA][0], a1 = s.coords[rA][1], a2 = s.coords[rA][2];
      const float b0 = s.coords[rB][0], b1 = s.coords[rB][1], b2 = s.coords[rB][2];
      float xA[16], xB[16];
#pragma unroll
      for (int t = 0; t < 8; ++t) {
#pragma unroll
        for (int j = 0; j < 2; ++j) {
          const int m = t * 8 + 2 * tig + j;
          const float m0 = s.coords[m][0], m1 = s.coords[m][1], m2 = s.coords[m][2];
          const bool okm = s.mrow[m] > 0.f;
          {
            float dx = a0 - m0, dy = a1 - m1, dz = a2 - m2;
            float d = sqrtf(dx * dx + dy * dy + dz * dz + 1e-12f);
            float g1 = 1.f / (1.f + __expf(2.f - d));
            float g2 = 1.f / (1.f + __expf(4.f - d));
            float g3 = 1.f / (1.f + __expf(6.f - d));
            float bias = dx * w0 + dy * w1 + dz * w2 + d * w3
                       + g1 * w4 + g2 * w5 + g3 * w6;
            xA[2 * t + j] = (okA && okm) ? acc[t][j] * INV_SQRT_DH + bias : NEGV;
          }
          {
            float dx = b0 - m0, dy = b1 - m1, dz = b2 - m2;
            float d = sqrtf(dx * dx + dy * dy + dz * dz + 1e-12f);
            float g1 = 1.f / (1.f + __expf(2.f - d));
            float g2 = 1.f / (1.f + __expf(4.f - d));
            float g3 = 1.f / (1.f + __expf(6.f - d));
            float bias = dx * w0 + dy * w1 + dz * w2 + d * w3
                       + g1 * w4 + g2 * w5 + g3 * w6;
            xB[2 * t + j] = (okB && okm) ? acc[t][2 + j] * INV_SQRT_DH + bias : NEGV;
          }
        }
      }
      float mxA = xA[0], mxB = xB[0];
#pragma unroll
      for (int i = 1; i < 16; ++i) { mxA = fmaxf(mxA, xA[i]); mxB = fmaxf(mxB, xB[i]); }
      mxA = fmaxf(mxA, __shfl_xor_sync(0xffffffffu, mxA, 1));
      mxA = fmaxf(mxA, __shfl_xor_sync(0xffffffffu, mxA, 2));
      mxB = fmaxf(mxB, __shfl_xor_sync(0xffffffffu, mxB, 1));
      mxB = fmaxf(mxB, __shfl_xor_sync(0xffffffffu, mxB, 2));
      float smA = 0.f, smB = 0.f;
#pragma unroll
      for (int i = 0; i < 16; ++i) {
        xA[i] = __expf(xA[i] - mxA); smA += xA[i];
        xB[i] = __expf(xB[i] - mxB); smB += xB[i];
      }
      smA += __shfl_xor_sync(0xffffffffu, smA, 1);
      smA += __shfl_xor_sync(0xffffffffu, smA, 2);
      smB += __shfl_xor_sync(0xffffffffu, smB, 1);
      smB += __shfl_xor_sync(0xffffffffu, smB, 2);
      const float invA = 1.f / smA, invB = 1.f / smB;
      const int baseA = (hh * 64 + rA) * TPAD;
      const int baseB = (hh * 64 + rB) * TPAD;
#pragma unroll
      for (int t = 0; t < 8; ++t) {
        int mp = t * 4 + tig;
        pack2(xA[2 * t] * invA, xA[2 * t + 1] * invA,
              &s.u1h[baseA + mp], &s.u1l[baseA + mp]);
        pack2(xB[2 * t] * invB, xB[2 * t + 1] * invB,
              &s.u1h[baseB + mp], &s.u1l[baseB + mp]);
      }
    }
    __syncthreads();   // athp/vth complete before msg mma

    // ---- msg = attn @ v per head (split-bf16 mma) -> pack into ahp/alp ----
#pragma unroll
    for (int t = 0; t < 8; ++t)
#pragma unroll
      for (int i = 0; i < 4; ++i) acc[t][i] = 0.f;
#pragma unroll
    for (int ks = 0; ks < 4; ++ks) {
      const int kb = ks * 8;
      const int baseA = (hh * 64 + rA) * TPAD;
      const int baseB = (hh * 64 + rB) * TPAD;
      uint32_t ah0 = s.u1h[baseA + kb + tig],     ah1 = s.u1h[baseB + kb + tig];
      uint32_t ah2 = s.u1h[baseA + kb + tig + 4], ah3 = s.u1h[baseB + kb + tig + 4];
      uint32_t al0 = s.u1l[baseA + kb + tig],     al1 = s.u1l[baseB + kb + tig];
      uint32_t al2 = s.u1l[baseA + kb + tig + 4], al3 = s.u1l[baseB + kb + tig + 4];
#pragma unroll
      for (int t = 0; t < 8; ++t) {
        const int dhg = hh * 64 + t * 8 + lm;
        uint32_t bh0 = s.vth[dhg][kb + tig];
        uint32_t bh1 = s.vth[dhg][kb + tig + 4];
        uint32_t bl0 = s.vtl[dhg][kb + tig];
        uint32_t bl1 = s.vtl[dhg][kb + tig + 4];
        mma_bf16(acc[t], ah0, ah1, ah2, ah3, bh0, bh1);
        mma_bf16(acc[t], ah0, ah1, ah2, ah3, bl0, bl1);
        mma_bf16(acc[t], al0, al1, al2, al3, bh0, bh1);
      }
    }
#pragma unroll
    for (int t = 0; t < 8; ++t) {
      int kp = hh * 32 + t * 4 + tig;
      pack2(acc[t][0], acc[t][1], &s.ahp[rA][kp], &s.alp[rA][kp]);
      pack2(acc[t][2], acc[t][3], &s.ahp[rB][kp], &s.alp[rB][kp]);
    }

    // ---- h += msg @ Wo ----
    gemm_mma(s.ahp, s.alp, wbase_h + 3 * 8192, wbase_l + 3 * 8192, s.swh, s.swl, tid, acc);
#pragma unroll
    for (int t = 0; t < 8; ++t) {
      int c = nb + t * 8 + 2 * tig;
      float2 h0 = *(float2*)&s.h[rA][c];
      h0.x += acc[t][0]; h0.y += acc[t][1];
      *(float2*)&s.h[rA][c] = h0;
      float2 h1 = *(float2*)&s.h[rB][c];
      h1.x += acc[t][2]; h1.y += acc[t][3];
      *(float2*)&s.h[rB][c] = h1;
    }
    __syncthreads();

    // ---- h = (h + tanh(LN(h) @ Wf + bf)) * mask ----
    ln_split(s.h, s.ahp, s.alp, tid);
    gemm_mma(s.ahp, s.alp, wbase_h + 4 * 8192, wbase_l + 4 * 8192, s.swh, s.swl, tid, acc);
    {
      float mr0 = s.mrow[rA];
      float mr1 = s.mrow[rB];
#pragma unroll
      for (int t = 0; t < 8; ++t) {
        int c = nb + t * 8 + 2 * tig;
        float2 h0 = *(float2*)&s.h[rA][c];
        h0.x = (h0.x + tanhf(acc[t][0] + s.bf_l[c]))     * mr0;
        h0.y = (h0.y + tanhf(acc[t][1] + s.bf_l[c + 1])) * mr0;
        *(float2*)&s.h[rA][c] = h0;
        float2 h1 = *(float2*)&s.h[rB][c];
        h1.x = (h1.x + tanhf(acc[t][2] + s.bf_l[c]))     * mr1;
        h1.y = (h1.y + tanhf(acc[t][3] + s.bf_l[c + 1])) * mr1;
        *(float2*)&s.h[rB][c] = h1;
      }
    }
    __syncthreads();
  }

  // ---- final layernorm -> global output ----
  {
    const int w = tid >> 5, ln = tid & 31;
    for (int n = w; n < N; n += 8) {
      float x0 = s.h[n][ln], x1 = s.h[n][ln + 32];
      float x2 = s.h[n][ln + 64], x3 = s.h[n][ln + 96];
      float sm = x0 + x1 + x2 + x3;
#pragma unroll
      for (int o = 16; o; o >>= 1) sm += __shfl_xor_sync(0xffffffffu, sm, o);
      float mean = sm * (1.f / 128.f);
      float d0 = x0 - mean, d1 = x1 - mean, d2 = x2 - mean, d3 = x3 - mean;
      float ss = d0 * d0 + d1 * d1 + d2 * d2 + d3 * d3;
#pragma unroll
      for (int o = 16; o; o >>= 1) ss += __shfl_xor_sync(0xffffffffu, ss, o);
      float inv = rsqrtf(ss * (1.f / 128.f) + 1e-5f);
      float* orow = g_out + (size_t)(b * N + n) * F;
      orow[ln]      = d0 * inv;
      orow[ln + 32] = d1 * inv;
      orow[ln + 64] = d2 * inv;
      orow[ln + 96] = d3 * inv;
    }
  }
}

// Split/pack all 15 weight matrices once.
__global__ void prep_weights(const float* __restrict__ Wq,
                             const float* __restrict__ Wk,
                             const float* __restrict__ Wv,
                             const float* __restrict__ Wo,
                             const float* __restrict__ Wf)
{
  int idx = blockIdx.x * blockDim.x + threadIdx.x;
  if (idx >= 15 * 64 * 128) return;
  int mat = idx >> 13;
  int kp  = (idx >> 7) & 63;
  int n   = idx & 127;
  int l = mat / 5, which = mat % 5;
  const float* W =
      (which == 0 ? Wq : which == 1 ? Wk : which == 2 ? Wv : which == 3 ? Wo : Wf)
      + l * F * F;
  float v0 = W[(2 * kp)     * F + n];
  float v1 = W[(2 * kp + 1) * F + n];
  __nv_bfloat162 h2 = __floats2bfloat162_rn(v0, v1);
  __nv_bfloat162 l2 = __floats2bfloat162_rn(v0 - __bfloat162float(h2.x),
                                            v1 - __bfloat162float(h2.y));
  g_whp[idx] = *reinterpret_cast<uint32_t*>(&h2);
  g_wlp[idx] = *reinterpret_cast<uint32_t*>(&l2);
}

}  // namespace

extern "C" void kernel_launch(void* const* d_in, const int* in_sizes, int n_in,
                              void* d_out, int out_size)
{
  (void)n_in; (void)out_size;
  const float* coords  = (const float*)d_in[0];
  const int*   species = (const int*)d_in[1];
  const int*   mask    = (const int*)d_in[2];
  const float* embed   = (const float*)d_in[3];
  const float* Wq      = (const float*)d_in[4];
  const float* Wk      = (const float*)d_in[5];
  const float* Wv      = (const float*)d_in[6];
  const float* Wo      = (const float*)d_in[7];
  const float* We      = (const float*)d_in[8];
  const float* Wf      = (const float*)d_in[9];
  const float* bf      = (const float*)d_in[10];

  const int B = in_sizes[0] / (N * 3);   // 2048

  prep_weights<<<(15 * 64 * 128 + 255) / 256, 256>>>(Wq, Wk, Wv, Wo, Wf);

  cudaFuncSetAttribute(gnn_kernel, cudaFuncAttributeMaxDynamicSharedMemorySize,
                       (int)sizeof(Smem));
  gnn_kernel<<<B, TPB, sizeof(Smem)>>>(coords, species, mask, embed,
                                       We, bf, (float*)d_out);
}

// round 7
// speedup vs baseline: 2.3592x; 1.2789x over previous
#include <cuda_runtime.h>
#include <cuda_bf16.h>
#include <stdint.h>
#include <math.h>

#define TPB 512

namespace {

constexpr int N  = 64;
constexpr int F  = 128;
constexpr int DH = 64;
constexpr int APAD = 68;  // [n][kpair] packed stride
constexpr int KPAD = 72;  // [kpair][m] packed stride (logits B)
constexpr int TPAD = 36;  // [dh][mpair] & [hh][n][mpair] stride
constexpr int WPAD = 136; // staged weight slice stride
constexpr float NEGV = -1e9f;
constexpr float INV_SQRT_DH = 0.125f;

__device__ uint32_t g_whp[15 * 64 * 128];
__device__ uint32_t g_wlp[15 * 64 * 128];

struct __align__(16) Smem {
  float h[N][F];
  uint32_t ahp[N][APAD], alp[N][APAD];        // A operand: LN(h) / msg
  uint32_t qhp[N][APAD], qlp[N][APAD];        // q packed [n][kpair]
  uint32_t u1h[64 * KPAD], u1l[64 * KPAD];    // k [kp][m]  UNION  attn [hh][n][mp]
  uint32_t vth[F][TPAD], vtl[F][TPAD];        // v transposed [dh][mpair]
  uint32_t swh[2][16][WPAD], swl[2][16][WPAD];// double-buffered weight slices
  float rmx[2][64][2], rsm[2][64][2];         // softmax cross-warp partials
  float coords[N][3];
  float mrow[N];
  float bf_l[F];
  float We_l[7][2];
};

__device__ __forceinline__ void mma_bf16(float* d,
    uint32_t a0, uint32_t a1, uint32_t a2, uint32_t a3,
    uint32_t b0, uint32_t b1)
{
  asm volatile(
    "mma.sync.aligned.m16n8k16.row.col.f32.bf16.bf16.f32 "
    "{%0,%1,%2,%3}, {%4,%5,%6,%7}, {%8,%9}, {%0,%1,%2,%3};\n"
    : "+f"(d[0]), "+f"(d[1]), "+f"(d[2]), "+f"(d[3])
    : "r"(a0), "r"(a1), "r"(a2), "r"(a3), "r"(b0), "r"(b1));
}

__device__ __forceinline__ void pack2(float x, float y,
                                      uint32_t* hp, uint32_t* lp)
{
  __nv_bfloat162 h2 = __floats2bfloat162_rn(x, y);
  float hx = __bfloat162float(h2.x), hy = __bfloat162float(h2.y);
  __nv_bfloat162 l2 = __floats2bfloat162_rn(x - hx, y - hy);
  *hp = *reinterpret_cast<uint32_t*>(&h2);
  *lp = *reinterpret_cast<uint32_t*>(&l2);
}

// LN over rows of src, split-packed into ahp/alp. 16 warps: rows stride 16.
__device__ __forceinline__ void ln_split(const float (*src)[F],
    uint32_t (*ahp)[APAD], uint32_t (*alp)[APAD], int tid)
{
  const int w = tid >> 5, l = tid & 31;
  for (int n = w; n < N; n += 16) {
    float2 p0 = *(const float2*)&src[n][2 * l];
    float2 p1 = *(const float2*)&src[n][64 + 2 * l];
    float sm = p0.x + p0.y + p1.x + p1.y;
#pragma unroll
    for (int o = 16; o; o >>= 1) sm += __shfl_xor_sync(0xffffffffu, sm, o);
    float mean = sm * (1.f / 128.f);
    float d0 = p0.x - mean, d1 = p0.y - mean, d2 = p1.x - mean, d3 = p1.y - mean;
    float ss = d0 * d0 + d1 * d1 + d2 * d2 + d3 * d3;
#pragma unroll
    for (int o = 16; o; o >>= 1) ss += __shfl_xor_sync(0xffffffffu, ss, o);
    float inv = rsqrtf(ss * (1.f / 128.f) + 1e-5f);
    d0 *= inv; d1 *= inv; d2 *= inv; d3 *= inv;
    pack2(d0, d1, &ahp[n][l],      &alp[n][l]);
    pack2(d2, d3, &ahp[n][l + 32], &alp[n][l + 32]);
  }
}

// C[64][128] = A @ W via split-bf16 mma, 16 warps (4 row x 4 col blocks),
// double-buffered weight staging with register prefetch (1 sync per slice).
__device__ __forceinline__ void gemm_mma(
    const uint32_t (*ahp)[APAD], const uint32_t (*alp)[APAD],
    const uint32_t* __restrict__ gWh, const uint32_t* __restrict__ gWl,
    uint32_t (*swh)[16][WPAD], uint32_t (*swl)[16][WPAD],
    int tid, float acc[4][4])
{
  const int warp = tid >> 5, lane = tid & 31;
  const int mb = (warp & 3) << 4;
  const int nb = (warp >> 2) << 5;
  const int lm = lane >> 2, tig = lane & 3;
  const int srow = tid >> 5;   // 0..15
  const int scol = tid & 31;   // 0..31

#pragma unroll
  for (int t = 0; t < 4; ++t)
#pragma unroll
    for (int i = 0; i < 4; ++i) acc[t][i] = 0.f;

  const uint4* __restrict__ gh4 = (const uint4*)gWh;
  const uint4* __restrict__ gl4 = (const uint4*)gWl;

  // preload slice 0
  uint4 ph = gh4[tid];
  uint4 pl = gl4[tid];
  ((uint4*)&swh[0][srow][0])[scol] = ph;
  ((uint4*)&swl[0][srow][0])[scol] = pl;
  __syncthreads();

  for (int ks = 0; ks < 4; ++ks) {
    if (ks < 3) { ph = gh4[(ks + 1) * 512 + tid]; pl = gl4[(ks + 1) * 512 + tid]; }
    const int cur = ks & 1;
#pragma unroll
    for (int half = 0; half < 2; ++half) {
      const int kp0 = ks * 16 + half * 8;
      const int kr  = half * 8;
      uint32_t ah0 = ahp[mb + lm    ][kp0 + tig];
      uint32_t ah1 = ahp[mb + lm + 8][kp0 + tig];
      uint32_t ah2 = ahp[mb + lm    ][kp0 + tig + 4];
      uint32_t ah3 = ahp[mb + lm + 8][kp0 + tig + 4];
      uint32_t al0 = alp[mb + lm    ][kp0 + tig];
      uint32_t al1 = alp[mb + lm + 8][kp0 + tig];
      uint32_t al2 = alp[mb + lm    ][kp0 + tig + 4];
      uint32_t al3 = alp[mb + lm + 8][kp0 + tig + 4];
#pragma unroll
      for (int t = 0; t < 4; ++t) {
        const int n0 = nb + t * 8 + lm;
        uint32_t bh0 = swh[cur][kr + tig    ][n0];
        uint32_t bh1 = swh[cur][kr + tig + 4][n0];
        uint32_t bl0 = swl[cur][kr + tig    ][n0];
        uint32_t bl1 = swl[cur][kr + tig + 4][n0];
        mma_bf16(acc[t], ah0, ah1, ah2, ah3, bh0, bh1);
        mma_bf16(acc[t], ah0, ah1, ah2, ah3, bl0, bl1);
        mma_bf16(acc[t], al0, al1, al2, al3, bh0, bh1);
      }
    }
    if (ks < 3) {
      ((uint4*)&swh[cur ^ 1][srow][0])[scol] = ph;
      ((uint4*)&swl[cur ^ 1][srow][0])[scol] = pl;
    }
    __syncthreads();
  }
}

__global__ void __launch_bounds__(TPB, 1) gnn_kernel(
    const float* __restrict__ g_coords,
    const int*   __restrict__ g_species,
    const int*   __restrict__ g_mask,
    const float* __restrict__ g_embed,
    const float* __restrict__ g_We,
    const float* __restrict__ g_bf,
    float* __restrict__ g_out)
{
  extern __shared__ unsigned char smem_raw[];
  Smem& s = *reinterpret_cast<Smem*>(smem_raw);
  const int b = blockIdx.x;
  const int tid = threadIdx.x;

  if (tid < N) {
    s.mrow[tid] = (g_mask[b * N + tid] != 0) ? 1.f : 0.f;
    s.coords[tid][0] = g_coords[(b * N + tid) * 3 + 0];
    s.coords[tid][1] = g_coords[(b * N + tid) * 3 + 1];
    s.coords[tid][2] = g_coords[(b * N + tid) * 3 + 2];
  }
  for (int i = tid; i < N * F; i += TPB) {
    int n = i >> 7, f = i & (F - 1);
    int sp = g_species[b * N + n] - 1;
    float hv = g_embed[sp * F + f];
    s.h[n][f] = (g_mask[b * N + n] != 0) ? hv : 0.f;
  }
  __syncthreads();

  const int warp = tid >> 5, lane = tid & 31;
  const int mb = (warp & 3) << 4;
  const int nb = (warp >> 2) << 5;
  const int lm = lane >> 2, tig = lane & 3;
  const int rA = mb + lm, rB = mb + lm + 8;
  const int hh   = warp >> 3;        // attention head
  const int mblk = (warp >> 2) & 1;  // attention m-half / dh-half

  float acc[4][4];

  for (int l = 0; l < 3; ++l) {
    if (tid < F) s.bf_l[tid] = g_bf[l * F + tid];
    if (tid >= 128 && tid < 128 + 14)
      ((float*)s.We_l)[tid - 128] = g_We[l * 14 + (tid - 128)];

    const uint32_t* wbase_h = g_whp + (size_t)(l * 5) * 64 * 128;
    const uint32_t* wbase_l = g_wlp + (size_t)(l * 5) * 64 * 128;

    // ---- hn = LN(h) -> ahp/alp ----
    ln_split(s.h, s.ahp, s.alp, tid);

    // ---- q ----
    gemm_mma(s.ahp, s.alp, wbase_h + 0 * 8192, wbase_l + 0 * 8192, s.swh, s.swl, tid, acc);
#pragma unroll
    for (int t = 0; t < 4; ++t) {
      int kp = (nb + t * 8 + 2 * tig) >> 1;
      pack2(acc[t][0], acc[t][1], &s.qhp[rA][kp], &s.qlp[rA][kp]);
      pack2(acc[t][2], acc[t][3], &s.qhp[rB][kp], &s.qlp[rB][kp]);
    }

    // ---- k -> [kpair][m] ----
    gemm_mma(s.ahp, s.alp, wbase_h + 1 * 8192, wbase_l + 1 * 8192, s.swh, s.swl, tid, acc);
#pragma unroll
    for (int t = 0; t < 4; ++t) {
      int kp = (nb + t * 8 + 2 * tig) >> 1;
      pack2(acc[t][0], acc[t][1], &s.u1h[kp * KPAD + rA], &s.u1l[kp * KPAD + rA]);
      pack2(acc[t][2], acc[t][3], &s.u1h[kp * KPAD + rB], &s.u1l[kp * KPAD + rB]);
    }

    // ---- v -> transposed [dh][mpair] ----
    gemm_mma(s.ahp, s.alp, wbase_h + 2 * 8192, wbase_l + 2 * 8192, s.swh, s.swl, tid, acc);
#pragma unroll
    for (int t = 0; t < 4; ++t) {
      int c = nb + t * 8 + 2 * tig;
      float p0 = __shfl_xor_sync(0xffffffffu, acc[t][0], 4);
      float p1 = __shfl_xor_sync(0xffffffffu, acc[t][1], 4);
      float p2 = __shfl_xor_sync(0xffffffffu, acc[t][2], 4);
      float p3 = __shfl_xor_sync(0xffffffffu, acc[t][3], 4);
      if ((lm & 1) == 0) {
        int mp = (mb + lm) >> 1;
        pack2(acc[t][0], p0, &s.vth[c][mp],     &s.vtl[c][mp]);
        pack2(acc[t][1], p1, &s.vth[c + 1][mp], &s.vtl[c + 1][mp]);
      } else {
        int mp = (mb + lm + 7) >> 1;
        pack2(p2, acc[t][2], &s.vth[c][mp],     &s.vtl[c][mp]);
        pack2(p3, acc[t][3], &s.vth[c + 1][mp], &s.vtl[c + 1][mp]);
      }
    }

    // ---- logits = q @ k^T (head hh, m-half mblk) ----
#pragma unroll
    for (int t = 0; t < 4; ++t)
#pragma unroll
      for (int i = 0; i < 4; ++i) acc[t][i] = 0.f;
#pragma unroll
    for (int ks = 0; ks < 4; ++ks) {
      const int kb = hh * 32 + ks * 8;
      uint32_t ah0 = s.qhp[rA][kb + tig],     ah1 = s.qhp[rB][kb + tig];
      uint32_t ah2 = s.qhp[rA][kb + tig + 4], ah3 = s.qhp[rB][kb + tig + 4];
      uint32_t al0 = s.qlp[rA][kb + tig],     al1 = s.qlp[rB][kb + tig];
      uint32_t al2 = s.qlp[rA][kb + tig + 4], al3 = s.qlp[rB][kb + tig + 4];
#pragma unroll
      for (int t = 0; t < 4; ++t) {
        const int m0 = mblk * 32 + t * 8 + lm;
        uint32_t bh0 = s.u1h[(kb + tig)     * KPAD + m0];
        uint32_t bh1 = s.u1h[(kb + tig + 4) * KPAD + m0];
        uint32_t bl0 = s.u1l[(kb + tig)     * KPAD + m0];
        uint32_t bl1 = s.u1l[(kb + tig + 4) * KPAD + m0];
        mma_bf16(acc[t], ah0, ah1, ah2, ah3, bh0, bh1);
        mma_bf16(acc[t], ah0, ah1, ah2, ah3, bl0, bl1);
        mma_bf16(acc[t], al0, al1, al2, al3, bh0, bh1);
      }
    }

    // ---- epilogue: scale + edge bias + mask + cross-warp softmax -> attn ----
    {
      const float w0 = s.We_l[0][hh], w1 = s.We_l[1][hh], w2 = s.We_l[2][hh],
                  w3 = s.We_l[3][hh], w4 = s.We_l[4][hh], w5 = s.We_l[5][hh],
                  w6 = s.We_l[6][hh];
      const bool okA = s.mrow[rA] > 0.f, okB = s.mrow[rB] > 0.f;
      const float a0 = s.coords[rA][0], a1 = s.coords[rA][1], a2 = s.coords[rA][2];
      const float b0 = s.coords[rB][0], b1 = s.coords[rB][1], b2 = s.coords[rB][2];
      float xA[8], xB[8];
#pragma unroll
      for (int t = 0; t < 4; ++t) {
#pragma unroll
        for (int j = 0; j < 2; ++j) {
          const int m = mblk * 32 + t * 8 + 2 * tig + j;
          const float m0 = s.coords[m][0], m1 = s.coords[m][1], m2 = s.coords[m][2];
          const bool okm = s.mrow[m] > 0.f;
          {
            float dx = a0 - m0, dy = a1 - m1, dz = a2 - m2;
            float d = sqrtf(dx * dx + dy * dy + dz * dz + 1e-12f);
            float g1 = 1.f / (1.f + __expf(2.f - d));
            float g2 = 1.f / (1.f + __expf(4.f - d));
            float g3 = 1.f / (1.f + __expf(6.f - d));
            float bias = dx * w0 + dy * w1 + dz * w2 + d * w3
                       + g1 * w4 + g2 * w5 + g3 * w6;
            xA[2 * t + j] = (okA && okm) ? acc[t][j] * INV_SQRT_DH + bias : NEGV;
          }
          {
            float dx = b0 - m0, dy = b1 - m1, dz = b2 - m2;
            float d = sqrtf(dx * dx + dy * dy + dz * dz + 1e-12f);
            float g1 = 1.f / (1.f + __expf(2.f - d));
            float g2 = 1.f / (1.f + __expf(4.f - d));
            float g3 = 1.f / (1.f + __expf(6.f - d));
            float bias = dx * w0 + dy * w1 + dz * w2 + d * w3
                       + g1 * w4 + g2 * w5 + g3 * w6;
            xB[2 * t + j] = (okB && okm) ? acc[t][2 + j] * INV_SQRT_DH + bias : NEGV;
          }
        }
      }
      float mxA = xA[0], mxB = xB[0];
#pragma unroll
      for (int i = 1; i < 8; ++i) { mxA = fmaxf(mxA, xA[i]); mxB = fmaxf(mxB, xB[i]); }
      mxA = fmaxf(mxA, __shfl_xor_sync(0xffffffffu, mxA, 1));
      mxA = fmaxf(mxA, __shfl_xor_sync(0xffffffffu, mxA, 2));
      mxB = fmaxf(mxB, __shfl_xor_sync(0xffffffffu, mxB, 1));
      mxB = fmaxf(mxB, __shfl_xor_sync(0xffffffffu, mxB, 2));
      if (tig == 0) {
        s.rmx[hh][rA][mblk] = mxA;
        s.rmx[hh][rB][mblk] = mxB;
      }
      __syncthreads();   // also: all u1(k) mma reads complete before attn overwrite
      const float gA = fmaxf(s.rmx[hh][rA][0], s.rmx[hh][rA][1]);
      const float gB = fmaxf(s.rmx[hh][rB][0], s.rmx[hh][rB][1]);
      float smA = 0.f, smB = 0.f;
#pragma unroll
      for (int i = 0; i < 8; ++i) {
        xA[i] = __expf(xA[i] - gA); smA += xA[i];
        xB[i] = __expf(xB[i] - gB); smB += xB[i];
      }
      smA += __shfl_xor_sync(0xffffffffu, smA, 1);
      smA += __shfl_xor_sync(0xffffffffu, smA, 2);
      smB += __shfl_xor_sync(0xffffffffu, smB, 1);
      smB += __shfl_xor_sync(0xffffffffu, smB, 2);
      if (tig == 0) {
        s.rsm[hh][rA][mblk] = smA;
        s.rsm[hh][rB][mblk] = smB;
      }
      __syncthreads();
      const float invA = 1.f / (s.rsm[hh][rA][0] + s.rsm[hh][rA][1]);
      const float invB = 1.f / (s.rsm[hh][rB][0] + s.rsm[hh][rB][1]);
      const int baseA = (hh * 64 + rA) * TPAD;
      const int baseB = (hh * 64 + rB) * TPAD;
#pragma unroll
      for (int t = 0; t < 4; ++t) {
        int mp = mblk * 16 + t * 4 + tig;
        pack2(xA[2 * t] * invA, xA[2 * t + 1] * invA,
              &s.u1h[baseA + mp], &s.u1l[baseA + mp]);
        pack2(xB[2 * t] * invB, xB[2 * t + 1] * invB,
              &s.u1h[baseB + mp], &s.u1l[baseB + mp]);
      }
    }
    __syncthreads();   // attn + vth visible before msg mma

    // ---- msg = attn @ v (head hh, dh-half mblk) -> pack into ahp/alp ----
#pragma unroll
    for (int t = 0; t < 4; ++t)
#pragma unroll
      for (int i = 0; i < 4; ++i) acc[t][i] = 0.f;
    {
      const int baseA = (hh * 64 + rA) * TPAD;
      const int baseB = (hh * 64 + rB) * TPAD;
      const int dhb = mblk * 32;
#pragma unroll
      for (int ks = 0; ks < 4; ++ks) {
        const int kb = ks * 8;
        uint32_t ah0 = s.u1h[baseA + kb + tig],     ah1 = s.u1h[baseB + kb + tig];
        uint32_t ah2 = s.u1h[baseA + kb + tig + 4], ah3 = s.u1h[baseB + kb + tig + 4];
        uint32_t al0 = s.u1l[baseA + kb + tig],     al1 = s.u1l[baseB + kb + tig];
        uint32_t al2 = s.u1l[baseA + kb + tig + 4], al3 = s.u1l[baseB + kb + tig + 4];
#pragma unroll
        for (int t = 0; t < 4; ++t) {
          const int dhg = hh * 64 + dhb + t * 8 + lm;
          uint32_t bh0 = s.vth[dhg][kb + tig];
          uint32_t bh1 = s.vth[dhg][kb + tig + 4];
          uint32_t bl0 = s.vtl[dhg][kb + tig];
          uint32_t bl1 = s.vtl[dhg][kb + tig + 4];
          mma_bf16(acc[t], ah0, ah1, ah2, ah3, bh0, bh1);
          mma_bf16(acc[t], ah0, ah1, ah2, ah3, bl0, bl1);
          mma_bf16(acc[t], al0, al1, al2, al3, bh0, bh1);
        }
      }
#pragma unroll
      for (int t = 0; t < 4; ++t) {
        int kp = hh * 32 + (dhb >> 1) + t * 4 + tig;
        pack2(acc[t][0], acc[t][1], &s.ahp[rA][kp], &s.alp[rA][kp]);
        pack2(acc[t][2], acc[t][3], &s.ahp[rB][kp], &s.alp[rB][kp]);
      }
    }

    // ---- h += msg @ Wo ----
    gemm_mma(s.ahp, s.alp, wbase_h + 3 * 8192, wbase_l + 3 * 8192, s.swh, s.swl, tid, acc);
#pragma unroll
    for (int t = 0; t < 4; ++t) {
      int c = nb + t * 8 + 2 * tig;
      float2 h0 = *(float2*)&s.h[rA][c];
      h0.x += acc[t][0]; h0.y += acc[t][1];
      *(float2*)&s.h[rA][c] = h0;
      float2 h1 = *(float2*)&s.h[rB][c];
      h1.x += acc[t][2]; h1.y += acc[t][3];
      *(float2*)&s.h[rB][c] = h1;
    }
    __syncthreads();

    // ---- h = (h + tanh(LN(h) @ Wf + bf)) * mask ----
    ln_split(s.h, s.ahp, s.alp, tid);
    gemm_mma(s.ahp, s.alp, wbase_h + 4 * 8192, wbase_l + 4 * 8192, s.swh, s.swl, tid, acc);
    {
      float mr0 = s.mrow[rA];
      float mr1 = s.mrow[rB];
#pragma unroll
      for (int t = 0; t < 4; ++t) {
        int c = nb + t * 8 + 2 * tig;
        float2 h0 = *(float2*)&s.h[rA][c];
        h0.x = (h0.x + tanhf(acc[t][0] + s.bf_l[c]))     * mr0;
        h0.y = (h0.y + tanhf(acc[t][1] + s.bf_l[c + 1])) * mr0;
        *(float2*)&s.h[rA][c] = h0;
        float2 h1 = *(float2*)&s.h[rB][c];
        h1.x = (h1.x + tanhf(acc[t][2] + s.bf_l[c]))     * mr1;
        h1.y = (h1.y + tanhf(acc[t][3] + s.bf_l[c + 1])) * mr1;
        *(float2*)&s.h[rB][c] = h1;
      }
    }
    __syncthreads();
  }

  // ---- final layernorm -> global output ----
  {
    const int w = tid >> 5, ln = tid & 31;
    for (int n = w; n < N; n += 16) {
      float x0 = s.h[n][ln], x1 = s.h[n][ln + 32];
      float x2 = s.h[n][ln + 64], x3 = s.h[n][ln + 96];
      float sm = x0 + x1 + x2 + x3;
#pragma unroll
      for (int o = 16; o; o >>= 1) sm += __shfl_xor_sync(0xffffffffu, sm, o);
      float mean = sm * (1.f / 128.f);
      float d0 = x0 - mean, d1 = x1 - mean, d2 = x2 - mean, d3 = x3 - mean;
      float ss = d0 * d0 + d1 * d1 + d2 * d2 + d3 * d3;
#pragma unroll
      for (int o = 16; o; o >>= 1) ss += __shfl_xor_sync(0xffffffffu, ss, o);
      float inv = rsqrtf(ss * (1.f / 128.f) + 1e-5f);
      float* orow = g_out + (size_t)(b * N + n) * F;
      orow[ln]      = d0 * inv;
      orow[ln + 32] = d1 * inv;
      orow[ln + 64] = d2 * inv;
      orow[ln + 96] = d3 * inv;
    }
  }
}

// Split/pack all 15 weight matrices once.
__global__ void prep_weights(const float* __restrict__ Wq,
                             const float* __restrict__ Wk,
                             const float* __restrict__ Wv,
                             const float* __restrict__ Wo,
                             const float* __restrict__ Wf)
{
  int idx = blockIdx.x * blockDim.x + threadIdx.x;
  if (idx >= 15 * 64 * 128) return;
  int mat = idx >> 13;
  int kp  = (idx >> 7) & 63;
  int n   = idx & 127;
  int l = mat / 5, which = mat % 5;
  const float* W =
      (which == 0 ? Wq : which == 1 ? Wk : which == 2 ? Wv : which == 3 ? Wo : Wf)
      + l * F * F;
  float v0 = W[(2 * kp)     * F + n];
  float v1 = W[(2 * kp + 1) * F + n];
  __nv_bfloat162 h2 = __floats2bfloat162_rn(v0, v1);
  __nv_bfloat162 l2 = __floats2bfloat162_rn(v0 - __bfloat162float(h2.x),
                                            v1 - __bfloat162float(h2.y));
  g_whp[idx] = *reinterpret_cast<uint32_t*>(&h2);
  g_wlp[idx] = *reinterpret_cast<uint32_t*>(&l2);
}

}  // namespace

extern "C" void kernel_launch(void* const* d_in, const int* in_sizes, int n_in,
                              void* d_out, int out_size)
{
  (void)n_in; (void)out_size;
  const float* coords  = (const float*)d_in[0];
  const int*   species = (const int*)d_in[1];
  const int*   mask    = (const int*)d_in[2];
  const float* embed   = (const float*)d_in[3];
  const float* Wq      = (const float*)d_in[4];
  const float* Wk      = (const float*)d_in[5];
  const float* Wv      = (const float*)d_in[6];
  const float* Wo      = (const float*)d_in[7];
  const float* We      = (const float*)d_in[8];
  const float* Wf      = (const float*)d_in[9];
  const float* bf      = (const float*)d_in[10];

  const int B = in_sizes[0] / (N * 3);   // 2048

  prep_weights<<<(15 * 64 * 128 + 255) / 256, 256>>>(Wq, Wk, Wv, Wo, Wf);

  cudaFuncSetAttribute(gnn_kernel, cudaFuncAttributeMaxDynamicSharedMemorySize,
                       (int)sizeof(Smem));
  gnn_kernel<<<B, TPB, sizeof(Smem)>>>(coords, species, mask, embed,
                                       We, bf, (float*)d_out);
}

// round 8
// speedup vs baseline: 2.4009x; 1.0177x over previous
#include <cuda_runtime.h>
#include <cuda_bf16.h>
#include <stdint.h>
#include <math.h>

#define TPB 512

namespace {

constexpr int N = 64;
constexpr int F = 128;
constexpr int APAD = 68;   // [n][kpair] packed stride
constexpr int KPAD = 72;   // [kpair][m] stride (logits B)
constexpr int TPAD = 36;   // [dh][mpair] & [hh][n][mpair] stride
constexpr int WROW = 136;  // staged weight row stride (128 + 8)
constexpr int WSLOT = 2 * 16 * WROW;  // words per matrix slot (hi+lo, 16 rows)
constexpr float NEGV = -1e9f;
constexpr float INV_SQRT_DH = 0.125f;

__device__ uint32_t g_whp[15 * 64 * 128];
__device__ uint32_t g_wlp[15 * 64 * 128];

struct __align__(16) Smem {
  float h[N][F];
  uint32_t ahp[N][APAD], alp[N][APAD];   // LN(h) -> q -> msg -> LN(h) (phased reuse)
  // ---- overlay region (contiguous): k/attn + v-transposed; doubles as fused
  //      staging buffer B while attention data is dead ----
  uint32_t u1h[64 * KPAD], u1l[64 * KPAD];
  uint32_t vth[F][TPAD], vtl[F][TPAD];
  // ---- dedicated staging: 3 matrix slots (fused buf A; Wo/Wf use slots 0,1) ----
  uint32_t swA[3 * WSLOT];
  float rmx[2][64][2], rsm[2][64][2];
  float coords[N][3];
  float mrow[N];
  float bf_l[F];
  float We_l[7][2];
};

__device__ __forceinline__ void mma_bf16(float* d,
    uint32_t a0, uint32_t a1, uint32_t a2, uint32_t a3,
    uint32_t b0, uint32_t b1)
{
  asm volatile(
    "mma.sync.aligned.m16n8k16.row.col.f32.bf16.bf16.f32 "
    "{%0,%1,%2,%3}, {%4,%5,%6,%7}, {%8,%9}, {%0,%1,%2,%3};\n"
    : "+f"(d[0]), "+f"(d[1]), "+f"(d[2]), "+f"(d[3])
    : "r"(a0), "r"(a1), "r"(a2), "r"(a3), "r"(b0), "r"(b1));
}

__device__ __forceinline__ void pack2(float x, float y,
                                      uint32_t* hp, uint32_t* lp)
{
  __nv_bfloat162 h2 = __floats2bfloat162_rn(x, y);
  float hx = __bfloat162float(h2.x), hy = __bfloat162float(h2.y);
  __nv_bfloat162 l2 = __floats2bfloat162_rn(x - hx, y - hy);
  *hp = *reinterpret_cast<uint32_t*>(&h2);
  *lp = *reinterpret_cast<uint32_t*>(&l2);
}

__device__ __forceinline__ void cp16(uint32_t dst, const void* src) {
  asm volatile("cp.async.cg.shared.global [%0], [%1], 16;" :: "r"(dst), "l"(src));
}
__device__ __forceinline__ void cp_commit() {
  asm volatile("cp.async.commit_group;");
}
__device__ __forceinline__ void cp_wait0() {
  asm volatile("cp.async.wait_group 0;" ::: "memory");
}
__device__ __forceinline__ uint32_t s2u(const void* p) {
  return (uint32_t)__cvta_generic_to_shared(p);
}

// Stage one 16-kpair slice of 3 matrices (q,k,v) via cp.async. 3072 16B chunks.
__device__ __forceinline__ void stage3(uint32_t* sw,
    const uint32_t* __restrict__ gWh, const uint32_t* __restrict__ gWl,
    int ks, int tid)
{
#pragma unroll
  for (int i = 0; i < 6; ++i) {
    int idx = tid + i * TPB;           // 0..3071
    int mat = idx >> 10;
    int hl  = (idx >> 9) & 1;
    int row = (idx >> 5) & 15;
    int c   = idx & 31;
    const uint32_t* src = (hl ? gWl : gWh) + mat * 8192 + (ks * 16 + row) * 128 + c * 4;
    uint32_t* dst = sw + ((mat * 2 + hl) * 16 + row) * WROW + c * 4;
    cp16(s2u(dst), src);
  }
  cp_commit();
}

// Stage one 16-kpair slice of a single matrix. 1024 chunks.
__device__ __forceinline__ void stage1(uint32_t* sw,
    const uint32_t* __restrict__ gWh, const uint32_t* __restrict__ gWl,
    int ks, int tid)
{
#pragma unroll
  for (int i = 0; i < 2; ++i) {
    int idx = tid + i * TPB;           // 0..1023
    int hl  = (idx >> 9) & 1;
    int row = (idx >> 5) & 15;
    int c   = idx & 31;
    const uint32_t* src = (hl ? gWl : gWh) + (ks * 16 + row) * 128 + c * 4;
    uint32_t* dst = sw + (hl * 16 + row) * WROW + c * 4;
    cp16(s2u(dst), src);
  }
  cp_commit();
}

// LN over rows of src, split-packed into ahp/alp (16 warps).
__device__ __forceinline__ void ln_split(const float (*src)[F],
    uint32_t (*ahp)[APAD], uint32_t (*alp)[APAD], int tid)
{
  const int w = tid >> 5, l = tid & 31;
  for (int n = w; n < N; n += 16) {
    float2 p0 = *(const float2*)&src[n][2 * l];
    float2 p1 = *(const float2*)&src[n][64 + 2 * l];
    float sm = p0.x + p0.y + p1.x + p1.y;
#pragma unroll
    for (int o = 16; o; o >>= 1) sm += __shfl_xor_sync(0xffffffffu, sm, o);
    float mean = sm * (1.f / 128.f);
    float d0 = p0.x - mean, d1 = p0.y - mean, d2 = p1.x - mean, d3 = p1.y - mean;
    float ss = d0 * d0 + d1 * d1 + d2 * d2 + d3 * d3;
#pragma unroll
    for (int o = 16; o; o >>= 1) ss += __shfl_xor_sync(0xffffffffu, ss, o);
    float inv = rsqrtf(ss * (1.f / 128.f) + 1e-5f);
    d0 *= inv; d1 *= inv; d2 *= inv; d3 *= inv;
    pack2(d0, d1, &ahp[n][l],      &alp[n][l]);
    pack2(d2, d3, &ahp[n][l + 32], &alp[n][l + 32]);
  }
}

// Fused q,k,v GEMM: one A-fragment load feeds 3 accumulator sets.
__device__ __forceinline__ void gemm_qkv(Smem& s,
    const uint32_t* __restrict__ gWh, const uint32_t* __restrict__ gWl,
    int tid, float aq[4][4], float ak[4][4], float av[4][4])
{
  const int warp = tid >> 5, lane = tid & 31;
  const int mb = (warp & 3) << 4;
  const int nb = (warp >> 2) << 5;
  const int lm = lane >> 2, tig = lane & 3;

#pragma unroll
  for (int t = 0; t < 4; ++t)
#pragma unroll
    for (int i = 0; i < 4; ++i) { aq[t][i] = 0.f; ak[t][i] = 0.f; av[t][i] = 0.f; }

  uint32_t* bufA = s.swA;
  uint32_t* bufB = s.u1h;   // overlay: u1/vt region is dead during weight GEMMs

  stage3(bufA, gWh, gWl, 0, tid);
  cp_wait0();
  __syncthreads();

  for (int ks = 0; ks < 4; ++ks) {
    uint32_t* cur = (ks & 1) ? bufB : bufA;
    if (ks < 3) stage3((ks & 1) ? bufA : bufB, gWh, gWl, ks + 1, tid);
#pragma unroll
    for (int half = 0; half < 2; ++half) {
      const int kp0 = ks * 16 + half * 8;
      const int kr  = half * 8;
      uint32_t ah0 = s.ahp[mb + lm    ][kp0 + tig];
      uint32_t ah1 = s.ahp[mb + lm + 8][kp0 + tig];
      uint32_t ah2 = s.ahp[mb + lm    ][kp0 + tig + 4];
      uint32_t ah3 = s.ahp[mb + lm + 8][kp0 + tig + 4];
      uint32_t al0 = s.alp[mb + lm    ][kp0 + tig];
      uint32_t al1 = s.alp[mb + lm + 8][kp0 + tig];
      uint32_t al2 = s.alp[mb + lm    ][kp0 + tig + 4];
      uint32_t al3 = s.alp[mb + lm + 8][kp0 + tig + 4];
#pragma unroll
      for (int t = 0; t < 4; ++t) {
        const int n0 = nb + t * 8 + lm;
#pragma unroll
        for (int mat = 0; mat < 3; ++mat) {
          const uint32_t* rh = cur + ((mat * 2 + 0) * 16) * WROW;
          const uint32_t* rl = cur + ((mat * 2 + 1) * 16) * WROW;
          uint32_t bh0 = rh[(kr + tig    ) * WROW + n0];
          uint32_t bh1 = rh[(kr + tig + 4) * WROW + n0];
          uint32_t bl0 = rl[(kr + tig    ) * WROW + n0];
          uint32_t bl1 = rl[(kr + tig + 4) * WROW + n0];
          float* a = (mat == 0) ? aq[t] : (mat == 1) ? ak[t] : av[t];
          mma_bf16(a, ah0, ah1, ah2, ah3, bh0, bh1);
          mma_bf16(a, ah0, ah1, ah2, ah3, bl0, bl1);
          mma_bf16(a, al0, al1, al2, al3, bh0, bh1);
        }
      }
    }
    if (ks < 3) cp_wait0();
    __syncthreads();
  }
}

// Single-matrix GEMM (Wo, Wf), double-buffered in swA slots 0/1.
__device__ __forceinline__ void gemm_one(Smem& s,
    const uint32_t* __restrict__ gWh, const uint32_t* __restrict__ gWl,
    int tid, float acc[4][4])
{
  const int warp = tid >> 5, lane = tid & 31;
  const int mb = (warp & 3) << 4;
  const int nb = (warp >> 2) << 5;
  const int lm = lane >> 2, tig = lane & 3;

#pragma unroll
  for (int t = 0; t < 4; ++t)
#pragma unroll
    for (int i = 0; i < 4; ++i) acc[t][i] = 0.f;

  stage1(s.swA, gWh, gWl, 0, tid);
  cp_wait0();
  __syncthreads();

  for (int ks = 0; ks < 4; ++ks) {
    uint32_t* cur = s.swA + (ks & 1) * WSLOT;
    if (ks < 3) stage1(s.swA + ((ks & 1) ^ 1) * WSLOT, gWh, gWl, ks + 1, tid);
#pragma unroll
    for (int half = 0; half < 2; ++half) {
      const int kp0 = ks * 16 + half * 8;
      const int kr  = half * 8;
      uint32_t ah0 = s.ahp[mb + lm    ][kp0 + tig];
      uint32_t ah1 = s.ahp[mb + lm + 8][kp0 + tig];
      uint32_t ah2 = s.ahp[mb + lm    ][kp0 + tig + 4];
      uint32_t ah3 = s.ahp[mb + lm + 8][kp0 + tig + 4];
      uint32_t al0 = s.alp[mb + lm    ][kp0 + tig];
      uint32_t al1 = s.alp[mb + lm + 8][kp0 + tig];
      uint32_t al2 = s.alp[mb + lm    ][kp0 + tig + 4];
      uint32_t al3 = s.alp[mb + lm + 8][kp0 + tig + 4];
#pragma unroll
      for (int t = 0; t < 4; ++t) {
        const int n0 = nb + t * 8 + lm;
        uint32_t bh0 = cur[(kr + tig     ) * WROW + n0];
        uint32_t bh1 = cur[(kr + tig + 4 ) * WROW + n0];
        uint32_t bl0 = cur[(16 + kr + tig    ) * WROW + n0];
        uint32_t bl1 = cur[(16 + kr + tig + 4) * WROW + n0];
        mma_bf16(acc[t], ah0, ah1, ah2, ah3, bh0, bh1);
        mma_bf16(acc[t], ah0, ah1, ah2, ah3, bl0, bl1);
        mma_bf16(acc[t], al0, al1, al2, al3, bh0, bh1);
      }
    }
    if (ks < 3) cp_wait0();
    __syncthreads();
  }
}

__global__ void __launch_bounds__(TPB, 1) gnn_kernel(
    const float* __restrict__ g_coords,
    const int*   __restrict__ g_species,
    const int*   __restrict__ g_mask,
    const float* __restrict__ g_embed,
    const float* __restrict__ g_We,
    const float* __restrict__ g_bf,
    float* __restrict__ g_out)
{
  extern __shared__ unsigned char smem_raw[];
  Smem& s = *reinterpret_cast<Smem*>(smem_raw);
  const int b = blockIdx.x;
  const int tid = threadIdx.x;

  if (tid < N) {
    s.mrow[tid] = (g_mask[b * N + tid] != 0) ? 1.f : 0.f;
    s.coords[tid][0] = g_coords[(b * N + tid) * 3 + 0];
    s.coords[tid][1] = g_coords[(b * N + tid) * 3 + 1];
    s.coords[tid][2] = g_coords[(b * N + tid) * 3 + 2];
  }
  for (int i = tid; i < N * F; i += TPB) {
    int n = i >> 7, f = i & (F - 1);
    int sp = g_species[b * N + n] - 1;
    float hv = g_embed[sp * F + f];
    s.h[n][f] = (g_mask[b * N + n] != 0) ? hv : 0.f;
  }
  __syncthreads();

  const int warp = tid >> 5, lane = tid & 31;
  const int mb = (warp & 3) << 4;
  const int nb = (warp >> 2) << 5;
  const int lm = lane >> 2, tig = lane & 3;
  const int rA = mb + lm, rB = mb + lm + 8;
  const int hh   = warp >> 3;        // attention head
  const int mblk = (warp >> 2) & 1;  // m-half / dh-half

  float aq[4][4], ak[4][4], av[4][4];

  for (int l = 0; l < 3; ++l) {
    if (tid < F) s.bf_l[tid] = g_bf[l * F + tid];
    if (tid >= 128 && tid < 128 + 14)
      ((float*)s.We_l)[tid - 128] = g_We[l * 14 + (tid - 128)];

    const uint32_t* wbase_h = g_whp + (size_t)(l * 5) * 8192;
    const uint32_t* wbase_l = g_wlp + (size_t)(l * 5) * 8192;

    // ---- hn = LN(h) -> ahp/alp ----
    ln_split(s.h, s.ahp, s.alp, tid);
    // (gemm_qkv's preload sync covers visibility)

    // ---- fused q,k,v ----
    gemm_qkv(s, wbase_h, wbase_l, tid, aq, ak, av);

    // q -> ahp/alp (overwrites LN; safe after gemm's final sync)
#pragma unroll
    for (int t = 0; t < 4; ++t) {
      int kp = (nb + t * 8 + 2 * tig) >> 1;
      pack2(aq[t][0], aq[t][1], &s.ahp[rA][kp], &s.alp[rA][kp]);
      pack2(aq[t][2], aq[t][3], &s.ahp[rB][kp], &s.alp[rB][kp]);
    }
    // k -> [kpair][m] in u1 (overwrites staging junk)
#pragma unroll
    for (int t = 0; t < 4; ++t) {
      int kp = (nb + t * 8 + 2 * tig) >> 1;
      pack2(ak[t][0], ak[t][1], &s.u1h[kp * KPAD + rA], &s.u1l[kp * KPAD + rA]);
      pack2(ak[t][2], ak[t][3], &s.u1h[kp * KPAD + rB], &s.u1l[kp * KPAD + rB]);
    }
    // v -> transposed [dh][mpair] via lane exchange
#pragma unroll
    for (int t = 0; t < 4; ++t) {
      int c = nb + t * 8 + 2 * tig;
      float p0 = __shfl_xor_sync(0xffffffffu, av[t][0], 4);
      float p1 = __shfl_xor_sync(0xffffffffu, av[t][1], 4);
      float p2 = __shfl_xor_sync(0xffffffffu, av[t][2], 4);
      float p3 = __shfl_xor_sync(0xffffffffu, av[t][3], 4);
      if ((lm & 1) == 0) {
        int mp = (mb + lm) >> 1;
        pack2(av[t][0], p0, &s.vth[c][mp],     &s.vtl[c][mp]);
        pack2(av[t][1], p1, &s.vth[c + 1][mp], &s.vtl[c + 1][mp]);
      } else {
        int mp = (mb + lm + 7) >> 1;
        pack2(p2, av[t][2], &s.vth[c][mp],     &s.vtl[c][mp]);
        pack2(p3, av[t][3], &s.vth[c + 1][mp], &s.vtl[c + 1][mp]);
      }
    }
    __syncthreads();   // q/k/v packs visible

    // ---- logits = q @ k^T (head hh, m-half mblk) ----
#pragma unroll
    for (int t = 0; t < 4; ++t)
#pragma unroll
      for (int i = 0; i < 4; ++i) aq[t][i] = 0.f;
#pragma unroll
    for (int ks = 0; ks < 4; ++ks) {
      const int kb = hh * 32 + ks * 8;
      uint32_t ah0 = s.ahp[rA][kb + tig],     ah1 = s.ahp[rB][kb + tig];
      uint32_t ah2 = s.ahp[rA][kb + tig + 4], ah3 = s.ahp[rB][kb + tig + 4];
      uint32_t al0 = s.alp[rA][kb + tig],     al1 = s.alp[rB][kb + tig];
      uint32_t al2 = s.alp[rA][kb + tig + 4], al3 = s.alp[rB][kb + tig + 4];
#pragma unroll
      for (int t = 0; t < 4; ++t) {
        const int m0 = mblk * 32 + t * 8 + lm;
        uint32_t bh0 = s.u1h[(kb + tig)     * KPAD + m0];
        uint32_t bh1 = s.u1h[(kb + tig + 4) * KPAD + m0];
        uint32_t bl0 = s.u1l[(kb + tig)     * KPAD + m0];
        uint32_t bl1 = s.u1l[(kb + tig + 4) * KPAD + m0];
        mma_bf16(aq[t], ah0, ah1, ah2, ah3, bh0, bh1);
        mma_bf16(aq[t], ah0, ah1, ah2, ah3, bl0, bl1);
        mma_bf16(aq[t], al0, al1, al2, al3, bh0, bh1);
      }
    }

    // ---- epilogue: scale + edge bias + mask + 1-barrier softmax -> attn ----
    {
      const float w0 = s.We_l[0][hh], w1 = s.We_l[1][hh], w2 = s.We_l[2][hh],
                  w3 = s.We_l[3][hh], w4 = s.We_l[4][hh], w5 = s.We_l[5][hh],
                  w6 = s.We_l[6][hh];
      const bool okA = s.mrow[rA] > 0.f, okB = s.mrow[rB] > 0.f;
      const float a0 = s.coords[rA][0], a1 = s.coords[rA][1], a2 = s.coords[rA][2];
      const float b0 = s.coords[rB][0], b1 = s.coords[rB][1], b2 = s.coords[rB][2];
      float xA[8], xB[8];
#pragma unroll
      for (int t = 0; t < 4; ++t) {
#pragma unroll
        for (int j = 0; j < 2; ++j) {
          const int m = mblk * 32 + t * 8 + 2 * tig + j;
          const float m0 = s.coords[m][0], m1 = s.coords[m][1], m2 = s.coords[m][2];
          const bool okm = s.mrow[m] > 0.f;
          {
            float dx = a0 - m0, dy = a1 - m1, dz = a2 - m2;
            float d = sqrtf(dx * dx + dy * dy + dz * dz + 1e-12f);
            float g1 = 1.f / (1.f + __expf(2.f - d));
            float g2 = 1.f / (1.f + __expf(4.f - d));
            float g3 = 1.f / (1.f + __expf(6.f - d));
            float bias = dx * w0 + dy * w1 + dz * w2 + d * w3
                       + g1 * w4 + g2 * w5 + g3 * w6;
            xA[2 * t + j] = (okA && okm) ? aq[t][j] * INV_SQRT_DH + bias : NEGV;
          }
          {
            float dx = b0 - m0, dy = b1 - m1, dz = b2 - m2;
            float d = sqrtf(dx * dx + dy * dy + dz * dz + 1e-12f);
            float g1 = 1.f / (1.f + __expf(2.f - d));
            float g2 = 1.f / (1.f + __expf(4.f - d));
            float g3 = 1.f / (1.f + __expf(6.f - d));
            float bias = dx * w0 + dy * w1 + dz * w2 + d * w3
                       + g1 * w4 + g2 * w5 + g3 * w6;
            xB[2 * t + j] = (okB && okm) ? aq[t][2 + j] * INV_SQRT_DH + bias : NEGV;
          }
        }
      }
      // local max
      float mxA = xA[0], mxB = xB[0];
#pragma unroll
      for (int i = 1; i < 8; ++i) { mxA = fmaxf(mxA, xA[i]); mxB = fmaxf(mxB, xB[i]); }
      mxA = fmaxf(mxA, __shfl_xor_sync(0xffffffffu, mxA, 1));
      mxA = fmaxf(mxA, __shfl_xor_sync(0xffffffffu, mxA, 2));
      mxB = fmaxf(mxB, __shfl_xor_sync(0xffffffffu, mxB, 1));
      mxB = fmaxf(mxB, __shfl_xor_sync(0xffffffffu, mxB, 2));
      // local sum of exp(x - local_max)
      float smA = 0.f, smB = 0.f;
#pragma unroll
      for (int i = 0; i < 8; ++i) {
        xA[i] = __expf(xA[i] - mxA); smA += xA[i];
        xB[i] = __expf(xB[i] - mxB); smB += xB[i];
      }
      smA += __shfl_xor_sync(0xffffffffu, smA, 1);
      smA += __shfl_xor_sync(0xffffffffu, smA, 2);
      smB += __shfl_xor_sync(0xffffffffu, smB, 1);
      smB += __shfl_xor_sync(0xffffffffu, smB, 2);
      if (tig == 0) {
        s.rmx[hh][rA][mblk] = mxA;  s.rsm[hh][rA][mblk] = smA;
        s.rmx[hh][rB][mblk] = mxB;  s.rsm[hh][rB][mblk] = smB;
      }
      __syncthreads();   // partials visible; also: k reads done before attn writes
      // combine halves
      float mA0 = s.rmx[hh][rA][0], mA1 = s.rmx[hh][rA][1];
      float gA = fmaxf(mA0, mA1);
      float dA = s.rsm[hh][rA][0] * __expf(mA0 - gA)
               + s.rsm[hh][rA][1] * __expf(mA1 - gA);
      float mB0 = s.rmx[hh][rB][0], mB1 = s.rmx[hh][rB][1];
      float gB = fmaxf(mB0, mB1);
      float dB = s.rsm[hh][rB][0] * __expf(mB0 - gB)
               + s.rsm[hh][rB][1] * __expf(mB1 - gB);
      const float scA = __expf(mxA - gA) / dA;
      const float scB = __expf(mxB - gB) / dB;
      const int baseA = (hh * 64 + rA) * TPAD;
      const int baseB = (hh * 64 + rB) * TPAD;
#pragma unroll
      for (int t = 0; t < 4; ++t) {
        int mp = mblk * 16 + t * 4 + tig;
        pack2(xA[2 * t] * scA, xA[2 * t + 1] * scA,
              &s.u1h[baseA + mp], &s.u1l[baseA + mp]);
        pack2(xB[2 * t] * scB, xB[2 * t + 1] * scB,
              &s.u1h[baseB + mp], &s.u1l[baseB + mp]);
      }
    }
    __syncthreads();   // attn visible before msg mma

    // ---- msg = attn @ v (head hh, dh-half mblk) -> pack into ahp/alp ----
#pragma unroll
    for (int t = 0; t < 4; ++t)
#pragma unroll
      for (int i = 0; i < 4; ++i) aq[t][i] = 0.f;
    {
      const int baseA = (hh * 64 + rA) * TPAD;
      const int baseB = (hh * 64 + rB) * TPAD;
      const int dhb = mblk * 32;
#pragma unroll
      for (int ks = 0; ks < 4; ++ks) {
        const int kb = ks * 8;
        uint32_t ah0 = s.u1h[baseA + kb + tig],     ah1 = s.u1h[baseB + kb + tig];
        uint32_t ah2 = s.u1h[baseA + kb + tig + 4], ah3 = s.u1h[baseB + kb + tig + 4];
        uint32_t al0 = s.u1l[baseA + kb + tig],     al1 = s.u1l[baseB + kb + tig];
        uint32_t al2 = s.u1l[baseA + kb + tig + 4], al3 = s.u1l[baseB + kb + tig + 4];
#pragma unroll
        for (int t = 0; t < 4; ++t) {
          const int dhg = hh * 64 + dhb + t * 8 + lm;
          uint32_t bh0 = s.vth[dhg][kb + tig];
          uint32_t bh1 = s.vth[dhg][kb + tig + 4];
          uint32_t bl0 = s.vtl[dhg][kb + tig];
          uint32_t bl1 = s.vtl[dhg][kb + tig + 4];
          mma_bf16(aq[t], ah0, ah1, ah2, ah3, bh0, bh1);
          mma_bf16(aq[t], ah0, ah1, ah2, ah3, bl0, bl1);
          mma_bf16(aq[t], al0, al1, al2, al3, bh0, bh1);
        }
      }
#pragma unroll
      for (int t = 0; t < 4; ++t) {
        int kp = hh * 32 + (dhb >> 1) + t * 4 + tig;
        pack2(aq[t][0], aq[t][1], &s.ahp[rA][kp], &s.alp[rA][kp]);
        pack2(aq[t][2], aq[t][3], &s.ahp[rB][kp], &s.alp[rB][kp]);
      }
    }
    // (gemm_one's preload sync covers msg-pack visibility)

    // ---- h += msg @ Wo ----
    gemm_one(s, wbase_h + 3 * 8192, wbase_l + 3 * 8192, tid, ak);
#pragma unroll
    for (int t = 0; t < 4; ++t) {
      int c = nb + t * 8 + 2 * tig;
      float2 h0 = *(float2*)&s.h[rA][c];
      h0.x += ak[t][0]; h0.y += ak[t][1];
      *(float2*)&s.h[rA][c] = h0;
      float2 h1 = *(float2*)&s.h[rB][c];
      h1.x += ak[t][2]; h1.y += ak[t][3];
      *(float2*)&s.h[rB][c] = h1;
    }
    __syncthreads();

    // ---- h = (h + tanh(LN(h) @ Wf + bf)) * mask ----
    ln_split(s.h, s.ahp, s.alp, tid);
    gemm_one(s, wbase_h + 4 * 8192, wbase_l + 4 * 8192, tid, ak);
    {
      float mr0 = s.mrow[rA];
      float mr1 = s.mrow[rB];
#pragma unroll
      for (int t = 0; t < 4; ++t) {
        int c = nb + t * 8 + 2 * tig;
        float2 h0 = *(float2*)&s.h[rA][c];
        h0.x = (h0.x + tanhf(ak[t][0] + s.bf_l[c]))     * mr0;
        h0.y = (h0.y + tanhf(ak[t][1] + s.bf_l[c + 1])) * mr0;
        *(float2*)&s.h[rA][c] = h0;
        float2 h1 = *(float2*)&s.h[rB][c];
        h1.x = (h1.x + tanhf(ak[t][2] + s.bf_l[c]))     * mr1;
        h1.y = (h1.y + tanhf(ak[t][3] + s.bf_l[c + 1])) * mr1;
        *(float2*)&s.h[rB][c] = h1;
      }
    }
    __syncthreads();
  }

  // ---- final layernorm -> global output ----
  {
    const int w = tid >> 5, ln = tid & 31;
    for (int n = w; n < N; n += 16) {
      float x0 = s.h[n][ln], x1 = s.h[n][ln + 32];
      float x2 = s.h[n][ln + 64], x3 = s.h[n][ln + 96];
      float sm = x0 + x1 + x2 + x3;
#pragma unroll
      for (int o = 16; o; o >>= 1) sm += __shfl_xor_sync(0xffffffffu, sm, o);
      float mean = sm * (1.f / 128.f);
      float d0 = x0 - mean, d1 = x1 - mean, d2 = x2 - mean, d3 = x3 - mean;
      float ss = d0 * d0 + d1 * d1 + d2 * d2 + d3 * d3;
#pragma unroll
      for (int o = 16; o; o >>= 1) ss += __shfl_xor_sync(0xffffffffu, ss, o);
      float inv = rsqrtf(ss * (1.f / 128.f) + 1e-5f);
      float* orow = g_out + (size_t)(b * N + n) * F;
      orow[ln]      = d0 * inv;
      orow[ln + 32] = d1 * inv;
      orow[ln + 64] = d2 * inv;
      orow[ln + 96] = d3 * inv;
    }
  }
}

// Split/pack all 15 weight matrices once.
__global__ void prep_weights(const float* __restrict__ Wq,
                             const float* __restrict__ Wk,
                             const float* __restrict__ Wv,
                             const float* __restrict__ Wo,
                             const float* __restrict__ Wf)
{
  int idx = blockIdx.x * blockDim.x + threadIdx.x;
  if (idx >= 15 * 64 * 128) return;
  int mat = idx >> 13;
  int kp  = (idx >> 7) & 63;
  int n   = idx & 127;
  int l = mat / 5, which = mat % 5;
  const float* W =
      (which == 0 ? Wq : which == 1 ? Wk : which == 2 ? Wv : which == 3 ? Wo : Wf)
      + l * F * F;
  float v0 = W[(2 * kp)     * F + n];
  float v1 = W[(2 * kp + 1) * F + n];
  __nv_bfloat162 h2 = __floats2bfloat162_rn(v0, v1);
  __nv_bfloat162 l2 = __floats2bfloat162_rn(v0 - __bfloat162float(h2.x),
                                            v1 - __bfloat162float(h2.y));
  g_whp[idx] = *reinterpret_cast<uint32_t*>(&h2);
  g_wlp[idx] = *reinterpret_cast<uint32_t*>(&l2);
}

}  // namespace

extern "C" void kernel_launch(void* const* d_in, const int* in_sizes, int n_in,
                              void* d_out, int out_size)
{
  (void)n_in; (void)out_size;
  const float* coords  = (const float*)d_in[0];
  const int*   species = (const int*)d_in[1];
  const int*   mask    = (const int*)d_in[2];
  const float* embed   = (const float*)d_in[3];
  const float* Wq      = (const float*)d_in[4];
  const float* Wk      = (const float*)d_in[5];
  const float* Wv      = (const float*)d_in[6];
  const float* Wo      = (const float*)d_in[7];
  const float* We      = (const float*)d_in[8];
  const float* Wf      = (const float*)d_in[9];
  const float* bf      = (const float*)d_in[10];

  const int B = in_sizes[0] / (N * 3);   // 2048

  prep_weights<<<(15 * 64 * 128 + 255) / 256, 256>>>(Wq, Wk, Wv, Wo, Wf);

  cudaFuncSetAttribute(gnn_kernel, cudaFuncAttributeMaxDynamicSharedMemorySize,
                       (int)sizeof(Smem));
  gnn_kernel<<<B, TPB, sizeof(Smem)>>>(coords, species, mask, embed,
                                       We, bf, (float*)d_out);
}

// round 9
// speedup vs baseline: 2.4641x; 1.0263x over previous
#include <cuda_runtime.h>
#include <cuda_bf16.h>
#include <stdint.h>
#include <math.h>

#define TPB 512

namespace {

constexpr int N = 64;
constexpr int F = 128;
constexpr int APAD = 68;   // [n][kpair] packed stride (A ops, q, k)
constexpr int TPAD = 36;   // [dh][mpair] & [hh][n][mpair] stride
constexpr int KPSL = 20;   // staged weight row stride (16 kpairs + 4 pad)
constexpr int SLICE = 128 * KPSL;     // words per half-matrix slice
constexpr int SLOT1 = 2 * SLICE;      // hi+lo single-matrix slice
constexpr float NEGV = -1e9f;
constexpr float INV_SQRT_DH = 0.125f;

// Pre-split weights, layout [15 matrices][n=128][kpair=64], bf16x2
__device__ uint32_t g_whp[15 * 64 * 128];
__device__ uint32_t g_wlp[15 * 64 * 128];

struct __align__(16) Smem {
  float h[N][F];
  uint32_t ahp[N][APAD], alp[N][APAD];   // LN(h) -> q -> msg -> LN(h)
  // overlay region (contiguous): k [m][APAD] / attn [hh*64+n][TPAD]; + staging buf B
  uint32_t u1h[4608], u1l[4608];
  uint32_t vth[F][TPAD], vtl[F][TPAD];   // v transposed [dh][mpair]
  uint32_t swA[3 * SLOT1];               // staging buf A (qkv) / double buf (Wo,Wf)
  float rmx[2][64][2], rsm[2][64][2];
  float coords[N][3];
  float mrow[N];
  float bf_l[F];
  float We_l[7][2];
};

__device__ __forceinline__ void mma_bf16(float* d,
    uint32_t a0, uint32_t a1, uint32_t a2, uint32_t a3,
    uint32_t b0, uint32_t b1)
{
  asm volatile(
    "mma.sync.aligned.m16n8k16.row.col.f32.bf16.bf16.f32 "
    "{%0,%1,%2,%3}, {%4,%5,%6,%7}, {%8,%9}, {%0,%1,%2,%3};\n"
    : "+f"(d[0]), "+f"(d[1]), "+f"(d[2]), "+f"(d[3])
    : "r"(a0), "r"(a1), "r"(a2), "r"(a3), "r"(b0), "r"(b1));
}

__device__ __forceinline__ void ldsm4(uint32_t& r0, uint32_t& r1,
                                      uint32_t& r2, uint32_t& r3, uint32_t a)
{
  asm volatile("ldmatrix.sync.aligned.m8n8.x4.shared.b16 {%0,%1,%2,%3}, [%4];"
               : "=r"(r0), "=r"(r1), "=r"(r2), "=r"(r3) : "r"(a));
}

__device__ __forceinline__ void pack2(float x, float y,
                                      uint32_t* hp, uint32_t* lp)
{
  __nv_bfloat162 h2 = __floats2bfloat162_rn(x, y);
  float hx = __bfloat162float(h2.x), hy = __bfloat162float(h2.y);
  __nv_bfloat162 l2 = __floats2bfloat162_rn(x - hx, y - hy);
  *hp = *reinterpret_cast<uint32_t*>(&h2);
  *lp = *reinterpret_cast<uint32_t*>(&l2);
}

__device__ __forceinline__ void cp16(uint32_t dst, const void* src) {
  asm volatile("cp.async.cg.shared.global [%0], [%1], 16;" :: "r"(dst), "l"(src));
}
__device__ __forceinline__ void cp_commit() { asm volatile("cp.async.commit_group;"); }
__device__ __forceinline__ void cp_wait0() {
  asm volatile("cp.async.wait_group 0;" ::: "memory");
}
__device__ __forceinline__ uint32_t s2u(const void* p) {
  return (uint32_t)__cvta_generic_to_shared(p);
}

// Stage one 16-kpair slice of 3 matrices into [mat][hl][n][KPSL]. 3072 chunks.
__device__ __forceinline__ void stage3(uint32_t* sw,
    const uint32_t* __restrict__ gWh, const uint32_t* __restrict__ gWl,
    int ks, int tid)
{
#pragma unroll
  for (int i = 0; i < 6; ++i) {
    int idx = tid + i * TPB;
    int mat = idx >> 10;
    int hl  = (idx >> 9) & 1;
    int c   = idx & 511;
    int n   = c >> 2, q = c & 3;
    const uint32_t* src = (hl ? gWl : gWh) + mat * 8192 + n * 64 + ks * 16 + q * 4;
    uint32_t* dst = sw + (mat * 2 + hl) * SLICE + n * KPSL + q * 4;
    cp16(s2u(dst), src);
  }
  cp_commit();
}

// Stage one slice of a single matrix. 1024 chunks.
__device__ __forceinline__ void stage1(uint32_t* sw,
    const uint32_t* __restrict__ gWh, const uint32_t* __restrict__ gWl,
    int ks, int tid)
{
#pragma unroll
  for (int i = 0; i < 2; ++i) {
    int idx = tid + i * TPB;
    int hl  = (idx >> 9) & 1;
    int c   = idx & 511;
    int n   = c >> 2, q = c & 3;
    const uint32_t* src = (hl ? gWl : gWh) + n * 64 + ks * 16 + q * 4;
    uint32_t* dst = sw + hl * SLICE + n * KPSL + q * 4;
    cp16(s2u(dst), src);
  }
  cp_commit();
}

// LN over rows of src, split-packed into ahp/alp.
__device__ __forceinline__ void ln_split(const float (*src)[F],
    uint32_t (*ahp)[APAD], uint32_t (*alp)[APAD], int tid)
{
  const int w = tid >> 5, l = tid & 31;
  for (int n = w; n < N; n += 16) {
    float2 p0 = *(const float2*)&src[n][2 * l];
    float2 p1 = *(const float2*)&src[n][64 + 2 * l];
    float sm = p0.x + p0.y + p1.x + p1.y;
#pragma unroll
    for (int o = 16; o; o >>= 1) sm += __shfl_xor_sync(0xffffffffu, sm, o);
    float mean = sm * (1.f / 128.f);
    float d0 = p0.x - mean, d1 = p0.y - mean, d2 = p1.x - mean, d3 = p1.y - mean;
    float ss = d0 * d0 + d1 * d1 + d2 * d2 + d3 * d3;
#pragma unroll
    for (int o = 16; o; o >>= 1) ss += __shfl_xor_sync(0xffffffffu, ss, o);
    float inv = rsqrtf(ss * (1.f / 128.f) + 1e-5f);
    d0 *= inv; d1 *= inv; d2 *= inv; d3 *= inv;
    pack2(d0, d1, &ahp[n][l],      &alp[n][l]);
    pack2(d2, d3, &ahp[n][l + 32], &alp[n][l + 32]);
  }
}

__global__ void __launch_bounds__(TPB, 1) gnn_kernel(
    const float* __restrict__ g_coords,
    const int*   __restrict__ g_species,
    const int*   __restrict__ g_mask,
    const float* __restrict__ g_embed,
    const float* __restrict__ g_We,
    const float* __restrict__ g_bf,
    float* __restrict__ g_out)
{
  extern __shared__ unsigned char smem_raw[];
  Smem& s = *reinterpret_cast<Smem*>(smem_raw);
  const int b = blockIdx.x;
  const int tid = threadIdx.x;

  if (tid < N) {
    s.mrow[tid] = (g_mask[b * N + tid] != 0) ? 1.f : 0.f;
    s.coords[tid][0] = g_coords[(b * N + tid) * 3 + 0];
    s.coords[tid][1] = g_coords[(b * N + tid) * 3 + 1];
    s.coords[tid][2] = g_coords[(b * N + tid) * 3 + 2];
  }
  for (int i = tid; i < N * F; i += TPB) {
    int n = i >> 7, f = i & (F - 1);
    int sp = g_species[b * N + n] - 1;
    float hv = g_embed[sp * F + f];
    s.h[n][f] = (g_mask[b * N + n] != 0) ? hv : 0.f;
  }
  __syncthreads();

  const int warp = tid >> 5, lane = tid & 31;
  const int mb = (warp & 3) << 4;
  const int nb = (warp >> 2) << 5;
  const int lm = lane >> 2, tig = lane & 3;
  const int rA = mb + lm, rB = mb + lm + 8;
  const int hh   = warp >> 3;
  const int mblk = (warp >> 2) & 1;

  // ldmatrix per-thread geometry
  const int g8 = lane >> 3, r8 = lane & 7;   // tile group, row-in-tile
  const int hl8 = g8 >> 1, bs8 = g8 & 1;     // B: hi/lo array, b0/b1 quad
  // A-op bases (ahp/alp [row][kp]): tiles (rows mb..+7 | mb+8..15) x (kp+0 | kp+4)
  const uint32_t aBaseH = s2u(&s.ahp[mb + (g8 & 1) * 8 + r8][(g8 >> 1) * 4]);
  const uint32_t aBaseL = s2u(&s.alp[mb + (g8 & 1) * 8 + r8][(g8 >> 1) * 4]);
  // weight B base offset (buffer-relative, bytes)
  const uint32_t bOff0 = (uint32_t)(hl8 * SLICE + r8 * KPSL + bs8 * 4) * 4;
  // logits B (k in u1 [m][APAD])
  const uint32_t kBase = s2u(hl8 ? s.u1l : s.u1h) + (uint32_t)(r8 * APAD + bs8 * 4) * 4;
  // msg A (attn in u1 [hh*64+n][TPAD])
  const uint32_t atBaseH = s2u(s.u1h)
      + (uint32_t)((hh * 64 + mb + (g8 & 1) * 8 + r8) * TPAD + (g8 >> 1) * 4) * 4;
  const uint32_t atBaseL = s2u(s.u1l)
      + (uint32_t)((hh * 64 + mb + (g8 & 1) * 8 + r8) * TPAD + (g8 >> 1) * 4) * 4;
  // msg B (v in vth/vtl [dh][mpair])
  const uint32_t vBase = s2u(hl8 ? (uint32_t*)s.vtl : (uint32_t*)s.vth)
      + (uint32_t)(r8 * TPAD + bs8 * 4) * 4;

  const uint32_t swAAddr = s2u(s.swA);
  const uint32_t ovlAddr = s2u(s.u1h);   // qkv staging buffer B overlay

  float aq[4][4], ak[4][4], av[4][4];

  for (int l = 0; l < 3; ++l) {
    if (tid < F) s.bf_l[tid] = g_bf[l * F + tid];
    if (tid >= 128 && tid < 128 + 14)
      ((float*)s.We_l)[tid - 128] = g_We[l * 14 + (tid - 128)];

    const uint32_t* wbase_h = g_whp + (size_t)(l * 5) * 8192;
    const uint32_t* wbase_l = g_wlp + (size_t)(l * 5) * 8192;

    // ---- hn = LN(h) -> ahp/alp ----
    ln_split(s.h, s.ahp, s.alp, tid);

    // ---- fused q,k,v GEMM ----
#pragma unroll
    for (int t = 0; t < 4; ++t)
#pragma unroll
      for (int i = 0; i < 4; ++i) { aq[t][i] = 0.f; ak[t][i] = 0.f; av[t][i] = 0.f; }
    stage3(s.swA, wbase_h, wbase_l, 0, tid);
    cp_wait0();
    __syncthreads();
    for (int ks = 0; ks < 4; ++ks) {
      const uint32_t curB = (ks & 1) ? ovlAddr : swAAddr;
      if (ks < 3)
        stage3((ks & 1) ? s.swA : s.u1h, wbase_h, wbase_l, ks + 1, tid);
#pragma unroll
      for (int half = 0; half < 2; ++half) {
        const uint32_t aoff = (uint32_t)(ks * 16 + half * 8) * 4;
        uint32_t ah0, ah1, ah2, ah3, al0, al1, al2, al3;
        ldsm4(ah0, ah1, ah2, ah3, aBaseH + aoff);
        ldsm4(al0, al1, al2, al3, aBaseL + aoff);
#pragma unroll
        for (int t = 0; t < 4; ++t) {
          const uint32_t rowoff = (uint32_t)((nb + t * 8) * KPSL + half * 8) * 4;
#pragma unroll
          for (int mat = 0; mat < 3; ++mat) {
            uint32_t bh0, bh1, bl0, bl1;
            ldsm4(bh0, bh1, bl0, bl1,
                  curB + bOff0 + (uint32_t)(mat * 2 * SLICE) * 4 + rowoff);
            float* a = (mat == 0) ? aq[t] : (mat == 1) ? ak[t] : av[t];
            mma_bf16(a, ah0, ah1, ah2, ah3, bh0, bh1);
            mma_bf16(a, ah0, ah1, ah2, ah3, bl0, bl1);
            mma_bf16(a, al0, al1, al2, al3, bh0, bh1);
          }
        }
      }
      if (ks < 3) cp_wait0();
      __syncthreads();
    }

    // q -> ahp/alp
#pragma unroll
    for (int t = 0; t < 4; ++t) {
      int kp = (nb + t * 8 + 2 * tig) >> 1;
      pack2(aq[t][0], aq[t][1], &s.ahp[rA][kp], &s.alp[rA][kp]);
      pack2(aq[t][2], aq[t][3], &s.ahp[rB][kp], &s.alp[rB][kp]);
    }
    // k -> u1 [m][APAD] (same layout as q)
#pragma unroll
    for (int t = 0; t < 4; ++t) {
      int kp = (nb + t * 8 + 2 * tig) >> 1;
      pack2(ak[t][0], ak[t][1], &s.u1h[rA * APAD + kp], &s.u1l[rA * APAD + kp]);
      pack2(ak[t][2], ak[t][3], &s.u1h[rB * APAD + kp], &s.u1l[rB * APAD + kp]);
    }
    // v -> transposed [dh][mpair]
#pragma unroll
    for (int t = 0; t < 4; ++t) {
      int c = nb + t * 8 + 2 * tig;
      float p0 = __shfl_xor_sync(0xffffffffu, av[t][0], 4);
      float p1 = __shfl_xor_sync(0xffffffffu, av[t][1], 4);
      float p2 = __shfl_xor_sync(0xffffffffu, av[t][2], 4);
      float p3 = __shfl_xor_sync(0xffffffffu, av[t][3], 4);
      if ((lm & 1) == 0) {
        int mp = (mb + lm) >> 1;
        pack2(av[t][0], p0, &s.vth[c][mp],     &s.vtl[c][mp]);
        pack2(av[t][1], p1, &s.vth[c + 1][mp], &s.vtl[c + 1][mp]);
      } else {
        int mp = (mb + lm + 7) >> 1;
        pack2(p2, av[t][2], &s.vth[c][mp],     &s.vtl[c][mp]);
        pack2(p3, av[t][3], &s.vth[c + 1][mp], &s.vtl[c + 1][mp]);
      }
    }
    __syncthreads();

    // ---- logits = q @ k^T (head hh, m-half mblk) ----
#pragma unroll
    for (int t = 0; t < 4; ++t)
#pragma unroll
      for (int i = 0; i < 4; ++i) aq[t][i] = 0.f;
#pragma unroll
    for (int ks = 0; ks < 4; ++ks) {
      const uint32_t aoff = (uint32_t)(hh * 32 + ks * 8) * 4;
      uint32_t ah0, ah1, ah2, ah3, al0, al1, al2, al3;
      ldsm4(ah0, ah1, ah2, ah3, aBaseH + aoff);
      ldsm4(al0, al1, al2, al3, aBaseL + aoff);
#pragma unroll
      for (int t = 0; t < 4; ++t) {
        uint32_t bh0, bh1, bl0, bl1;
        ldsm4(bh0, bh1, bl0, bl1,
              kBase + (uint32_t)((mblk * 32 + t * 8) * APAD + hh * 32 + ks * 8) * 4);
        mma_bf16(aq[t], ah0, ah1, ah2, ah3, bh0, bh1);
        mma_bf16(aq[t], ah0, ah1, ah2, ah3, bl0, bl1);
        mma_bf16(aq[t], al0, al1, al2, al3, bh0, bh1);
      }
    }

    // ---- epilogue: scale + edge bias + mask + 1-barrier softmax -> attn ----
    {
      const float w0 = s.We_l[0][hh], w1 = s.We_l[1][hh], w2 = s.We_l[2][hh],
                  w3 = s.We_l[3][hh], w4 = s.We_l[4][hh], w5 = s.We_l[5][hh],
                  w6 = s.We_l[6][hh];
      const bool okA = s.mrow[rA] > 0.f, okB = s.mrow[rB] > 0.f;
      const float a0 = s.coords[rA][0], a1 = s.coords[rA][1], a2 = s.coords[rA][2];
      const float b0 = s.coords[rB][0], b1 = s.coords[rB][1], b2 = s.coords[rB][2];
      float xA[8], xB[8];
#pragma unroll
      for (int t = 0; t < 4; ++t) {
#pragma unroll
        for (int j = 0; j < 2; ++j) {
          const int m = mblk * 32 + t * 8 + 2 * tig + j;
          const float m0 = s.coords[m][0], m1 = s.coords[m][1], m2 = s.coords[m][2];
          const bool okm = s.mrow[m] > 0.f;
          {
            float dx = a0 - m0, dy = a1 - m1, dz = a2 - m2;
            float d = sqrtf(dx * dx + dy * dy + dz * dz + 1e-12f);
            float g1 = 1.f / (1.f + __expf(2.f - d));
            float g2 = 1.f / (1.f + __expf(4.f - d));
            float g3 = 1.f / (1.f + __expf(6.f - d));
            float bias = dx * w0 + dy * w1 + dz * w2 + d * w3
                       + g1 * w4 + g2 * w5 + g3 * w6;
            xA[2 * t + j] = (okA && okm) ? aq[t][j] * INV_SQRT_DH + bias : NEGV;
          }
          {
            float dx = b0 - m0, dy = b1 - m1, dz = b2 - m2;
            float d = sqrtf(dx * dx + dy * dy + dz * dz + 1e-12f);
            float g1 = 1.f / (1.f + __expf(2.f - d));
            float g2 = 1.f / (1.f + __expf(4.f - d));
            float g3 = 1.f / (1.f + __expf(6.f - d));
            float bias = dx * w0 + dy * w1 + dz * w2 + d * w3
                       + g1 * w4 + g2 * w5 + g3 * w6;
            xB[2 * t + j] = (okB && okm) ? aq[t][2 + j] * INV_SQRT_DH + bias : NEGV;
          }
        }
      }
      float mxA = xA[0], mxB = xB[0];
#pragma unroll
      for (int i = 1; i < 8; ++i) { mxA = fmaxf(mxA, xA[i]); mxB = fmaxf(mxB, xB[i]); }
      mxA = fmaxf(mxA, __shfl_xor_sync(0xffffffffu, mxA, 1));
      mxA = fmaxf(mxA, __shfl_xor_sync(0xffffffffu, mxA, 2));
      mxB = fmaxf(mxB, __shfl_xor_sync(0xffffffffu, mxB, 1));
      mxB = fmaxf(mxB, __shfl_xor_sync(0xffffffffu, mxB, 2));
      float smA = 0.f, smB = 0.f;
#pragma unroll
      for (int i = 0; i < 8; ++i) {
        xA[i] = __expf(xA[i] - mxA); smA += xA[i];
        xB[i] = __expf(xB[i] - mxB); smB += xB[i];
      }
      smA += __shfl_xor_sync(0xffffffffu, smA, 1);
      smA += __shfl_xor_sync(0xffffffffu, smA, 2);
      smB += __shfl_xor_sync(0xffffffffu, smB, 1);
      smB += __shfl_xor_sync(0xffffffffu, smB, 2);
      if (tig == 0) {
        s.rmx[hh][rA][mblk] = mxA;  s.rsm[hh][rA][mblk] = smA;
        s.rmx[hh][rB][mblk] = mxB;  s.rsm[hh][rB][mblk] = smB;
      }
      __syncthreads();   // partials visible; k reads done before attn overwrite
      float mA0 = s.rmx[hh][rA][0], mA1 = s.rmx[hh][rA][1];
      float gA = fmaxf(mA0, mA1);
      float dA = s.rsm[hh][rA][0] * __expf(mA0 - gA)
               + s.rsm[hh][rA][1] * __expf(mA1 - gA);
      float mB0 = s.rmx[hh][rB][0], mB1 = s.rmx[hh][rB][1];
      float gB = fmaxf(mB0, mB1);
      float dB = s.rsm[hh][rB][0] * __expf(mB0 - gB)
               + s.rsm[hh][rB][1] * __expf(mB1 - gB);
      const float scA = __expf(mxA - gA) / dA;
      const float scB = __expf(mxB - gB) / dB;
      const int baseA = (hh * 64 + rA) * TPAD;
      const int baseB = (hh * 64 + rB) * TPAD;
#pragma unroll
      for (int t = 0; t < 4; ++t) {
        int mp = mblk * 16 + t * 4 + tig;
        pack2(xA[2 * t] * scA, xA[2 * t + 1] * scA,
              &s.u1h[baseA + mp], &s.u1l[baseA + mp]);
        pack2(xB[2 * t] * scB, xB[2 * t + 1] * scB,
              &s.u1h[baseB + mp], &s.u1l[baseB + mp]);
      }
    }
    __syncthreads();

    // ---- msg = attn @ v (head hh, dh-half mblk) -> pack into ahp/alp ----
#pragma unroll
    for (int t = 0; t < 4; ++t)
#pragma unroll
      for (int i = 0; i < 4; ++i) aq[t][i] = 0.f;
    {
      const int dhb = mblk * 32;
#pragma unroll
      for (int ks = 0; ks < 4; ++ks) {
        const uint32_t aoff = (uint32_t)(ks * 8) * 4;
        uint32_t ah0, ah1, ah2, ah3, al0, al1, al2, al3;
        ldsm4(ah0, ah1, ah2, ah3, atBaseH + aoff);
        ldsm4(al0, al1, al2, al3, atBaseL + aoff);
#pragma unroll
        for (int t = 0; t < 4; ++t) {
          uint32_t bh0, bh1, bl0, bl1;
          ldsm4(bh0, bh1, bl0, bl1,
                vBase + (uint32_t)((hh * 64 + dhb + t * 8) * TPAD + ks * 8) * 4);
          mma_bf16(aq[t], ah0, ah1, ah2, ah3, bh0, bh1);
          mma_bf16(aq[t], ah0, ah1, ah2, ah3, bl0, bl1);
          mma_bf16(aq[t], al0, al1, al2, al3, bh0, bh1);
        }
      }
#pragma unroll
      for (int t = 0; t < 4; ++t) {
        int kp = hh * 32 + (dhb >> 1) + t * 4 + tig;
        pack2(aq[t][0], aq[t][1], &s.ahp[rA][kp], &s.alp[rA][kp]);
        pack2(aq[t][2], aq[t][3], &s.ahp[rB][kp], &s.alp[rB][kp]);
      }
    }

    // ---- h += msg @ Wo ----
    {
      const uint32_t* gh = wbase_h + 3 * 8192;
      const uint32_t* gl = wbase_l + 3 * 8192;
#pragma unroll
      for (int t = 0; t < 4; ++t)
#pragma unroll
        for (int i = 0; i < 4; ++i) ak[t][i] = 0.f;
      stage1(s.swA, gh, gl, 0, tid);
      cp_wait0();
      __syncthreads();
      for (int ks = 0; ks < 4; ++ks) {
        const uint32_t curB = swAAddr + (uint32_t)((ks & 1) * SLOT1) * 4;
        if (ks < 3) stage1(s.swA + (((ks & 1) ^ 1) * SLOT1), gh, gl, ks + 1, tid);
#pragma unroll
        for (int half = 0; half < 2; ++half) {
          const uint32_t aoff = (uint32_t)(ks * 16 + half * 8) * 4;
          uint32_t ah0, ah1, ah2, ah3, al0, al1, al2, al3;
          ldsm4(ah0, ah1, ah2, ah3, aBaseH + aoff);
          ldsm4(al0, al1, al2, al3, aBaseL + aoff);
#pragma unroll
          for (int t = 0; t < 4; ++t) {
            uint32_t bh0, bh1, bl0, bl1;
            ldsm4(bh0, bh1, bl0, bl1,
                  curB + bOff0 + (uint32_t)((nb + t * 8) * KPSL + half * 8) * 4);
            mma_bf16(ak[t], ah0, ah1, ah2, ah3, bh0, bh1);
            mma_bf16(ak[t], ah0, ah1, ah2, ah3, bl0, bl1);
            mma_bf16(ak[t], al0, al1, al2, al3, bh0, bh1);
          }
        }
        if (ks < 3) cp_wait0();
        __syncthreads();
      }
    }
#pragma unroll
    for (int t = 0; t < 4; ++t) {
      int c = nb + t * 8 + 2 * tig;
      float2 h0 = *(float2*)&s.h[rA][c];
      h0.x += ak[t][0]; h0.y += ak[t][1];
      *(float2*)&s.h[rA][c] = h0;
      float2 h1 = *(float2*)&s.h[rB][c];
      h1.x += ak[t][2]; h1.y += ak[t][3];
      *(float2*)&s.h[rB][c] = h1;
    }
    __syncthreads();

    // ---- h = (h + tanh(LN(h) @ Wf + bf)) * mask ----
    ln_split(s.h, s.ahp, s.alp, tid);
    {
      const uint32_t* gh = wbase_h + 4 * 8192;
      const uint32_t* gl = wbase_l + 4 * 8192;
#pragma unroll
      for (int t = 0; t < 4; ++t)
#pragma unroll
        for (int i = 0; i < 4; ++i) ak[t][i] = 0.f;
      stage1(s.swA, gh, gl, 0, tid);
      cp_wait0();
      __syncthreads();
      for (int ks = 0; ks < 4; ++ks) {
        const uint32_t curB = swAAddr + (uint32_t)((ks & 1) * SLOT1) * 4;
        if (ks < 3) stage1(s.swA + (((ks & 1) ^ 1) * SLOT1), gh, gl, ks + 1, tid);
#pragma unroll
        for (int half = 0; half < 2; ++half) {
          const uint32_t aoff = (uint32_t)(ks * 16 + half * 8) * 4;
          uint32_t ah0, ah1, ah2, ah3, al0, al1, al2, al3;
          ldsm4(ah0, ah1, ah2, ah3, aBaseH + aoff);
          ldsm4(al0, al1, al2, al3, aBaseL + aoff);
#pragma unroll
          for (int t = 0; t < 4; ++t) {
            uint32_t bh0, bh1, bl0, bl1;
            ldsm4(bh0, bh1, bl0, bl1,
                  curB + bOff0 + (uint32_t)((nb + t * 8) * KPSL + half * 8) * 4);
            mma_bf16(ak[t], ah0, ah1, ah2, ah3, bh0, bh1);
            mma_bf16(ak[t], ah0, ah1, ah2, ah3, bl0, bl1);
            mma_bf16(ak[t], al0, al1, al2, al3, bh0, bh1);
          }
        }
        if (ks < 3) cp_wait0();
        __syncthreads();
      }
    }
    {
      float mr0 = s.mrow[rA];
      float mr1 = s.mrow[rB];
#pragma unroll
      for (int t = 0; t < 4; ++t) {
        int c = nb + t * 8 + 2 * tig;
        float2 h0 = *(float2*)&s.h[rA][c];
        h0.x = (h0.x + tanhf(ak[t][0] + s.bf_l[c]))     * mr0;
        h0.y = (h0.y + tanhf(ak[t][1] + s.bf_l[c + 1])) * mr0;
        *(float2*)&s.h[rA][c] = h0;
        float2 h1 = *(float2*)&s.h[rB][c];
        h1.x = (h1.x + tanhf(ak[t][2] + s.bf_l[c]))     * mr1;
        h1.y = (h1.y + tanhf(ak[t][3] + s.bf_l[c + 1])) * mr1;
        *(float2*)&s.h[rB][c] = h1;
      }
    }
    __syncthreads();
  }

  // ---- final layernorm -> global output ----
  {
    const int w = tid >> 5, ln = tid & 31;
    for (int n = w; n < N; n += 16) {
      float x0 = s.h[n][ln], x1 = s.h[n][ln + 32];
      float x2 = s.h[n][ln + 64], x3 = s.h[n][ln + 96];
      float sm = x0 + x1 + x2 + x3;
#pragma unroll
      for (int o = 16; o; o >>= 1) sm += __shfl_xor_sync(0xffffffffu, sm, o);
      float mean = sm * (1.f / 128.f);
      float d0 = x0 - mean, d1 = x1 - mean, d2 = x2 - mean, d3 = x3 - mean;
      float ss = d0 * d0 + d1 * d1 + d2 * d2 + d3 * d3;
#pragma unroll
      for (int o = 16; o; o >>= 1) ss += __shfl_xor_sync(0xffffffffu, ss, o);
      float inv = rsqrtf(ss * (1.f / 128.f) + 1e-5f);
      float* orow = g_out + (size_t)(b * N + n) * F;
      orow[ln]      = d0 * inv;
      orow[ln + 32] = d1 * inv;
      orow[ln + 64] = d2 * inv;
      orow[ln + 96] = d3 * inv;
    }
  }
}

// Split/pack all 15 weight matrices, layout [mat][n][kpair].
__global__ void prep_weights(const float* __restrict__ Wq,
                             const float* __restrict__ Wk,
                             const float* __restrict__ Wv,
                             const float* __restrict__ Wo,
                             const float* __restrict__ Wf)
{
  int idx = blockIdx.x * blockDim.x + threadIdx.x;
  if (idx >= 15 * 64 * 128) return;
  int mat = idx >> 13;
  int n   = (idx >> 6) & 127;
  int kp  = idx & 63;
  int l = mat / 5, which = mat % 5;
  const float* W =
      (which == 0 ? Wq : which == 1 ? Wk : which == 2 ? Wv : which == 3 ? Wo : Wf)
      + l * F * F;
  float v0 = W[(2 * kp)     * F + n];
  float v1 = W[(2 * kp + 1) * F + n];
  __nv_bfloat162 h2 = __floats2bfloat162_rn(v0, v1);
  __nv_bfloat162 l2 = __floats2bfloat162_rn(v0 - __bfloat162float(h2.x),
                                            v1 - __bfloat162float(h2.y));
  g_whp[idx] = *reinterpret_cast<uint32_t*>(&h2);
  g_wlp[idx] = *reinterpret_cast<uint32_t*>(&l2);
}

}  // namespace

extern "C" void kernel_launch(void* const* d_in, const int* in_sizes, int n_in,
                              void* d_out, int out_size)
{
  (void)n_in; (void)out_size;
  const float* coords  = (const float*)d_in[0];
  const int*   species = (const int*)d_in[1];
  const int*   mask    = (const int*)d_in[2];
  const float* embed   = (const float*)d_in[3];
  const float* Wq      = (const float*)d_in[4];
  const float* Wk      = (const float*)d_in[5];
  const float* Wv      = (const float*)d_in[6];
  const float* Wo      = (const float*)d_in[7];
  const float* We      = (const float*)d_in[8];
  const float* Wf      = (const float*)d_in[9];
  const float* bf      = (const float*)d_in[10];

  const int B = in_sizes[0] / (N * 3);   // 2048

  prep_weights<<<(15 * 64 * 128 + 255) / 256, 256>>>(Wq, Wk, Wv, Wo, Wf);

  cudaFuncSetAttribute(gnn_kernel, cudaFuncAttributeMaxDynamicSharedMemorySize,
                       (int)sizeof(Smem));
  gnn_kernel<<<B, TPB, sizeof(Smem)>>>(coords, species, mask, embed,
                                       We, bf, (float*)d_out);
}

// round 10
// speedup vs baseline: 2.8112x; 1.1408x over previous
#include <cuda_runtime.h>
#include <cuda_bf16.h>
#include <stdint.h>
#include <math.h>

#define TPB 512

namespace {

constexpr int N = 64;
constexpr int F = 128;
constexpr int APAD = 68;   // [n][kpair] packed stride (A ops, q, k)
constexpr int TPAD = 36;   // [dh][mpair] & [hh][n][mpair] stride
constexpr float NEGV = -1e9f;
constexpr float INV_SQRT_DH = 0.125f;

// Fragment-ordered split weights: [15 mats][kstep 8][ntile 16][lane 32] x uint4
// (.x = bh0, .y = bh1, .z = bl0, .w = bl1 — exactly what each lane's mma needs)
__device__ uint4 g_wfrag[15 * 8 * 16 * 32];

struct __align__(16) Smem {
  float h[N][F];
  uint32_t ahp[N][APAD], alp[N][APAD];   // LN(h) -> q -> msg -> LN(h)
  uint32_t u1h[4608], u1l[4608];         // k [m][APAD]  then  attn [hh*64+n][TPAD]
  uint32_t vth[F][TPAD], vtl[F][TPAD];   // v transposed [dh][mpair]
  float rmx[2][64][2], rsm[2][64][2];
  float coords[N][3];
  float mrow[N];
  float bf_l[F];
  float We_l[7][2];
};

__device__ __forceinline__ void mma_bf16(float* d,
    uint32_t a0, uint32_t a1, uint32_t a2, uint32_t a3,
    uint32_t b0, uint32_t b1)
{
  asm volatile(
    "mma.sync.aligned.m16n8k16.row.col.f32.bf16.bf16.f32 "
    "{%0,%1,%2,%3}, {%4,%5,%6,%7}, {%8,%9}, {%0,%1,%2,%3};\n"
    : "+f"(d[0]), "+f"(d[1]), "+f"(d[2]), "+f"(d[3])
    : "r"(a0), "r"(a1), "r"(a2), "r"(a3), "r"(b0), "r"(b1));
}

// 3-mma split product with fragment-packed weight
__device__ __forceinline__ void mma3(float* d,
    uint32_t ah0, uint32_t ah1, uint32_t ah2, uint32_t ah3,
    uint32_t al0, uint32_t al1, uint32_t al2, uint32_t al3,
    uint4 w)
{
  mma_bf16(d, ah0, ah1, ah2, ah3, w.x, w.y);
  mma_bf16(d, ah0, ah1, ah2, ah3, w.z, w.w);
  mma_bf16(d, al0, al1, al2, al3, w.x, w.y);
}

__device__ __forceinline__ void ldsm4(uint32_t& r0, uint32_t& r1,
                                      uint32_t& r2, uint32_t& r3, uint32_t a)
{
  asm volatile("ldmatrix.sync.aligned.m8n8.x4.shared.b16 {%0,%1,%2,%3}, [%4];"
               : "=r"(r0), "=r"(r1), "=r"(r2), "=r"(r3) : "r"(a));
}

__device__ __forceinline__ void pack2(float x, float y,
                                      uint32_t* hp, uint32_t* lp)
{
  __nv_bfloat162 h2 = __floats2bfloat162_rn(x, y);
  float hx = __bfloat162float(h2.x), hy = __bfloat162float(h2.y);
  __nv_bfloat162 l2 = __floats2bfloat162_rn(x - hx, y - hy);
  *hp = *reinterpret_cast<uint32_t*>(&h2);
  *lp = *reinterpret_cast<uint32_t*>(&l2);
}

__device__ __forceinline__ uint32_t s2u(const void* p) {
  return (uint32_t)__cvta_generic_to_shared(p);
}

// LN over rows of src, split-packed into ahp/alp.
__device__ __forceinline__ void ln_split(const float (*src)[F],
    uint32_t (*ahp)[APAD], uint32_t (*alp)[APAD], int tid)
{
  const int w = tid >> 5, l = tid & 31;
  for (int n = w; n < N; n += 16) {
    float2 p0 = *(const float2*)&src[n][2 * l];
    float2 p1 = *(const float2*)&src[n][64 + 2 * l];
    float sm = p0.x + p0.y + p1.x + p1.y;
#pragma unroll
    for (int o = 16; o; o >>= 1) sm += __shfl_xor_sync(0xffffffffu, sm, o);
    float mean = sm * (1.f / 128.f);
    float d0 = p0.x - mean, d1 = p0.y - mean, d2 = p1.x - mean, d3 = p1.y - mean;
    float ss = d0 * d0 + d1 * d1 + d2 * d2 + d3 * d3;
#pragma unroll
    for (int o = 16; o; o >>= 1) ss += __shfl_xor_sync(0xffffffffu, ss, o);
    float inv = rsqrtf(ss * (1.f / 128.f) + 1e-5f);
    d0 *= inv; d1 *= inv; d2 *= inv; d3 *= inv;
    pack2(d0, d1, &ahp[n][l],      &alp[n][l]);
    pack2(d2, d3, &ahp[n][l + 32], &alp[n][l + 32]);
  }
}

__global__ void __launch_bounds__(TPB, 1) gnn_kernel(
    const float* __restrict__ g_coords,
    const int*   __restrict__ g_species,
    const int*   __restrict__ g_mask,
    const float* __restrict__ g_embed,
    const float* __restrict__ g_We,
    const float* __restrict__ g_bf,
    float* __restrict__ g_out)
{
  extern __shared__ unsigned char smem_raw[];
  Smem& s = *reinterpret_cast<Smem*>(smem_raw);
  const int b = blockIdx.x;
  const int tid = threadIdx.x;

  if (tid < N) {
    s.mrow[tid] = (g_mask[b * N + tid] != 0) ? 1.f : 0.f;
    s.coords[tid][0] = g_coords[(b * N + tid) * 3 + 0];
    s.coords[tid][1] = g_coords[(b * N + tid) * 3 + 1];
    s.coords[tid][2] = g_coords[(b * N + tid) * 3 + 2];
  }
  for (int i = tid; i < N * F; i += TPB) {
    int n = i >> 7, f = i & (F - 1);
    int sp = g_species[b * N + n] - 1;
    float hv = g_embed[sp * F + f];
    s.h[n][f] = (g_mask[b * N + n] != 0) ? hv : 0.f;
  }
  __syncthreads();

  const int warp = tid >> 5, lane = tid & 31;
  const int mb = (warp & 3) << 4;
  const int nb = (warp >> 2) << 5;
  const int lm = lane >> 2, tig = lane & 3;
  const int rA = mb + lm, rB = mb + lm + 8;
  const int hh   = warp >> 3;
  const int mblk = (warp >> 2) & 1;
  const int tb   = (warp >> 2) << 2;      // ntile base (nb / 8)

  // ldmatrix per-thread geometry (A operands + attention, as validated)
  const int g8 = lane >> 3, r8 = lane & 7;
  const int hl8 = g8 >> 1, bs8 = g8 & 1;
  const uint32_t aBaseH = s2u(&s.ahp[mb + (g8 & 1) * 8 + r8][(g8 >> 1) * 4]);
  const uint32_t aBaseL = s2u(&s.alp[mb + (g8 & 1) * 8 + r8][(g8 >> 1) * 4]);
  const uint32_t kBase = s2u(hl8 ? s.u1l : s.u1h) + (uint32_t)(r8 * APAD + bs8 * 4) * 4;
  const uint32_t atBaseH = s2u(s.u1h)
      + (uint32_t)((hh * 64 + mb + (g8 & 1) * 8 + r8) * TPAD + (g8 >> 1) * 4) * 4;
  const uint32_t atBaseL = s2u(s.u1l)
      + (uint32_t)((hh * 64 + mb + (g8 & 1) * 8 + r8) * TPAD + (g8 >> 1) * 4) * 4;
  const uint32_t vBase = s2u(hl8 ? (uint32_t*)s.vtl : (uint32_t*)s.vth)
      + (uint32_t)(r8 * TPAD + bs8 * 4) * 4;

  float aq[4][4], ak[4][4], av[4][4];

  for (int l = 0; l < 3; ++l) {
    if (tid < F) s.bf_l[tid] = g_bf[l * F + tid];
    if (tid >= 128 && tid < 128 + 14)
      ((float*)s.We_l)[tid - 128] = g_We[l * 14 + (tid - 128)];

    const uint4* __restrict__ wq = g_wfrag + (size_t)(l * 5 + 0) * 4096;
    const uint4* __restrict__ wk = g_wfrag + (size_t)(l * 5 + 1) * 4096;
    const uint4* __restrict__ wv = g_wfrag + (size_t)(l * 5 + 2) * 4096;
    const uint4* __restrict__ wo = g_wfrag + (size_t)(l * 5 + 3) * 4096;
    const uint4* __restrict__ wf = g_wfrag + (size_t)(l * 5 + 4) * 4096;

    // ---- hn = LN(h) -> ahp/alp ----
    ln_split(s.h, s.ahp, s.alp, tid);
    __syncthreads();                                           // (1)

    // ---- fused q,k,v GEMM (B fragments direct from L2) ----
#pragma unroll
    for (int t = 0; t < 4; ++t)
#pragma unroll
      for (int i = 0; i < 4; ++i) { aq[t][i] = 0.f; ak[t][i] = 0.f; av[t][i] = 0.f; }
#pragma unroll
    for (int kst = 0; kst < 8; ++kst) {
      uint32_t ah0, ah1, ah2, ah3, al0, al1, al2, al3;
      ldsm4(ah0, ah1, ah2, ah3, aBaseH + kst * 32);
      ldsm4(al0, al1, al2, al3, aBaseL + kst * 32);
      const int fo = kst * 512 + tb * 32 + lane;
      {
        uint4 f0 = wq[fo], f1 = wq[fo + 32], f2 = wq[fo + 64], f3 = wq[fo + 96];
        mma3(aq[0], ah0, ah1, ah2, ah3, al0, al1, al2, al3, f0);
        mma3(aq[1], ah0, ah1, ah2, ah3, al0, al1, al2, al3, f1);
        mma3(aq[2], ah0, ah1, ah2, ah3, al0, al1, al2, al3, f2);
        mma3(aq[3], ah0, ah1, ah2, ah3, al0, al1, al2, al3, f3);
      }
      {
        uint4 f0 = wk[fo], f1 = wk[fo + 32], f2 = wk[fo + 64], f3 = wk[fo + 96];
        mma3(ak[0], ah0, ah1, ah2, ah3, al0, al1, al2, al3, f0);
        mma3(ak[1], ah0, ah1, ah2, ah3, al0, al1, al2, al3, f1);
        mma3(ak[2], ah0, ah1, ah2, ah3, al0, al1, al2, al3, f2);
        mma3(ak[3], ah0, ah1, ah2, ah3, al0, al1, al2, al3, f3);
      }
      {
        uint4 f0 = wv[fo], f1 = wv[fo + 32], f2 = wv[fo + 64], f3 = wv[fo + 96];
        mma3(av[0], ah0, ah1, ah2, ah3, al0, al1, al2, al3, f0);
        mma3(av[1], ah0, ah1, ah2, ah3, al0, al1, al2, al3, f1);
        mma3(av[2], ah0, ah1, ah2, ah3, al0, al1, al2, al3, f2);
        mma3(av[3], ah0, ah1, ah2, ah3, al0, al1, al2, al3, f3);
      }
    }
    __syncthreads();                                           // (2) A reads done

    // q -> ahp/alp
#pragma unroll
    for (int t = 0; t < 4; ++t) {
      int kp = (nb + t * 8 + 2 * tig) >> 1;
      pack2(aq[t][0], aq[t][1], &s.ahp[rA][kp], &s.alp[rA][kp]);
      pack2(aq[t][2], aq[t][3], &s.ahp[rB][kp], &s.alp[rB][kp]);
    }
    // k -> u1 [m][APAD]
#pragma unroll
    for (int t = 0; t < 4; ++t) {
      int kp = (nb + t * 8 + 2 * tig) >> 1;
      pack2(ak[t][0], ak[t][1], &s.u1h[rA * APAD + kp], &s.u1l[rA * APAD + kp]);
      pack2(ak[t][2], ak[t][3], &s.u1h[rB * APAD + kp], &s.u1l[rB * APAD + kp]);
    }
    // v -> transposed [dh][mpair]
#pragma unroll
    for (int t = 0; t < 4; ++t) {
      int c = nb + t * 8 + 2 * tig;
      float p0 = __shfl_xor_sync(0xffffffffu, av[t][0], 4);
      float p1 = __shfl_xor_sync(0xffffffffu, av[t][1], 4);
      float p2 = __shfl_xor_sync(0xffffffffu, av[t][2], 4);
      float p3 = __shfl_xor_sync(0xffffffffu, av[t][3], 4);
      if ((lm & 1) == 0) {
        int mp = (mb + lm) >> 1;
        pack2(av[t][0], p0, &s.vth[c][mp],     &s.vtl[c][mp]);
        pack2(av[t][1], p1, &s.vth[c + 1][mp], &s.vtl[c + 1][mp]);
      } else {
        int mp = (mb + lm + 7) >> 1;
        pack2(p2, av[t][2], &s.vth[c][mp],     &s.vtl[c][mp]);
        pack2(p3, av[t][3], &s.vth[c + 1][mp], &s.vtl[c + 1][mp]);
      }
    }
    __syncthreads();                                           // (3)

    // ---- logits = q @ k^T (head hh, m-half mblk) ----
#pragma unroll
    for (int t = 0; t < 4; ++t)
#pragma unroll
      for (int i = 0; i < 4; ++i) aq[t][i] = 0.f;
#pragma unroll
    for (int ks = 0; ks < 4; ++ks) {
      const uint32_t aoff = (uint32_t)(hh * 32 + ks * 8) * 4;
      uint32_t ah0, ah1, ah2, ah3, al0, al1, al2, al3;
      ldsm4(ah0, ah1, ah2, ah3, aBaseH + aoff);
      ldsm4(al0, al1, al2, al3, aBaseL + aoff);
#pragma unroll
      for (int t = 0; t < 4; ++t) {
        uint32_t bh0, bh1, bl0, bl1;
        ldsm4(bh0, bh1, bl0, bl1,
              kBase + (uint32_t)((mblk * 32 + t * 8) * APAD + hh * 32 + ks * 8) * 4);
        mma_bf16(aq[t], ah0, ah1, ah2, ah3, bh0, bh1);
        mma_bf16(aq[t], ah0, ah1, ah2, ah3, bl0, bl1);
        mma_bf16(aq[t], al0, al1, al2, al3, bh0, bh1);
      }
    }

    // ---- epilogue: scale + edge bias + mask + 1-barrier softmax -> attn ----
    {
      const float w0 = s.We_l[0][hh], w1 = s.We_l[1][hh], w2 = s.We_l[2][hh],
                  w3 = s.We_l[3][hh], w4 = s.We_l[4][hh], w5 = s.We_l[5][hh],
                  w6 = s.We_l[6][hh];
      const bool okA = s.mrow[rA] > 0.f, okB = s.mrow[rB] > 0.f;
      const float a0 = s.coords[rA][0], a1 = s.coords[rA][1], a2 = s.coords[rA][2];
      const float b0 = s.coords[rB][0], b1 = s.coords[rB][1], b2 = s.coords[rB][2];
      float xA[8], xB[8];
#pragma unroll
      for (int t = 0; t < 4; ++t) {
#pragma unroll
        for (int j = 0; j < 2; ++j) {
          const int m = mblk * 32 + t * 8 + 2 * tig + j;
          const float m0 = s.coords[m][0], m1 = s.coords[m][1], m2 = s.coords[m][2];
          const bool okm = s.mrow[m] > 0.f;
          {
            float dx = a0 - m0, dy = a1 - m1, dz = a2 - m2;
            float d = sqrtf(dx * dx + dy * dy + dz * dz + 1e-12f);
            float g1 = 1.f / (1.f + __expf(2.f - d));
            float g2 = 1.f / (1.f + __expf(4.f - d));
            float g3 = 1.f / (1.f + __expf(6.f - d));
            float bias = dx * w0 + dy * w1 + dz * w2 + d * w3
                       + g1 * w4 + g2 * w5 + g3 * w6;
            xA[2 * t + j] = (okA && okm) ? aq[t][j] * INV_SQRT_DH + bias : NEGV;
          }
          {
            float dx = b0 - m0, dy = b1 - m1, dz = b2 - m2;
            float d = sqrtf(dx * dx + dy * dy + dz * dz + 1e-12f);
            float g1 = 1.f / (1.f + __expf(2.f - d));
            float g2 = 1.f / (1.f + __expf(4.f - d));
            float g3 = 1.f / (1.f + __expf(6.f - d));
            float bias = dx * w0 + dy * w1 + dz * w2 + d * w3
                       + g1 * w4 + g2 * w5 + g3 * w6;
            xB[2 * t + j] = (okB && okm) ? aq[t][2 + j] * INV_SQRT_DH + bias : NEGV;
          }
        }
      }
      float mxA = xA[0], mxB = xB[0];
#pragma unroll
      for (int i = 1; i < 8; ++i) { mxA = fmaxf(mxA, xA[i]); mxB = fmaxf(mxB, xB[i]); }
      mxA = fmaxf(mxA, __shfl_xor_sync(0xffffffffu, mxA, 1));
      mxA = fmaxf(mxA, __shfl_xor_sync(0xffffffffu, mxA, 2));
      mxB = fmaxf(mxB, __shfl_xor_sync(0xffffffffu, mxB, 1));
      mxB = fmaxf(mxB, __shfl_xor_sync(0xffffffffu, mxB, 2));
      float smA = 0.f, smB = 0.f;
#pragma unroll
      for (int i = 0; i < 8; ++i) {
        xA[i] = __expf(xA[i] - mxA); smA += xA[i];
        xB[i] = __expf(xB[i] - mxB); smB += xB[i];
      }
      smA += __shfl_xor_sync(0xffffffffu, smA, 1);
      smA += __shfl_xor_sync(0xffffffffu, smA, 2);
      smB += __shfl_xor_sync(0xffffffffu, smB, 1);
      smB += __shfl_xor_sync(0xffffffffu, smB, 2);
      if (tig == 0) {
        s.rmx[hh][rA][mblk] = mxA;  s.rsm[hh][rA][mblk] = smA;
        s.rmx[hh][rB][mblk] = mxB;  s.rsm[hh][rB][mblk] = smB;
      }
      __syncthreads();                                         // (4)
      float mA0 = s.rmx[hh][rA][0], mA1 = s.rmx[hh][rA][1];
      float gA = fmaxf(mA0, mA1);
      float dA = s.rsm[hh][rA][0] * __expf(mA0 - gA)
               + s.rsm[hh][rA][1] * __expf(mA1 - gA);
      float mB0 = s.rmx[hh][rB][0], mB1 = s.rmx[hh][rB][1];
      float gB = fmaxf(mB0, mB1);
      float dB = s.rsm[hh][rB][0] * __expf(mB0 - gB)
               + s.rsm[hh][rB][1] * __expf(mB1 - gB);
      const float scA = __expf(mxA - gA) / dA;
      const float scB = __expf(mxB - gB) / dB;
      const int baseA = (hh * 64 + rA) * TPAD;
      const int baseB = (hh * 64 + rB) * TPAD;
#pragma unroll
      for (int t = 0; t < 4; ++t) {
        int mp = mblk * 16 + t * 4 + tig;
        pack2(xA[2 * t] * scA, xA[2 * t + 1] * scA,
              &s.u1h[baseA + mp], &s.u1l[baseA + mp]);
        pack2(xB[2 * t] * scB, xB[2 * t + 1] * scB,
              &s.u1h[baseB + mp], &s.u1l[baseB + mp]);
      }
    }
    __syncthreads();                                           // (5)

    // ---- msg = attn @ v (head hh, dh-half mblk) -> pack into ahp/alp ----
#pragma unroll
    for (int t = 0; t < 4; ++t)
#pragma unroll
      for (int i = 0; i < 4; ++i) aq[t][i] = 0.f;
    {
      const int dhb = mblk * 32;
#pragma unroll
      for (int ks = 0; ks < 4; ++ks) {
        const uint32_t aoff = (uint32_t)(ks * 8) * 4;
        uint32_t ah0, ah1, ah2, ah3, al0, al1, al2, al3;
        ldsm4(ah0, ah1, ah2, ah3, atBaseH + aoff);
        ldsm4(al0, al1, al2, al3, atBaseL + aoff);
#pragma unroll
        for (int t = 0; t < 4; ++t) {
          uint32_t bh0, bh1, bl0, bl1;
          ldsm4(bh0, bh1, bl0, bl1,
                vBase + (uint32_t)((hh * 64 + dhb + t * 8) * TPAD + ks * 8) * 4);
          mma_bf16(aq[t], ah0, ah1, ah2, ah3, bh0, bh1);
          mma_bf16(aq[t], ah0, ah1, ah2, ah3, bl0, bl1);
          mma_bf16(aq[t], al0, al1, al2, al3, bh0, bh1);
        }
      }
#pragma unroll
      for (int t = 0; t < 4; ++t) {
        int kp = hh * 32 + (dhb >> 1) + t * 4 + tig;
        pack2(aq[t][0], aq[t][1], &s.ahp[rA][kp], &s.alp[rA][kp]);
        pack2(aq[t][2], aq[t][3], &s.ahp[rB][kp], &s.alp[rB][kp]);
      }
    }
    __syncthreads();                                           // (6)

    // ---- h += msg @ Wo ----
#pragma unroll
    for (int t = 0; t < 4; ++t)
#pragma unroll
      for (int i = 0; i < 4; ++i) ak[t][i] = 0.f;
#pragma unroll
    for (int kst = 0; kst < 8; ++kst) {
      uint32_t ah0, ah1, ah2, ah3, al0, al1, al2, al3;
      ldsm4(ah0, ah1, ah2, ah3, aBaseH + kst * 32);
      ldsm4(al0, al1, al2, al3, aBaseL + kst * 32);
      const int fo = kst * 512 + tb * 32 + lane;
      uint4 f0 = wo[fo], f1 = wo[fo + 32], f2 = wo[fo + 64], f3 = wo[fo + 96];
      mma3(ak[0], ah0, ah1, ah2, ah3, al0, al1, al2, al3, f0);
      mma3(ak[1], ah0, ah1, ah2, ah3, al0, al1, al2, al3, f1);
      mma3(ak[2], ah0, ah1, ah2, ah3, al0, al1, al2, al3, f2);
      mma3(ak[3], ah0, ah1, ah2, ah3, al0, al1, al2, al3, f3);
    }
#pragma unroll
    for (int t = 0; t < 4; ++t) {
      int c = nb + t * 8 + 2 * tig;
      float2 h0 = *(float2*)&s.h[rA][c];
      h0.x += ak[t][0]; h0.y += ak[t][1];
      *(float2*)&s.h[rA][c] = h0;
      float2 h1 = *(float2*)&s.h[rB][c];
      h1.x += ak[t][2]; h1.y += ak[t][3];
      *(float2*)&s.h[rB][c] = h1;
    }
    __syncthreads();                                           // (7)

    // ---- h = (h + tanh(LN(h) @ Wf + bf)) * mask ----
    ln_split(s.h, s.ahp, s.alp, tid);
    __syncthreads();                                           // (8)
#pragma unroll
    for (int t = 0; t < 4; ++t)
#pragma unroll
      for (int i = 0; i < 4; ++i) ak[t][i] = 0.f;
#pragma unroll
    for (int kst = 0; kst < 8; ++kst) {
      uint32_t ah0, ah1, ah2, ah3, al0, al1, al2, al3;
      ldsm4(ah0, ah1, ah2, ah3, aBaseH + kst * 32);
      ldsm4(al0, al1, al2, al3, aBaseL + kst * 32);
      const int fo = kst * 512 + tb * 32 + lane;
      uint4 f0 = wf[fo], f1 = wf[fo + 32], f2 = wf[fo + 64], f3 = wf[fo + 96];
      mma3(ak[0], ah0, ah1, ah2, ah3, al0, al1, al2, al3, f0);
      mma3(ak[1], ah0, ah1, ah2, ah3, al0, al1, al2, al3, f1);
      mma3(ak[2], ah0, ah1, ah2, ah3, al0, al1, al2, al3, f2);
      mma3(ak[3], ah0, ah1, ah2, ah3, al0, al1, al2, al3, f3);
    }
    {
      float mr0 = s.mrow[rA];
      float mr1 = s.mrow[rB];
#pragma unroll
      for (int t = 0; t < 4; ++t) {
        int c = nb + t * 8 + 2 * tig;
        float2 h0 = *(float2*)&s.h[rA][c];
        h0.x = (h0.x + tanhf(ak[t][0] + s.bf_l[c]))     * mr0;
        h0.y = (h0.y + tanhf(ak[t][1] + s.bf_l[c + 1])) * mr0;
        *(float2*)&s.h[rA][c] = h0;
        float2 h1 = *(float2*)&s.h[rB][c];
        h1.x = (h1.x + tanhf(ak[t][2] + s.bf_l[c]))     * mr1;
        h1.y = (h1.y + tanhf(ak[t][3] + s.bf_l[c + 1])) * mr1;
        *(float2*)&s.h[rB][c] = h1;
      }
    }
    __syncthreads();                                           // (9)
  }

  // ---- final layernorm -> global output ----
  {
    const int w = tid >> 5, ln = tid & 31;
    for (int n = w; n < N; n += 16) {
      float x0 = s.h[n][ln], x1 = s.h[n][ln + 32];
      float x2 = s.h[n][ln + 64], x3 = s.h[n][ln + 96];
      float sm = x0 + x1 + x2 + x3;
#pragma unroll
      for (int o = 16; o; o >>= 1) sm += __shfl_xor_sync(0xffffffffu, sm, o);
      float mean = sm * (1.f / 128.f);
      float d0 = x0 - mean, d1 = x1 - mean, d2 = x2 - mean, d3 = x3 - mean;
      float ss = d0 * d0 + d1 * d1 + d2 * d2 + d3 * d3;
#pragma unroll
      for (int o = 16; o; o >>= 1) ss += __shfl_xor_sync(0xffffffffu, ss, o);
      float inv = rsqrtf(ss * (1.f / 128.f) + 1e-5f);
      float* orow = g_out + (size_t)(b * N + n) * F;
      orow[ln]      = d0 * inv;
      orow[ln + 32] = d1 * inv;
      orow[ln + 64] = d2 * inv;
      orow[ln + 96] = d3 * inv;
    }
  }
}

// Split + fragment-order all 15 weight matrices.
__global__ void prep_weights(const float* __restrict__ Wq,
                             const float* __restrict__ Wk,
                             const float* __restrict__ Wv,
                             const float* __restrict__ Wo,
                             const float* __restrict__ Wf)
{
  int idx = blockIdx.x * blockDim.x + threadIdx.x;
  if (idx >= 15 * 8 * 16 * 32) return;
  int mat   = idx >> 12;
  int kst   = (idx >> 9) & 7;
  int ntile = (idx >> 5) & 15;
  int lane  = idx & 31;
  int l = mat / 5, which = mat % 5;
  const float* W =
      (which == 0 ? Wq : which == 1 ? Wk : which == 2 ? Wv : which == 3 ? Wo : Wf)
      + l * F * F;
  int n   = ntile * 8 + (lane >> 2);
  int kpA = kst * 8 + (lane & 3);
  int kpB = kpA + 4;

  float a0 = W[(2 * kpA)     * F + n];
  float a1 = W[(2 * kpA + 1) * F + n];
  float c0 = W[(2 * kpB)     * F + n];
  float c1 = W[(2 * kpB + 1) * F + n];

  __nv_bfloat162 ha = __floats2bfloat162_rn(a0, a1);
  __nv_bfloat162 la = __floats2bfloat162_rn(a0 - __bfloat162float(ha.x),
                                            a1 - __bfloat162float(ha.y));
  __nv_bfloat162 hc = __floats2bfloat162_rn(c0, c1);
  __nv_bfloat162 lc = __floats2bfloat162_rn(c0 - __bfloat162float(hc.x),
                                            c1 - __bfloat162float(hc.y));
  uint4 w;
  w.x = *reinterpret_cast<uint32_t*>(&ha);
  w.y = *reinterpret_cast<uint32_t*>(&hc);
  w.z = *reinterpret_cast<uint32_t*>(&la);
  w.w = *reinterpret_cast<uint32_t*>(&lc);
  g_wfrag[idx] = w;
}

}  // namespace

extern "C" void kernel_launch(void* const* d_in, const int* in_sizes, int n_in,
                              void* d_out, int out_size)
{
  (void)n_in; (void)out_size;
  const float* coords  = (const float*)d_in[0];
  const int*   species = (const int*)d_in[1];
  const int*   mask    = (const int*)d_in[2];
  const float* embed   = (const float*)d_in[3];
  const float* Wq      = (const float*)d_in[4];
  const float* Wk      = (const float*)d_in[5];
  const float* Wv      = (const float*)d_in[6];
  const float* Wo      = (const float*)d_in[7];
  const float* We      = (const float*)d_in[8];
  const float* Wf      = (const float*)d_in[9];
  const float* bf      = (const float*)d_in[10];

  const int B = in_sizes[0] / (N * 3);   // 2048

  prep_weights<<<(15 * 8 * 16 * 32 + 255) / 256, 256>>>(Wq, Wk, Wv, Wo, Wf);

  cudaFuncSetAttribute(gnn_kernel, cudaFuncAttributeMaxDynamicSharedMemorySize,
                       (int)sizeof(Smem));
  gnn_kernel<<<B, TPB, sizeof(Smem)>>>(coords, species, mask, embed,
                                       We, bf, (float*)d_out);
}

// round 11
// speedup vs baseline: 3.1993x; 1.1381x over previous
#include <cuda_runtime.h>
#include <cuda_bf16.h>
#include <stdint.h>
#include <math.h>

#define TPB 512

namespace {

constexpr int N = 64;
constexpr int F = 128;
constexpr int APAD = 68;   // [n][kpair] packed stride (A ops, q, k)
constexpr int TPAD = 36;   // [dh][mpair] & [hh][n][mpair] stride
constexpr float NEGV = -1e9f;
constexpr float INV_SQRT_DH = 0.125f;

// Fragment-ordered split weights: [15 mats][kstep 8][ntile 16][lane 32] x uint4
__device__ uint4 g_wfrag[15 * 8 * 16 * 32];

struct __align__(16) Smem {
  float h[N][F];
  uint32_t ahp[N][APAD], alp[N][APAD];   // LN(h) -> q -> msg -> LN(h)
  uint32_t u1h[4608], u1l[4608];         // k [m][APAD]  then  attn [hh*64+n][TPAD]
  uint32_t vth[F][TPAD], vtl[F][TPAD];   // v transposed [dh][mpair]
  float bias12[2][2][64][64];            // cached edge bias for layers 1,2 (mask folded)
  float rmx[2][64][2], rsm[2][64][2];
  float coords[N][3];
  float mrow[N];
  float bf_l[F];
  float Wel[3][7][2];
};

__device__ __forceinline__ void mma_bf16(float* d,
    uint32_t a0, uint32_t a1, uint32_t a2, uint32_t a3,
    uint32_t b0, uint32_t b1)
{
  asm volatile(
    "mma.sync.aligned.m16n8k16.row.col.f32.bf16.bf16.f32 "
    "{%0,%1,%2,%3}, {%4,%5,%6,%7}, {%8,%9}, {%0,%1,%2,%3};\n"
    : "+f"(d[0]), "+f"(d[1]), "+f"(d[2]), "+f"(d[3])
    : "r"(a0), "r"(a1), "r"(a2), "r"(a3), "r"(b0), "r"(b1));
}

__device__ __forceinline__ void mma3(float* d,
    uint32_t ah0, uint32_t ah1, uint32_t ah2, uint32_t ah3,
    uint32_t al0, uint32_t al1, uint32_t al2, uint32_t al3,
    uint4 w)
{
  mma_bf16(d, ah0, ah1, ah2, ah3, w.x, w.y);
  mma_bf16(d, ah0, ah1, ah2, ah3, w.z, w.w);
  mma_bf16(d, al0, al1, al2, al3, w.x, w.y);
}

__device__ __forceinline__ void ldsm4(uint32_t& r0, uint32_t& r1,
                                      uint32_t& r2, uint32_t& r3, uint32_t a)
{
  asm volatile("ldmatrix.sync.aligned.m8n8.x4.shared.b16 {%0,%1,%2,%3}, [%4];"
               : "=r"(r0), "=r"(r1), "=r"(r2), "=r"(r3) : "r"(a));
}

__device__ __forceinline__ void pack2(float x, float y,
                                      uint32_t* hp, uint32_t* lp)
{
  __nv_bfloat162 h2 = __floats2bfloat162_rn(x, y);
  float hx = __bfloat162float(h2.x), hy = __bfloat162float(h2.y);
  __nv_bfloat162 l2 = __floats2bfloat162_rn(x - hx, y - hy);
  *hp = *reinterpret_cast<uint32_t*>(&h2);
  *lp = *reinterpret_cast<uint32_t*>(&l2);
}

__device__ __forceinline__ uint32_t s2u(const void* p) {
  return (uint32_t)__cvta_generic_to_shared(p);
}

__device__ __forceinline__ void ln_split(const float (*src)[F],
    uint32_t (*ahp)[APAD], uint32_t (*alp)[APAD], int tid)
{
  const int w = tid >> 5, l = tid & 31;
  for (int n = w; n < N; n += 16) {
    float2 p0 = *(const float2*)&src[n][2 * l];
    float2 p1 = *(const float2*)&src[n][64 + 2 * l];
    float sm = p0.x + p0.y + p1.x + p1.y;
#pragma unroll
    for (int o = 16; o; o >>= 1) sm += __shfl_xor_sync(0xffffffffu, sm, o);
    float mean = sm * (1.f / 128.f);
    float d0 = p0.x - mean, d1 = p0.y - mean, d2 = p1.x - mean, d3 = p1.y - mean;
    float ss = d0 * d0 + d1 * d1 + d2 * d2 + d3 * d3;
#pragma unroll
    for (int o = 16; o; o >>= 1) ss += __shfl_xor_sync(0xffffffffu, ss, o);
    float inv = rsqrtf(ss * (1.f / 128.f) + 1e-5f);
    d0 *= inv; d1 *= inv; d2 *= inv; d3 *= inv;
    pack2(d0, d1, &ahp[n][l],      &alp[n][l]);
    pack2(d2, d3, &ahp[n][l + 32], &alp[n][l + 32]);
  }
}

__global__ void __launch_bounds__(TPB, 1) gnn_kernel(
    const float* __restrict__ g_coords,
    const int*   __restrict__ g_species,
    const int*   __restrict__ g_mask,
    const float* __restrict__ g_embed,
    const float* __restrict__ g_We,
    const float* __restrict__ g_bf,
    float* __restrict__ g_out)
{
  extern __shared__ unsigned char smem_raw[];
  Smem& s = *reinterpret_cast<Smem*>(smem_raw);
  const int b = blockIdx.x;
  const int tid = threadIdx.x;

  if (tid < N) {
    s.mrow[tid] = (g_mask[b * N + tid] != 0) ? 1.f : 0.f;
    s.coords[tid][0] = g_coords[(b * N + tid) * 3 + 0];
    s.coords[tid][1] = g_coords[(b * N + tid) * 3 + 1];
    s.coords[tid][2] = g_coords[(b * N + tid) * 3 + 2];
  }
  if (tid >= 64 && tid < 64 + 42)
    ((float*)s.Wel)[tid - 64] = g_We[tid - 64];
  for (int i = tid; i < N * F; i += TPB) {
    int n = i >> 7, f = i & (F - 1);
    int sp = g_species[b * N + n] - 1;
    float hv = g_embed[sp * F + f];
    s.h[n][f] = (g_mask[b * N + n] != 0) ? hv : 0.f;
  }
  __syncthreads();

  const int warp = tid >> 5, lane = tid & 31;
  // Wo/Wf + attention mapping (M=16 x N=32)
  const int mb = (warp & 3) << 4;
  const int nb = (warp >> 2) << 5;
  const int lm = lane >> 2, tig = lane & 3;
  const int rA = mb + lm, rB = mb + lm + 8;
  const int hh   = warp >> 3;
  const int mblk = (warp >> 2) & 1;
  const int tb   = (warp >> 2) << 2;
  // qkv mapping (M=32 x N=16): halved weight-fragment redundancy
  const int wqm = (warp & 1) << 5;       // 0, 32
  const int wqn = (warp >> 1) << 4;      // 0..112
  const int ntb = (warp >> 1) << 1;      // n8-tile base 0..14

  const int g8 = lane >> 3, r8 = lane & 7;
  const int hl8 = g8 >> 1, bs8 = g8 & 1;
  const uint32_t aBaseH = s2u(&s.ahp[mb + (g8 & 1) * 8 + r8][(g8 >> 1) * 4]);
  const uint32_t aBaseL = s2u(&s.alp[mb + (g8 & 1) * 8 + r8][(g8 >> 1) * 4]);
  const uint32_t aqBaseH = s2u(&s.ahp[wqm + (g8 & 1) * 8 + r8][(g8 >> 1) * 4]);
  const uint32_t aqBaseL = s2u(&s.alp[wqm + (g8 & 1) * 8 + r8][(g8 >> 1) * 4]);
  const uint32_t RT1 = 16 * APAD * 4;    // +16 rows
  const uint32_t kBase = s2u(hl8 ? s.u1l : s.u1h) + (uint32_t)(r8 * APAD + bs8 * 4) * 4;
  const uint32_t atBaseH = s2u(s.u1h)
      + (uint32_t)((hh * 64 + mb + (g8 & 1) * 8 + r8) * TPAD + (g8 >> 1) * 4) * 4;
  const uint32_t atBaseL = s2u(s.u1l)
      + (uint32_t)((hh * 64 + mb + (g8 & 1) * 8 + r8) * TPAD + (g8 >> 1) * 4) * 4;
  const uint32_t vBase = s2u(hl8 ? (uint32_t*)s.vtl : (uint32_t*)s.vth)
      + (uint32_t)(r8 * TPAD + bs8 * 4) * 4;

  float aq[4][4], ak[4][4], av[4][4];

  for (int l = 0; l < 3; ++l) {
    if (tid < F) s.bf_l[tid] = g_bf[l * F + tid];

    const uint4* __restrict__ wq = g_wfrag + (size_t)(l * 5 + 0) * 4096;
    const uint4* __restrict__ wk = g_wfrag + (size_t)(l * 5 + 1) * 4096;
    const uint4* __restrict__ wv = g_wfrag + (size_t)(l * 5 + 2) * 4096;
    const uint4* __restrict__ wo = g_wfrag + (size_t)(l * 5 + 3) * 4096;
    const uint4* __restrict__ wf = g_wfrag + (size_t)(l * 5 + 4) * 4096;

    // ---- hn = LN(h) -> ahp/alp ----
    ln_split(s.h, s.ahp, s.alp, tid);
    __syncthreads();                                           // (1)

    // ---- fused q,k,v GEMM, M=32 x N=16 per warp ----
#pragma unroll
    for (int u = 0; u < 4; ++u)
#pragma unroll
      for (int i = 0; i < 4; ++i) { aq[u][i] = 0.f; ak[u][i] = 0.f; av[u][i] = 0.f; }
#pragma unroll
    for (int kst = 0; kst < 8; ++kst) {
      uint32_t x0h0, x0h1, x0h2, x0h3, x0l0, x0l1, x0l2, x0l3;
      uint32_t x1h0, x1h1, x1h2, x1h3, x1l0, x1l1, x1l2, x1l3;
      ldsm4(x0h0, x0h1, x0h2, x0h3, aqBaseH + kst * 32);
      ldsm4(x0l0, x0l1, x0l2, x0l3, aqBaseL + kst * 32);
      ldsm4(x1h0, x1h1, x1h2, x1h3, aqBaseH + RT1 + kst * 32);
      ldsm4(x1l0, x1l1, x1l2, x1l3, aqBaseL + RT1 + kst * 32);
      const int fo = kst * 512 + ntb * 32 + lane;
      {
        uint4 f0 = wq[fo], f1 = wq[fo + 32];
        mma3(aq[0], x0h0, x0h1, x0h2, x0h3, x0l0, x0l1, x0l2, x0l3, f0);
        mma3(aq[1], x0h0, x0h1, x0h2, x0h3, x0l0, x0l1, x0l2, x0l3, f1);
        mma3(aq[2], x1h0, x1h1, x1h2, x1h3, x1l0, x1l1, x1l2, x1l3, f0);
        mma3(aq[3], x1h0, x1h1, x1h2, x1h3, x1l0, x1l1, x1l2, x1l3, f1);
      }
      {
        uint4 f0 = wk[fo], f1 = wk[fo + 32];
        mma3(ak[0], x0h0, x0h1, x0h2, x0h3, x0l0, x0l1, x0l2, x0l3, f0);
        mma3(ak[1], x0h0, x0h1, x0h2, x0h3, x0l0, x0l1, x0l2, x0l3, f1);
        mma3(ak[2], x1h0, x1h1, x1h2, x1h3, x1l0, x1l1, x1l2, x1l3, f0);
        mma3(ak[3], x1h0, x1h1, x1h2, x1h3, x1l0, x1l1, x1l2, x1l3, f1);
      }
      {
        uint4 f0 = wv[fo], f1 = wv[fo + 32];
        mma3(av[0], x0h0, x0h1, x0h2, x0h3, x0l0, x0l1, x0l2, x0l3, f0);
        mma3(av[1], x0h0, x0h1, x0h2, x0h3, x0l0, x0l1, x0l2, x0l3, f1);
        mma3(av[2], x1h0, x1h1, x1h2, x1h3, x1l0, x1l1, x1l2, x1l3, f0);
        mma3(av[3], x1h0, x1h1, x1h2, x1h3, x1l0, x1l1, x1l2, x1l3, f1);
      }
    }
    __syncthreads();                                           // (2) A reads done

    // q/k/v packs (qkv mapping)
#pragma unroll
    for (int rt = 0; rt < 2; ++rt)
#pragma unroll
      for (int tq = 0; tq < 2; ++tq) {
        const int u = rt * 2 + tq;
        const int rowA = wqm + rt * 16 + lm, rowB = rowA + 8;
        const int kp = (wqn + tq * 8 + 2 * tig) >> 1;
        pack2(aq[u][0], aq[u][1], &s.ahp[rowA][kp], &s.alp[rowA][kp]);
        pack2(aq[u][2], aq[u][3], &s.ahp[rowB][kp], &s.alp[rowB][kp]);
        pack2(ak[u][0], ak[u][1], &s.u1h[rowA * APAD + kp], &s.u1l[rowA * APAD + kp]);
        pack2(ak[u][2], ak[u][3], &s.u1h[rowB * APAD + kp], &s.u1l[rowB * APAD + kp]);
        const int c = wqn + tq * 8 + 2 * tig;
        const int mbv = wqm + rt * 16;
        float p0 = __shfl_xor_sync(0xffffffffu, av[u][0], 4);
        float p1 = __shfl_xor_sync(0xffffffffu, av[u][1], 4);
        float p2 = __shfl_xor_sync(0xffffffffu, av[u][2], 4);
        float p3 = __shfl_xor_sync(0xffffffffu, av[u][3], 4);
        if ((lm & 1) == 0) {
          int mp = (mbv + lm) >> 1;
          pack2(av[u][0], p0, &s.vth[c][mp],     &s.vtl[c][mp]);
          pack2(av[u][1], p1, &s.vth[c + 1][mp], &s.vtl[c + 1][mp]);
        } else {
          int mp = (mbv + lm + 7) >> 1;
          pack2(p2, av[u][2], &s.vth[c][mp],     &s.vtl[c][mp]);
          pack2(p3, av[u][3], &s.vth[c + 1][mp], &s.vtl[c + 1][mp]);
        }
      }
    __syncthreads();                                           // (3)

    // ---- logits = q @ k^T (head hh, m-half mblk) ----
#pragma unroll
    for (int t = 0; t < 4; ++t)
#pragma unroll
      for (int i = 0; i < 4; ++i) aq[t][i] = 0.f;
#pragma unroll
    for (int ks = 0; ks < 4; ++ks) {
      const uint32_t aoff = (uint32_t)(hh * 32 + ks * 8) * 4;
      uint32_t ah0, ah1, ah2, ah3, al0, al1, al2, al3;
      ldsm4(ah0, ah1, ah2, ah3, aBaseH + aoff);
      ldsm4(al0, al1, al2, al3, aBaseL + aoff);
#pragma unroll
      for (int t = 0; t < 4; ++t) {
        uint32_t bh0, bh1, bl0, bl1;
        ldsm4(bh0, bh1, bl0, bl1,
              kBase + (uint32_t)((mblk * 32 + t * 8) * APAD + hh * 32 + ks * 8) * 4);
        mma_bf16(aq[t], ah0, ah1, ah2, ah3, bh0, bh1);
        mma_bf16(aq[t], ah0, ah1, ah2, ah3, bl0, bl1);
        mma_bf16(aq[t], al0, al1, al2, al3, bh0, bh1);
      }
    }

    // ---- epilogue: scale + bias + mask + 1-barrier softmax -> attn ----
    {
      float xA[8], xB[8];
      if (l == 0) {
        const float w0 = s.Wel[0][0][hh], w1 = s.Wel[0][1][hh], w2 = s.Wel[0][2][hh],
                    w3 = s.Wel[0][3][hh], w4 = s.Wel[0][4][hh], w5 = s.Wel[0][5][hh],
                    w6 = s.Wel[0][6][hh];
        const float u0 = s.Wel[1][0][hh], u1 = s.Wel[1][1][hh], u2 = s.Wel[1][2][hh],
                    u3 = s.Wel[1][3][hh], u4 = s.Wel[1][4][hh], u5 = s.Wel[1][5][hh],
                    u6 = s.Wel[1][6][hh];
        const float v0 = s.Wel[2][0][hh], v1 = s.Wel[2][1][hh], v2 = s.Wel[2][2][hh],
                    v3 = s.Wel[2][3][hh], v4 = s.Wel[2][4][hh], v5 = s.Wel[2][5][hh],
                    v6 = s.Wel[2][6][hh];
        const bool okA = s.mrow[rA] > 0.f, okB = s.mrow[rB] > 0.f;
        const float a0 = s.coords[rA][0], a1 = s.coords[rA][1], a2 = s.coords[rA][2];
        const float b0 = s.coords[rB][0], b1 = s.coords[rB][1], b2 = s.coords[rB][2];
#pragma unroll
        for (int t = 0; t < 4; ++t) {
          float biasA1[2], biasA2[2], biasB1[2], biasB2[2];
#pragma unroll
          for (int j = 0; j < 2; ++j) {
            const int m = mblk * 32 + t * 8 + 2 * tig + j;
            const float m0 = s.coords[m][0], m1 = s.coords[m][1], m2 = s.coords[m][2];
            const bool okm = s.mrow[m] > 0.f;
            {
              float dx = a0 - m0, dy = a1 - m1, dz = a2 - m2;
              float d = sqrtf(dx * dx + dy * dy + dz * dz + 1e-12f);
              float g1 = 1.f / (1.f + __expf(2.f - d));
              float g2 = 1.f / (1.f + __expf(4.f - d));
              float g3 = 1.f / (1.f + __expf(6.f - d));
              float bias = dx * w0 + dy * w1 + dz * w2 + d * w3
                         + g1 * w4 + g2 * w5 + g3 * w6;
              bool ok = okA && okm;
              xA[2 * t + j] = ok ? aq[t][j] * INV_SQRT_DH + bias : NEGV;
              biasA1[j] = ok ? dx * u0 + dy * u1 + dz * u2 + d * u3
                             + g1 * u4 + g2 * u5 + g3 * u6 : NEGV;
              biasA2[j] = ok ? dx * v0 + dy * v1 + dz * v2 + d * v3
                             + g1 * v4 + g2 * v5 + g3 * v6 : NEGV;
            }
            {
              float dx = b0 - m0, dy = b1 - m1, dz = b2 - m2;
              float d = sqrtf(dx * dx + dy * dy + dz * dz + 1e-12f);
              float g1 = 1.f / (1.f + __expf(2.f - d));
              float g2 = 1.f / (1.f + __expf(4.f - d));
              float g3 = 1.f / (1.f + __expf(6.f - d));
              float bias = dx * w0 + dy * w1 + dz * w2 + d * w3
                         + g1 * w4 + g2 * w5 + g3 * w6;
              bool ok = okB && okm;
              xB[2 * t + j] = ok ? aq[t][2 + j] * INV_SQRT_DH + bias : NEGV;
              biasB1[j] = ok ? dx * u0 + dy * u1 + dz * u2 + d * u3
                             + g1 * u4 + g2 * u5 + g3 * u6 : NEGV;
              biasB2[j] = ok ? dx * v0 + dy * v1 + dz * v2 + d * v3
                             + g1 * v4 + g2 * v5 + g3 * v6 : NEGV;
            }
          }
          const int m0i = mblk * 32 + t * 8 + 2 * tig;
          *(float2*)&s.bias12[0][hh][rA][m0i] = make_float2(biasA1[0], biasA1[1]);
          *(float2*)&s.bias12[1][hh][rA][m0i] = make_float2(biasA2[0], biasA2[1]);
          *(float2*)&s.bias12[0][hh][rB][m0i] = make_float2(biasB1[0], biasB1[1]);
          *(float2*)&s.bias12[1][hh][rB][m0i] = make_float2(biasB2[0], biasB2[1]);
        }
      } else {
        const float* bA = &s.bias12[l - 1][hh][rA][0];
        const float* bB = &s.bias12[l - 1][hh][rB][0];
#pragma unroll
        for (int t = 0; t < 4; ++t) {
          const int m0i = mblk * 32 + t * 8 + 2 * tig;
          float2 vA = *(const float2*)&bA[m0i];
          float2 vB = *(const float2*)&bB[m0i];
          xA[2 * t]     = aq[t][0] * INV_SQRT_DH + vA.x;
          xA[2 * t + 1] = aq[t][1] * INV_SQRT_DH + vA.y;
          xB[2 * t]     = aq[t][2] * INV_SQRT_DH + vB.x;
          xB[2 * t + 1] = aq[t][3] * INV_SQRT_DH + vB.y;
        }
      }
      float mxA = xA[0], mxB = xB[0];
#pragma unroll
      for (int i = 1; i < 8; ++i) { mxA = fmaxf(mxA, xA[i]); mxB = fmaxf(mxB, xB[i]); }
      mxA = fmaxf(mxA, __shfl_xor_sync(0xffffffffu, mxA, 1));
      mxA = fmaxf(mxA, __shfl_xor_sync(0xffffffffu, mxA, 2));
      mxB = fmaxf(mxB, __shfl_xor_sync(0xffffffffu, mxB, 1));
      mxB = fmaxf(mxB, __shfl_xor_sync(0xffffffffu, mxB, 2));
      float smA = 0.f, smB = 0.f;
#pragma unroll
      for (int i = 0; i < 8; ++i) {
        xA[i] = __expf(xA[i] - mxA); smA += xA[i];
        xB[i] = __expf(xB[i] - mxB); smB += xB[i];
      }
      smA += __shfl_xor_sync(0xffffffffu, smA, 1);
      smA += __shfl_xor_sync(0xffffffffu, smA, 2);
      smB += __shfl_xor_sync(0xffffffffu, smB, 1);
      smB += __shfl_xor_sync(0xffffffffu, smB, 2);
      if (tig == 0) {
        s.rmx[hh][rA][mblk] = mxA;  s.rsm[hh][rA][mblk] = smA;
        s.rmx[hh][rB][mblk] = mxB;  s.rsm[hh][rB][mblk] = smB;
      }
      __syncthreads();                                         // (4)
      float mA0 = s.rmx[hh][rA][0], mA1 = s.rmx[hh][rA][1];
      float gA = fmaxf(mA0, mA1);
      float dA = s.rsm[hh][rA][0] * __expf(mA0 - gA)
               + s.rsm[hh][rA][1] * __expf(mA1 - gA);
      float mB0 = s.rmx[hh][rB][0], mB1 = s.rmx[hh][rB][1];
      float gB = fmaxf(mB0, mB1);
      float dB = s.rsm[hh][rB][0] * __expf(mB0 - gB)
               + s.rsm[hh][rB][1] * __expf(mB1 - gB);
      const float scA = __expf(mxA - gA) / dA;
      const float scB = __expf(mxB - gB) / dB;
      const int baseA = (hh * 64 + rA) * TPAD;
      const int baseB = (hh * 64 + rB) * TPAD;
#pragma unroll
      for (int t = 0; t < 4; ++t) {
        int mp = mblk * 16 + t * 4 + tig;
        pack2(xA[2 * t] * scA, xA[2 * t + 1] * scA,
              &s.u1h[baseA + mp], &s.u1l[baseA + mp]);
        pack2(xB[2 * t] * scB, xB[2 * t + 1] * scB,
              &s.u1h[baseB + mp], &s.u1l[baseB + mp]);
      }
    }
    __syncthreads();                                           // (5)

    // ---- msg = attn @ v (head hh, dh-half mblk) -> pack into ahp/alp ----
#pragma unroll
    for (int t = 0; t < 4; ++t)
#pragma unroll
      for (int i = 0; i < 4; ++i) aq[t][i] = 0.f;
    {
      const int dhb = mblk * 32;
#pragma unroll
      for (int ks = 0; ks < 4; ++ks) {
        const uint32_t aoff = (uint32_t)(ks * 8) * 4;
        uint32_t ah0, ah1, ah2, ah3, al0, al1, al2, al3;
        ldsm4(ah0, ah1, ah2, ah3, atBaseH + aoff);
        ldsm4(al0, al1, al2, al3, atBaseL + aoff);
#pragma unroll
        for (int t = 0; t < 4; ++t) {
          uint32_t bh0, bh1, bl0, bl1;
          ldsm4(bh0, bh1, bl0, bl1,
                vBase + (uint32_t)((hh * 64 + dhb + t * 8) * TPAD + ks * 8) * 4);
          mma_bf16(aq[t], ah0, ah1, ah2, ah3, bh0, bh1);
          mma_bf16(aq[t], ah0, ah1, ah2, ah3, bl0, bl1);
          mma_bf16(aq[t], al0, al1, al2, al3, bh0, bh1);
        }
      }
#pragma unroll
      for (int t = 0; t < 4; ++t) {
        int kp = hh * 32 + (dhb >> 1) + t * 4 + tig;
        pack2(aq[t][0], aq[t][1], &s.ahp[rA][kp], &s.alp[rA][kp]);
        pack2(aq[t][2], aq[t][3], &s.ahp[rB][kp], &s.alp[rB][kp]);
      }
    }
    __syncthreads();                                           // (6)

    // ---- h += msg @ Wo (M=16 x N=32 mapping) ----
#pragma unroll
    for (int t = 0; t < 4; ++t)
#pragma unroll
      for (int i = 0; i < 4; ++i) ak[t][i] = 0.f;
#pragma unroll
    for (int kst = 0; kst < 8; ++kst) {
      uint32_t ah0, ah1, ah2, ah3, al0, al1, al2, al3;
      ldsm4(ah0, ah1, ah2, ah3, aBaseH + kst * 32);
      ldsm4(al0, al1, al2, al3, aBaseL + kst * 32);
      const int fo = kst * 512 + tb * 32 + lane;
      uint4 f0 = wo[fo], f1 = wo[fo + 32], f2 = wo[fo + 64], f3 = wo[fo + 96];
      mma3(ak[0], ah0, ah1, ah2, ah3, al0, al1, al2, al3, f0);
      mma3(ak[1], ah0, ah1, ah2, ah3, al0, al1, al2, al3, f1);
      mma3(ak[2], ah0, ah1, ah2, ah3, al0, al1, al2, al3, f2);
      mma3(ak[3], ah0, ah1, ah2, ah3, al0, al1, al2, al3, f3);
    }
#pragma unroll
    for (int t = 0; t < 4; ++t) {
      int c = nb + t * 8 + 2 * tig;
      float2 h0 = *(float2*)&s.h[rA][c];
      h0.x += ak[t][0]; h0.y += ak[t][1];
      *(float2*)&s.h[rA][c] = h0;
      float2 h1 = *(float2*)&s.h[rB][c];
      h1.x += ak[t][2]; h1.y += ak[t][3];
      *(float2*)&s.h[rB][c] = h1;
    }
    __syncthreads();                                           // (7)

    // ---- h = (h + tanh(LN(h) @ Wf + bf)) * mask ----
    ln_split(s.h, s.ahp, s.alp, tid);
    __syncthreads();                                           // (8)
#pragma unroll
    for (int t = 0; t < 4; ++t)
#pragma unroll
      for (int i = 0; i < 4; ++i) ak[t][i] = 0.f;
#pragma unroll
    for (int kst = 0; kst < 8; ++kst) {
      uint32_t ah0, ah1, ah2, ah3, al0, al1, al2, al3;
      ldsm4(ah0, ah1, ah2, ah3, aBaseH + kst * 32);
      ldsm4(al0, al1, al2, al3, aBaseL + kst * 32);
      const int fo = kst * 512 + tb * 32 + lane;
      uint4 f0 = wf[fo], f1 = wf[fo + 32], f2 = wf[fo + 64], f3 = wf[fo + 96];
      mma3(ak[0], ah0, ah1, ah2, ah3, al0, al1, al2, al3, f0);
      mma3(ak[1], ah0, ah1, ah2, ah3, al0, al1, al2, al3, f1);
      mma3(ak[2], ah0, ah1, ah2, ah3, al0, al1, al2, al3, f2);
      mma3(ak[3], ah0, ah1, ah2, ah3, al0, al1, al2, al3, f3);
    }
    {
      float mr0 = s.mrow[rA];
      float mr1 = s.mrow[rB];
#pragma unroll
      for (int t = 0; t < 4; ++t) {
        int c = nb + t * 8 + 2 * tig;
        float2 h0 = *(float2*)&s.h[rA][c];
        h0.x = (h0.x + tanhf(ak[t][0] + s.bf_l[c]))     * mr0;
        h0.y = (h0.y + tanhf(ak[t][1] + s.bf_l[c + 1])) * mr0;
        *(float2*)&s.h[rA][c] = h0;
        float2 h1 = *(float2*)&s.h[rB][c];
        h1.x = (h1.x + tanhf(ak[t][2] + s.bf_l[c]))     * mr1;
        h1.y = (h1.y + tanhf(ak[t][3] + s.bf_l[c + 1])) * mr1;
        *(float2*)&s.h[rB][c] = h1;
      }
    }
    __syncthreads();                                           // (9)
  }

  // ---- final layernorm -> global output ----
  {
    const int w = tid >> 5, ln = tid & 31;
    for (int n = w; n < N; n += 16) {
      float x0 = s.h[n][ln], x1 = s.h[n][ln + 32];
      float x2 = s.h[n][ln + 64], x3 = s.h[n][ln + 96];
      float sm = x0 + x1 + x2 + x3;
#pragma unroll
      for (int o = 16; o; o >>= 1) sm += __shfl_xor_sync(0xffffffffu, sm, o);
      float mean = sm * (1.f / 128.f);
      float d0 = x0 - mean, d1 = x1 - mean, d2 = x2 - mean, d3 = x3 - mean;
      float ss = d0 * d0 + d1 * d1 + d2 * d2 + d3 * d3;
#pragma unroll
      for (int o = 16; o; o >>= 1) ss += __shfl_xor_sync(0xffffffffu, ss, o);
      float inv = rsqrtf(ss * (1.f / 128.f) + 1e-5f);
      float* orow = g_out + (size_t)(b * N + n) * F;
      orow[ln]      = d0 * inv;
      orow[ln + 32] = d1 * inv;
      orow[ln + 64] = d2 * inv;
      orow[ln + 96] = d3 * inv;
    }
  }
}

// Split + fragment-order all 15 weight matrices.
__global__ void prep_weights(const float* __restrict__ Wq,
                             const float* __restrict__ Wk,
                             const float* __restrict__ Wv,
                             const float* __restrict__ Wo,
                             const float* __restrict__ Wf)
{
  int idx = blockIdx.x * blockDim.x + threadIdx.x;
  if (idx >= 15 * 8 * 16 * 32) return;
  int mat   = idx >> 12;
  int kst   = (idx >> 9) & 7;
  int ntile = (idx >> 5) & 15;
  int lane  = idx & 31;
  int l = mat / 5, which = mat % 5;
  const float* W =
      (which == 0 ? Wq : which == 1 ? Wk : which == 2 ? Wv : which == 3 ? Wo : Wf)
      + l * F * F;
  int n   = ntile * 8 + (lane >> 2);
  int kpA = kst * 8 + (lane & 3);
  int kpB = kpA + 4;

  float a0 = W[(2 * kpA)     * F + n];
  float a1 = W[(2 * kpA + 1) * F + n];
  float c0 = W[(2 * kpB)     * F + n];
  float c1 = W[(2 * kpB + 1) * F + n];

  __nv_bfloat162 ha = __floats2bfloat162_rn(a0, a1);
  __nv_bfloat162 la = __floats2bfloat162_rn(a0 - __bfloat162float(ha.x),
                                            a1 - __bfloat162float(ha.y));
  __nv_bfloat162 hc = __floats2bfloat162_rn(c0, c1);
  __nv_bfloat162 lc = __floats2bfloat162_rn(c0 - __bfloat162float(hc.x),
                                            c1 - __bfloat162float(hc.y));
  uint4 w;
  w.x = *reinterpret_cast<uint32_t*>(&ha);
  w.y = *reinterpret_cast<uint32_t*>(&hc);
  w.z = *reinterpret_cast<uint32_t*>(&la);
  w.w = *reinterpret_cast<uint32_t*>(&lc);
  g_wfrag[idx] = w;
}

}  // namespace

extern "C" void kernel_launch(void* const* d_in, const int* in_sizes, int n_in,
                              void* d_out, int out_size)
{
  (void)n_in; (void)out_size;
  const float* coords  = (const float*)d_in[0];
  const int*   species = (const int*)d_in[1];
  const int*   mask    = (const int*)d_in[2];
  const float* embed   = (const float*)d_in[3];
  const float* Wq      = (const float*)d_in[4];
  const float* Wk      = (const float*)d_in[5];
  const float* Wv      = (const float*)d_in[6];
  const float* Wo      = (const float*)d_in[7];
  const float* We      = (const float*)d_in[8];
  const float* Wf      = (const float*)d_in[9];
  const float* bf      = (const float*)d_in[10];

  const int B = in_sizes[0] / (N * 3);   // 2048

  prep_weights<<<(15 * 8 * 16 * 32 + 255) / 256, 256>>>(Wq, Wk, Wv, Wo, Wf);

  cudaFuncSetAttribute(gnn_kernel, cudaFuncAttributeMaxDynamicSharedMemorySize,
                       (int)sizeof(Smem));
  gnn_kernel<<<B, TPB, sizeof(Smem)>>>(coords, species, mask, embed,
                                       We, bf, (float*)d_out);
}

// round 12
// speedup vs baseline: 3.4981x; 1.0934x over previous
#include <cuda_runtime.h>
#include <cuda_bf16.h>
#include <stdint.h>
#include <math.h>

#define TPB 512

namespace {

constexpr int N = 64;
constexpr int F = 128;
constexpr int APAD = 68;   // [n][kpair] packed stride (A ops, q, k)
constexpr int TPAD = 36;   // [dh][mpair] & [hh][n][mpair] stride
constexpr float NEGV = -1e9f;
constexpr float INV_SQRT_DH = 0.125f;

// Fragment-ordered split weights: [15 mats][kstep 8][ntile 16][lane 32] x uint4
__device__ uint4 g_wfrag[15 * 8 * 16 * 32];

struct __align__(16) Smem {
  float h[N][F];                         // residual (1W + 1R per layer)
  uint32_t ahp[N][APAD], alp[N][APAD];   // LN(h) -> q -> msg -> LN(h)
  uint32_t u1h[4608], u1l[4608];         // k [m][APAD]  then  attn [hh*64+n][TPAD]
  uint32_t vth[F][TPAD], vtl[F][TPAD];   // v transposed [dh][mpair]
  float bias12[2][2][64][64];            // cached edge bias for layers 1,2
  float rmx[2][64][2], rsm[2][64][2];
  float pS[64][8], pQ[64][8];            // LN row-stat partials (8 col groups)
  float coords[N][3];
  float mrow[N];
  float bf_l[F];
  float Wel[3][7][2];
};

__device__ __forceinline__ void mma_bf16(float* d,
    uint32_t a0, uint32_t a1, uint32_t a2, uint32_t a3,
    uint32_t b0, uint32_t b1)
{
  asm volatile(
    "mma.sync.aligned.m16n8k16.row.col.f32.bf16.bf16.f32 "
    "{%0,%1,%2,%3}, {%4,%5,%6,%7}, {%8,%9}, {%0,%1,%2,%3};\n"
    : "+f"(d[0]), "+f"(d[1]), "+f"(d[2]), "+f"(d[3])
    : "r"(a0), "r"(a1), "r"(a2), "r"(a3), "r"(b0), "r"(b1));
}

__device__ __forceinline__ void mma3(float* d,
    uint32_t ah0, uint32_t ah1, uint32_t ah2, uint32_t ah3,
    uint32_t al0, uint32_t al1, uint32_t al2, uint32_t al3,
    uint4 w)
{
  mma_bf16(d, ah0, ah1, ah2, ah3, w.x, w.y);
  mma_bf16(d, ah0, ah1, ah2, ah3, w.z, w.w);
  mma_bf16(d, al0, al1, al2, al3, w.x, w.y);
}

__device__ __forceinline__ void ldsm4(uint32_t& r0, uint32_t& r1,
                                      uint32_t& r2, uint32_t& r3, uint32_t a)
{
  asm volatile("ldmatrix.sync.aligned.m8n8.x4.shared.b16 {%0,%1,%2,%3}, [%4];"
               : "=r"(r0), "=r"(r1), "=r"(r2), "=r"(r3) : "r"(a));
}

__device__ __forceinline__ void pack2(float x, float y,
                                      uint32_t* hp, uint32_t* lp)
{
  __nv_bfloat162 h2 = __floats2bfloat162_rn(x, y);
  float hx = __bfloat162float(h2.x), hy = __bfloat162float(h2.y);
  __nv_bfloat162 l2 = __floats2bfloat162_rn(x - hx, y - hy);
  *hp = *reinterpret_cast<uint32_t*>(&h2);
  *lp = *reinterpret_cast<uint32_t*>(&l2);
}

__device__ __forceinline__ uint32_t s2u(const void* p) {
  return (uint32_t)__cvta_generic_to_shared(p);
}

// Write LN row partial sums/sumsq from the register h tile (M32xN16 mapping).
// Rows r0q, r0q+8, r0q+16, r0q+24; 16-col group cg.
__device__ __forceinline__ void ln_partials(const float hv[4][4], int r0q,
    int cg, int tig, float (*pS)[8], float (*pQ)[8])
{
  float s0 = (hv[0][0] + hv[0][1]) + (hv[1][0] + hv[1][1]);
  float s1 = (hv[0][2] + hv[0][3]) + (hv[1][2] + hv[1][3]);
  float s2 = (hv[2][0] + hv[2][1]) + (hv[3][0] + hv[3][1]);
  float s3 = (hv[2][2] + hv[2][3]) + (hv[3][2] + hv[3][3]);
  float q0 = (hv[0][0]*hv[0][0] + hv[0][1]*hv[0][1]) + (hv[1][0]*hv[1][0] + hv[1][1]*hv[1][1]);
  float q1 = (hv[0][2]*hv[0][2] + hv[0][3]*hv[0][3]) + (hv[1][2]*hv[1][2] + hv[1][3]*hv[1][3]);
  float q2 = (hv[2][0]*hv[2][0] + hv[2][1]*hv[2][1]) + (hv[3][0]*hv[3][0] + hv[3][1]*hv[3][1]);
  float q3 = (hv[2][2]*hv[2][2] + hv[2][3]*hv[2][3]) + (hv[3][2]*hv[3][2] + hv[3][3]*hv[3][3]);
#pragma unroll
  for (int o = 1; o <= 2; o <<= 1) {
    s0 += __shfl_xor_sync(0xffffffffu, s0, o);
    s1 += __shfl_xor_sync(0xffffffffu, s1, o);
    s2 += __shfl_xor_sync(0xffffffffu, s2, o);
    s3 += __shfl_xor_sync(0xffffffffu, s3, o);
    q0 += __shfl_xor_sync(0xffffffffu, q0, o);
    q1 += __shfl_xor_sync(0xffffffffu, q1, o);
    q2 += __shfl_xor_sync(0xffffffffu, q2, o);
    q3 += __shfl_xor_sync(0xffffffffu, q3, o);
  }
  if (tig == 0) {
    pS[r0q     ][cg] = s0;  pQ[r0q     ][cg] = q0;
    pS[r0q +  8][cg] = s1;  pQ[r0q +  8][cg] = q1;
    pS[r0q + 16][cg] = s2;  pQ[r0q + 16][cg] = q2;
    pS[r0q + 24][cg] = s3;  pQ[r0q + 24][cg] = q3;
  }
}

// Read stats, normalize register h tile, pack into ahp/alp.
__device__ __forceinline__ void ln_pack(const float hv[4][4], int r0q, int kp0,
    const float (*pS)[8], const float (*pQ)[8],
    uint32_t (*ahp)[APAD], uint32_t (*alp)[APAD])
{
#pragma unroll
  for (int rr = 0; rr < 4; ++rr) {
    const int r = r0q + rr * 8;
    float4 sa = *(const float4*)&pS[r][0];
    float4 sb = *(const float4*)&pS[r][4];
    float sum = ((sa.x + sa.y) + (sa.z + sa.w)) + ((sb.x + sb.y) + (sb.z + sb.w));
    float4 qa = *(const float4*)&pQ[r][0];
    float4 qb = *(const float4*)&pQ[r][4];
    float qs = ((qa.x + qa.y) + (qa.z + qa.w)) + ((qb.x + qb.y) + (qb.z + qb.w));
    float mean = sum * (1.f / 128.f);
    float var = qs * (1.f / 128.f) - mean * mean;
    float inv = rsqrtf(var + 1e-5f);
    const int ub = (rr >> 1) * 2;
    const int ib = (rr & 1) * 2;
    float n0 = (hv[ub][ib]     - mean) * inv;
    float n1 = (hv[ub][ib + 1] - mean) * inv;
    float n2 = (hv[ub + 1][ib]     - mean) * inv;
    float n3 = (hv[ub + 1][ib + 1] - mean) * inv;
    pack2(n0, n1, &ahp[r][kp0],     &alp[r][kp0]);
    pack2(n2, n3, &ahp[r][kp0 + 4], &alp[r][kp0 + 4]);
  }
}

__global__ void __launch_bounds__(TPB, 1) gnn_kernel(
    const float* __restrict__ g_coords,
    const int*   __restrict__ g_species,
    const int*   __restrict__ g_mask,
    const float* __restrict__ g_embed,
    const float* __restrict__ g_We,
    const float* __restrict__ g_bf,
    float* __restrict__ g_out)
{
  extern __shared__ unsigned char smem_raw[];
  Smem& s = *reinterpret_cast<Smem*>(smem_raw);
  const int b = blockIdx.x;
  const int tid = threadIdx.x;

  const int warp = tid >> 5, lane = tid & 31;
  // attention mapping (M=16 x N=32 tiles)
  const int mb = (warp & 3) << 4;
  const int lm = lane >> 2, tig = lane & 3;
  const int rA = mb + lm, rB = mb + lm + 8;
  const int hh   = warp >> 3;
  const int mblk = (warp >> 2) & 1;
  // weight-GEMM mapping (M=32 x N=16)
  const int wqm = (warp & 1) << 5;
  const int wqn = (warp >> 1) << 4;
  const int ntb = (warp >> 1) << 1;
  const int r0q = wqm + lm;              // base row of this thread's h tile
  const int cg  = warp >> 1;             // 16-col group 0..7
  const int kp0 = (wqn >> 1) + tig;      // base kpair for LN pack

  if (tid < N) {
    s.mrow[tid] = (g_mask[b * N + tid] != 0) ? 1.f : 0.f;
    s.coords[tid][0] = g_coords[(b * N + tid) * 3 + 0];
    s.coords[tid][1] = g_coords[(b * N + tid) * 3 + 1];
    s.coords[tid][2] = g_coords[(b * N + tid) * 3 + 2];
  }
  if (tid >= 64 && tid < 64 + 42)
    ((float*)s.Wel)[tid - 64] = g_We[tid - 64];

  // ---- initial h: registers + one smem copy + LN partials ----
  float hv[4][4];
#pragma unroll
  for (int rt = 0; rt < 2; ++rt)
#pragma unroll
    for (int tq = 0; tq < 2; ++tq) {
      const int u = rt * 2 + tq;
      const int rA2 = wqm + rt * 16 + lm, rB2 = rA2 + 8;
      const int c2 = wqn + tq * 8 + 2 * tig;
      const int mA = g_mask[b * N + rA2], mB = g_mask[b * N + rB2];
      const int sA = g_species[b * N + rA2] - 1;
      const int sB = g_species[b * N + rB2] - 1;
      float2 eA = *(const float2*)&g_embed[sA * F + c2];
      float2 eB = *(const float2*)&g_embed[sB * F + c2];
      hv[u][0] = mA ? eA.x : 0.f;  hv[u][1] = mA ? eA.y : 0.f;
      hv[u][2] = mB ? eB.x : 0.f;  hv[u][3] = mB ? eB.y : 0.f;
      *(float2*)&s.h[rA2][c2] = make_float2(hv[u][0], hv[u][1]);
      *(float2*)&s.h[rB2][c2] = make_float2(hv[u][2], hv[u][3]);
    }
  ln_partials(hv, r0q, cg, tig, s.pS, s.pQ);
  __syncthreads();

  // ldmatrix per-thread geometry
  const int g8 = lane >> 3, r8 = lane & 7;
  const int hl8 = g8 >> 1, bs8 = g8 & 1;
  const uint32_t aBaseH = s2u(&s.ahp[mb + (g8 & 1) * 8 + r8][(g8 >> 1) * 4]);
  const uint32_t aBaseL = s2u(&s.alp[mb + (g8 & 1) * 8 + r8][(g8 >> 1) * 4]);
  const uint32_t aqBaseH = s2u(&s.ahp[wqm + (g8 & 1) * 8 + r8][(g8 >> 1) * 4]);
  const uint32_t aqBaseL = s2u(&s.alp[wqm + (g8 & 1) * 8 + r8][(g8 >> 1) * 4]);
  const uint32_t RT1 = 16 * APAD * 4;
  const uint32_t kBase = s2u(hl8 ? s.u1l : s.u1h) + (uint32_t)(r8 * APAD + bs8 * 4) * 4;
  const uint32_t atBaseH = s2u(s.u1h)
      + (uint32_t)((hh * 64 + mb + (g8 & 1) * 8 + r8) * TPAD + (g8 >> 1) * 4) * 4;
  const uint32_t atBaseL = s2u(s.u1l)
      + (uint32_t)((hh * 64 + mb + (g8 & 1) * 8 + r8) * TPAD + (g8 >> 1) * 4) * 4;
  const uint32_t vBase = s2u(hl8 ? (uint32_t*)s.vtl : (uint32_t*)s.vth)
      + (uint32_t)(r8 * TPAD + bs8 * 4) * 4;

  float aq[4][4], ak[4][4], av[4][4];

  for (int l = 0; l < 3; ++l) {
    if (tid < F) s.bf_l[tid] = g_bf[l * F + tid];

    const uint4* __restrict__ wq = g_wfrag + (size_t)(l * 5 + 0) * 4096;
    const uint4* __restrict__ wk = g_wfrag + (size_t)(l * 5 + 1) * 4096;
    const uint4* __restrict__ wv = g_wfrag + (size_t)(l * 5 + 2) * 4096;
    const uint4* __restrict__ wo = g_wfrag + (size_t)(l * 5 + 3) * 4096;
    const uint4* __restrict__ wf = g_wfrag + (size_t)(l * 5 + 4) * 4096;

    // ---- LN(h) from registers -> ahp/alp ----
    ln_pack(hv, r0q, kp0, s.pS, s.pQ, s.ahp, s.alp);
    __syncthreads();                                           // (1)

    // ---- fused q,k,v GEMM, M=32 x N=16 per warp ----
#pragma unroll
    for (int u = 0; u < 4; ++u)
#pragma unroll
      for (int i = 0; i < 4; ++i) { aq[u][i] = 0.f; ak[u][i] = 0.f; av[u][i] = 0.f; }
#pragma unroll
    for (int kst = 0; kst < 8; ++kst) {
      uint32_t x0h0, x0h1, x0h2, x0h3, x0l0, x0l1, x0l2, x0l3;
      uint32_t x1h0, x1h1, x1h2, x1h3, x1l0, x1l1, x1l2, x1l3;
      ldsm4(x0h0, x0h1, x0h2, x0h3, aqBaseH + kst * 32);
      ldsm4(x0l0, x0l1, x0l2, x0l3, aqBaseL + kst * 32);
      ldsm4(x1h0, x1h1, x1h2, x1h3, aqBaseH + RT1 + kst * 32);
      ldsm4(x1l0, x1l1, x1l2, x1l3, aqBaseL + RT1 + kst * 32);
      const int fo = kst * 512 + ntb * 32 + lane;
      {
        uint4 f0 = wq[fo], f1 = wq[fo + 32];
        mma3(aq[0], x0h0, x0h1, x0h2, x0h3, x0l0, x0l1, x0l2, x0l3, f0);
        mma3(aq[1], x0h0, x0h1, x0h2, x0h3, x0l0, x0l1, x0l2, x0l3, f1);
        mma3(aq[2], x1h0, x1h1, x1h2, x1h3, x1l0, x1l1, x1l2, x1l3, f0);
        mma3(aq[3], x1h0, x1h1, x1h2, x1h3, x1l0, x1l1, x1l2, x1l3, f1);
      }
      {
        uint4 f0 = wk[fo], f1 = wk[fo + 32];
        mma3(ak[0], x0h0, x0h1, x0h2, x0h3, x0l0, x0l1, x0l2, x0l3, f0);
        mma3(ak[1], x0h0, x0h1, x0h2, x0h3, x0l0, x0l1, x0l2, x0l3, f1);
        mma3(ak[2], x1h0, x1h1, x1h2, x1h3, x1l0, x1l1, x1l2, x1l3, f0);
        mma3(ak[3], x1h0, x1h1, x1h2, x1h3, x1l0, x1l1, x1l2, x1l3, f1);
      }
      {
        uint4 f0 = wv[fo], f1 = wv[fo + 32];
        mma3(av[0], x0h0, x0h1, x0h2, x0h3, x0l0, x0l1, x0l2, x0l3, f0);
        mma3(av[1], x0h0, x0h1, x0h2, x0h3, x0l0, x0l1, x0l2, x0l3, f1);
        mma3(av[2], x1h0, x1h1, x1h2, x1h3, x1l0, x1l1, x1l2, x1l3, f0);
        mma3(av[3], x1h0, x1h1, x1h2, x1h3, x1l0, x1l1, x1l2, x1l3, f1);
      }
    }
    __syncthreads();                                           // (2) A reads done

    // q/k/v packs (qkv mapping)
#pragma unroll
    for (int rt = 0; rt < 2; ++rt)
#pragma unroll
      for (int tq = 0; tq < 2; ++tq) {
        const int u = rt * 2 + tq;
        const int rowA = wqm + rt * 16 + lm, rowB = rowA + 8;
        const int kp = (wqn + tq * 8 + 2 * tig) >> 1;
        pack2(aq[u][0], aq[u][1], &s.ahp[rowA][kp], &s.alp[rowA][kp]);
        pack2(aq[u][2], aq[u][3], &s.ahp[rowB][kp], &s.alp[rowB][kp]);
        pack2(ak[u][0], ak[u][1], &s.u1h[rowA * APAD + kp], &s.u1l[rowA * APAD + kp]);
        pack2(ak[u][2], ak[u][3], &s.u1h[rowB * APAD + kp], &s.u1l[rowB * APAD + kp]);
        const int c = wqn + tq * 8 + 2 * tig;
        const int mbv = wqm + rt * 16;
        float p0 = __shfl_xor_sync(0xffffffffu, av[u][0], 4);
        float p1 = __shfl_xor_sync(0xffffffffu, av[u][1], 4);
        float p2 = __shfl_xor_sync(0xffffffffu, av[u][2], 4);
        float p3 = __shfl_xor_sync(0xffffffffu, av[u][3], 4);
        if ((lm & 1) == 0) {
          int mp = (mbv + lm) >> 1;
          pack2(av[u][0], p0, &s.vth[c][mp],     &s.vtl[c][mp]);
          pack2(av[u][1], p1, &s.vth[c + 1][mp], &s.vtl[c + 1][mp]);
        } else {
          int mp = (mbv + lm + 7) >> 1;
          pack2(p2, av[u][2], &s.vth[c][mp],     &s.vtl[c][mp]);
          pack2(p3, av[u][3], &s.vth[c + 1][mp], &s.vtl[c + 1][mp]);
        }
      }
    __syncthreads();                                           // (3)

    // ---- logits = q @ k^T (head hh, m-half mblk) ----
#pragma unroll
    for (int t = 0; t < 4; ++t)
#pragma unroll
      for (int i = 0; i < 4; ++i) aq[t][i] = 0.f;
#pragma unroll
    for (int ks = 0; ks < 4; ++ks) {
      const uint32_t aoff = (uint32_t)(hh * 32 + ks * 8) * 4;
      uint32_t ah0, ah1, ah2, ah3, al0, al1, al2, al3;
      ldsm4(ah0, ah1, ah2, ah3, aBaseH + aoff);
      ldsm4(al0, al1, al2, al3, aBaseL + aoff);
#pragma unroll
      for (int t = 0; t < 4; ++t) {
        uint32_t bh0, bh1, bl0, bl1;
        ldsm4(bh0, bh1, bl0, bl1,
              kBase + (uint32_t)((mblk * 32 + t * 8) * APAD + hh * 32 + ks * 8) * 4);
        mma_bf16(aq[t], ah0, ah1, ah2, ah3, bh0, bh1);
        mma_bf16(aq[t], ah0, ah1, ah2, ah3, bl0, bl1);
        mma_bf16(aq[t], al0, al1, al2, al3, bh0, bh1);
      }
    }

    // ---- epilogue: scale + bias + mask + 1-barrier softmax -> attn ----
    {
      float xA[8], xB[8];
      if (l == 0) {
        const float w0 = s.Wel[0][0][hh], w1 = s.Wel[0][1][hh], w2 = s.Wel[0][2][hh],
                    w3 = s.Wel[0][3][hh], w4 = s.Wel[0][4][hh], w5 = s.Wel[0][5][hh],
                    w6 = s.Wel[0][6][hh];
        const float u0 = s.Wel[1][0][hh], u1 = s.Wel[1][1][hh], u2 = s.Wel[1][2][hh],
                    u3 = s.Wel[1][3][hh], u4 = s.Wel[1][4][hh], u5 = s.Wel[1][5][hh],
                    u6 = s.Wel[1][6][hh];
        const float v0 = s.Wel[2][0][hh], v1 = s.Wel[2][1][hh], v2 = s.Wel[2][2][hh],
                    v3 = s.Wel[2][3][hh], v4 = s.Wel[2][4][hh], v5 = s.Wel[2][5][hh],
                    v6 = s.Wel[2][6][hh];
        const bool okA = s.mrow[rA] > 0.f, okB = s.mrow[rB] > 0.f;
        const float a0 = s.coords[rA][0], a1 = s.coords[rA][1], a2 = s.coords[rA][2];
        const float b0 = s.coords[rB][0], b1 = s.coords[rB][1], b2 = s.coords[rB][2];
#pragma unroll
        for (int t = 0; t < 4; ++t) {
          float biasA1[2], biasA2[2], biasB1[2], biasB2[2];
#pragma unroll
          for (int j = 0; j < 2; ++j) {
            const int m = mblk * 32 + t * 8 + 2 * tig + j;
            const float m0 = s.coords[m][0], m1 = s.coords[m][1], m2 = s.coords[m][2];
            const bool okm = s.mrow[m] > 0.f;
            {
              float dx = a0 - m0, dy = a1 - m1, dz = a2 - m2;
              float d = sqrtf(dx * dx + dy * dy + dz * dz + 1e-12f);
              float g1 = 1.f / (1.f + __expf(2.f - d));
              float g2 = 1.f / (1.f + __expf(4.f - d));
              float g3 = 1.f / (1.f + __expf(6.f - d));
              float bias = dx * w0 + dy * w1 + dz * w2 + d * w3
                         + g1 * w4 + g2 * w5 + g3 * w6;
              bool ok = okA && okm;
              xA[2 * t + j] = ok ? aq[t][j] * INV_SQRT_DH + bias : NEGV;
              biasA1[j] = ok ? dx * u0 + dy * u1 + dz * u2 + d * u3
                             + g1 * u4 + g2 * u5 + g3 * u6 : NEGV;
              biasA2[j] = ok ? dx * v0 + dy * v1 + dz * v2 + d * v3
                             + g1 * v4 + g2 * v5 + g3 * v6 : NEGV;
            }
            {
              float dx = b0 - m0, dy = b1 - m1, dz = b2 - m2;
              float d = sqrtf(dx * dx + dy * dy + dz * dz + 1e-12f);
              float g1 = 1.f / (1.f + __expf(2.f - d));
              float g2 = 1.f / (1.f + __expf(4.f - d));
              float g3 = 1.f / (1.f + __expf(6.f - d));
              float bias = dx * w0 + dy * w1 + dz * w2 + d * w3
                         + g1 * w4 + g2 * w5 + g3 * w6;
              bool ok = okB && okm;
              xB[2 * t + j] = ok ? aq[t][2 + j] * INV_SQRT_DH + bias : NEGV;
              biasB1[j] = ok ? dx * u0 + dy * u1 + dz * u2 + d * u3
                             + g1 * u4 + g2 * u5 + g3 * u6 : NEGV;
              biasB2[j] = ok ? dx * v0 + dy * v1 + dz * v2 + d * v3
                             + g1 * v4 + g2 * v5 + g3 * v6 : NEGV;
            }
          }
          const int m0i = mblk * 32 + t * 8 + 2 * tig;
          *(float2*)&s.bias12[0][hh][rA][m0i] = make_float2(biasA1[0], biasA1[1]);
          *(float2*)&s.bias12[1][hh][rA][m0i] = make_float2(biasA2[0], biasA2[1]);
          *(float2*)&s.bias12[0][hh][rB][m0i] = make_float2(biasB1[0], biasB1[1]);
          *(float2*)&s.bias12[1][hh][rB][m0i] = make_float2(biasB2[0], biasB2[1]);
        }
      } else {
        const float* bA = &s.bias12[l - 1][hh][rA][0];
        const float* bB = &s.bias12[l - 1][hh][rB][0];
#pragma unroll
        for (int t = 0; t < 4; ++t) {
          const int m0i = mblk * 32 + t * 8 + 2 * tig;
          float2 vA = *(const float2*)&bA[m0i];
          float2 vB = *(const float2*)&bB[m0i];
          xA[2 * t]     = aq[t][0] * INV_SQRT_DH + vA.x;
          xA[2 * t + 1] = aq[t][1] * INV_SQRT_DH + vA.y;
          xB[2 * t]     = aq[t][2] * INV_SQRT_DH + vB.x;
          xB[2 * t + 1] = aq[t][3] * INV_SQRT_DH + vB.y;
        }
      }
      float mxA = xA[0], mxB = xB[0];
#pragma unroll
      for (int i = 1; i < 8; ++i) { mxA = fmaxf(mxA, xA[i]); mxB = fmaxf(mxB, xB[i]); }
      mxA = fmaxf(mxA, __shfl_xor_sync(0xffffffffu, mxA, 1));
      mxA = fmaxf(mxA, __shfl_xor_sync(0xffffffffu, mxA, 2));
      mxB = fmaxf(mxB, __shfl_xor_sync(0xffffffffu, mxB, 1));
      mxB = fmaxf(mxB, __shfl_xor_sync(0xffffffffu, mxB, 2));
      float smA = 0.f, smB = 0.f;
#pragma unroll
      for (int i = 0; i < 8; ++i) {
        xA[i] = __expf(xA[i] - mxA); smA += xA[i];
        xB[i] = __expf(xB[i] - mxB); smB += xB[i];
      }
      smA += __shfl_xor_sync(0xffffffffu, smA, 1);
      smA += __shfl_xor_sync(0xffffffffu, smA, 2);
      smB += __shfl_xor_sync(0xffffffffu, smB, 1);
      smB += __shfl_xor_sync(0xffffffffu, smB, 2);
      if (tig == 0) {
        s.rmx[hh][rA][mblk] = mxA;  s.rsm[hh][rA][mblk] = smA;
        s.rmx[hh][rB][mblk] = mxB;  s.rsm[hh][rB][mblk] = smB;
      }
      __syncthreads();                                         // (4)
      float mA0 = s.rmx[hh][rA][0], mA1 = s.rmx[hh][rA][1];
      float gA = fmaxf(mA0, mA1);
      float dA = s.rsm[hh][rA][0] * __expf(mA0 - gA)
               + s.rsm[hh][rA][1] * __expf(mA1 - gA);
      float mB0 = s.rmx[hh][rB][0], mB1 = s.rmx[hh][rB][1];
      float gB = fmaxf(mB0, mB1);
      float dB = s.rsm[hh][rB][0] * __expf(mB0 - gB)
               + s.rsm[hh][rB][1] * __expf(mB1 - gB);
      const float scA = __expf(mxA - gA) / dA;
      const float scB = __expf(mxB - gB) / dB;
      const int baseA = (hh * 64 + rA) * TPAD;
      const int baseB = (hh * 64 + rB) * TPAD;
#pragma unroll
      for (int t = 0; t < 4; ++t) {
        int mp = mblk * 16 + t * 4 + tig;
        pack2(xA[2 * t] * scA, xA[2 * t + 1] * scA,
              &s.u1h[baseA + mp], &s.u1l[baseA + mp]);
        pack2(xB[2 * t] * scB, xB[2 * t + 1] * scB,
              &s.u1h[baseB + mp], &s.u1l[baseB + mp]);
      }
    }
    __syncthreads();                                           // (5)

    // ---- msg = attn @ v (head hh, dh-half mblk) -> pack into ahp/alp ----
#pragma unroll
    for (int t = 0; t < 4; ++t)
#pragma unroll
      for (int i = 0; i < 4; ++i) aq[t][i] = 0.f;
    {
      const int dhb = mblk * 32;
#pragma unroll
      for (int ks = 0; ks < 4; ++ks) {
        const uint32_t aoff = (uint32_t)(ks * 8) * 4;
        uint32_t ah0, ah1, ah2, ah3, al0, al1, al2, al3;
        ldsm4(ah0, ah1, ah2, ah3, atBaseH + aoff);
        ldsm4(al0, al1, al2, al3, atBaseL + aoff);
#pragma unroll
        for (int t = 0; t < 4; ++t) {
          uint32_t bh0, bh1, bl0, bl1;
          ldsm4(bh0, bh1, bl0, bl1,
                vBase + (uint32_t)((hh * 64 + dhb + t * 8) * TPAD + ks * 8) * 4);
          mma_bf16(aq[t], ah0, ah1, ah2, ah3, bh0, bh1);
          mma_bf16(aq[t], ah0, ah1, ah2, ah3, bl0, bl1);
          mma_bf16(aq[t], al0, al1, al2, al3, bh0, bh1);
        }
      }
#pragma unroll
      for (int t = 0; t < 4; ++t) {
        int kp = hh * 32 + (dhb >> 1) + t * 4 + tig;
        pack2(aq[t][0], aq[t][1], &s.ahp[rA][kp], &s.alp[rA][kp]);
        pack2(aq[t][2], aq[t][3], &s.ahp[rB][kp], &s.alp[rB][kp]);
      }
    }
    __syncthreads();                                           // (6)

    // ---- h += msg @ Wo (M=32 x N=16 mapping) ----
#pragma unroll
    for (int u = 0; u < 4; ++u)
#pragma unroll
      for (int i = 0; i < 4; ++i) ak[u][i] = 0.f;
#pragma unroll
    for (int kst = 0; kst < 8; ++kst) {
      uint32_t x0h0, x0h1, x0h2, x0h3, x0l0, x0l1, x0l2, x0l3;
      uint32_t x1h0, x1h1, x1h2, x1h3, x1l0, x1l1, x1l2, x1l3;
      ldsm4(x0h0, x0h1, x0h2, x0h3, aqBaseH + kst * 32);
      ldsm4(x0l0, x0l1, x0l2, x0l3, aqBaseL + kst * 32);
      ldsm4(x1h0, x1h1, x1h2, x1h3, aqBaseH + RT1 + kst * 32);
      ldsm4(x1l0, x1l1, x1l2, x1l3, aqBaseL + RT1 + kst * 32);
      const int fo = kst * 512 + ntb * 32 + lane;
      uint4 f0 = wo[fo], f1 = wo[fo + 32];
      mma3(ak[0], x0h0, x0h1, x0h2, x0h3, x0l0, x0l1, x0l2, x0l3, f0);
      mma3(ak[1], x0h0, x0h1, x0h2, x0h3, x0l0, x0l1, x0l2, x0l3, f1);
      mma3(ak[2], x1h0, x1h1, x1h2, x1h3, x1l0, x1l1, x1l2, x1l3, f0);
      mma3(ak[3], x1h0, x1h1, x1h2, x1h3, x1l0, x1l1, x1l2, x1l3, f1);
    }
    // Wo epilogue: h -> registers; LN partials
#pragma unroll
    for (int rt = 0; rt < 2; ++rt)
#pragma unroll
      for (int tq = 0; tq < 2; ++tq) {
        const int u = rt * 2 + tq;
        const int rA2 = wqm + rt * 16 + lm, rB2 = rA2 + 8;
        const int c2 = wqn + tq * 8 + 2 * tig;
        float2 h0 = *(float2*)&s.h[rA2][c2];
        hv[u][0] = h0.x + ak[u][0];  hv[u][1] = h0.y + ak[u][1];
        float2 h1 = *(float2*)&s.h[rB2][c2];
        hv[u][2] = h1.x + ak[u][2];  hv[u][3] = h1.y + ak[u][3];
      }
    ln_partials(hv, r0q, cg, tig, s.pS, s.pQ);
    __syncthreads();                                           // (7)

    // ---- LN(h) from registers -> ahp/alp ----
    ln_pack(hv, r0q, kp0, s.pS, s.pQ, s.ahp, s.alp);
    __syncthreads();                                           // (8)

    // ---- Wf GEMM (M=32 x N=16) ----
#pragma unroll
    for (int u = 0; u < 4; ++u)
#pragma unroll
      for (int i = 0; i < 4; ++i) ak[u][i] = 0.f;
#pragma unroll
    for (int kst = 0; kst < 8; ++kst) {
      uint32_t x0h0, x0h1, x0h2, x0h3, x0l0, x0l1, x0l2, x0l3;
      uint32_t x1h0, x1h1, x1h2, x1h3, x1l0, x1l1, x1l2, x1l3;
      ldsm4(x0h0, x0h1, x0h2, x0h3, aqBaseH + kst * 32);
      ldsm4(x0l0, x0l1, x0l2, x0l3, aqBaseL + kst * 32);
      ldsm4(x1h0, x1h1, x1h2, x1h3, aqBaseH + RT1 + kst * 32);
      ldsm4(x1l0, x1l1, x1l2, x1l3, aqBaseL + RT1 + kst * 32);
      const int fo = kst * 512 + ntb * 32 + lane;
      uint4 f0 = wf[fo], f1 = wf[fo + 32];
      mma3(ak[0], x0h0, x0h1, x0h2, x0h3, x0l0, x0l1, x0l2, x0l3, f0);
      mma3(ak[1], x0h0, x0h1, x0h2, x0h3, x0l0, x0l1, x0l2, x0l3, f1);
      mma3(ak[2], x1h0, x1h1, x1h2, x1h3, x1l0, x1l1, x1l2, x1l3, f0);
      mma3(ak[3], x1h0, x1h1, x1h2, x1h3, x1l0, x1l1, x1l2, x1l3, f1);
    }
    // Wf epilogue: finalize h in registers; store to smem; LN partials
#pragma unroll
    for (int rt = 0; rt < 2; ++rt)
#pragma unroll
      for (int tq = 0; tq < 2; ++tq) {
        const int u = rt * 2 + tq;
        const int rA2 = wqm + rt * 16 + lm, rB2 = rA2 + 8;
        const int c2 = wqn + tq * 8 + 2 * tig;
        float mr0 = s.mrow[rA2], mr1 = s.mrow[rB2];
        hv[u][0] = (hv[u][0] + tanhf(ak[u][0] + s.bf_l[c2]))     * mr0;
        hv[u][1] = (hv[u][1] + tanhf(ak[u][1] + s.bf_l[c2 + 1])) * mr0;
        hv[u][2] = (hv[u][2] + tanhf(ak[u][2] + s.bf_l[c2]))     * mr1;
        hv[u][3] = (hv[u][3] + tanhf(ak[u][3] + s.bf_l[c2 + 1])) * mr1;
        *(float2*)&s.h[rA2][c2] = make_float2(hv[u][0], hv[u][1]);
        *(float2*)&s.h[rB2][c2] = make_float2(hv[u][2], hv[u][3]);
      }
    ln_partials(hv, r0q, cg, tig, s.pS, s.pQ);
    __syncthreads();                                           // (9) / next (1)
  }

  // ---- final layernorm from registers -> global output ----
#pragma unroll
  for (int rr = 0; rr < 4; ++rr) {
    const int r = r0q + rr * 8;
    float4 sa = *(const float4*)&s.pS[r][0];
    float4 sb = *(const float4*)&s.pS[r][4];
    float sum = ((sa.x + sa.y) + (sa.z + sa.w)) + ((sb.x + sb.y) + (sb.z + sb.w));
    float4 qa = *(const float4*)&s.pQ[r][0];
    float4 qb = *(const float4*)&s.pQ[r][4];
    float qs = ((qa.x + qa.y) + (qa.z + qa.w)) + ((qb.x + qb.y) + (qb.z + qb.w));
    float mean = sum * (1.f / 128.f);
    float var = qs * (1.f / 128.f) - mean * mean;
    float inv = rsqrtf(var + 1e-5f);
    const int ub = (rr >> 1) * 2;
    const int ib = (rr & 1) * 2;
    float* orow = g_out + ((size_t)(b * N + r)) * F;
    const int cA = wqn + 2 * tig;
    *(float2*)&orow[cA] = make_float2((hv[ub][ib] - mean) * inv,
                                      (hv[ub][ib + 1] - mean) * inv);
    *(float2*)&orow[cA + 8] = make_float2((hv[ub + 1][ib] - mean) * inv,
                                          (hv[ub + 1][ib + 1] - mean) * inv);
  }
}

// Split + fragment-order all 15 weight matrices.
__global__ void prep_weights(const float* __restrict__ Wq,
                             const float* __restrict__ Wk,
                             const float* __restrict__ Wv,
                             const float* __restrict__ Wo,
                             const float* __restrict__ Wf)
{
  int idx = blockIdx.x * blockDim.x + threadIdx.x;
  if (idx >= 15 * 8 * 16 * 32) return;
  int mat   = idx >> 12;
  int kst   = (idx >> 9) & 7;
  int ntile = (idx >> 5) & 15;
  int lane  = idx & 31;
  int l = mat / 5, which = mat % 5;
  const float* W =
      (which == 0 ? Wq : which == 1 ? Wk : which == 2 ? Wv : which == 3 ? Wo : Wf)
      + l * F * F;
  int n   = ntile * 8 + (lane >> 2);
  int kpA = kst * 8 + (lane & 3);
  int kpB = kpA + 4;

  float a0 = W[(2 * kpA)     * F + n];
  float a1 = W[(2 * kpA + 1) * F + n];
  float c0 = W[(2 * kpB)     * F + n];
  float c1 = W[(2 * kpB + 1) * F + n];

  __nv_bfloat162 ha = __floats2bfloat162_rn(a0, a1);
  __nv_bfloat162 la = __floats2bfloat162_rn(a0 - __bfloat162float(ha.x),
                                            a1 - __bfloat162float(ha.y));
  __nv_bfloat162 hc = __floats2bfloat162_rn(c0, c1);
  __nv_bfloat162 lc = __floats2bfloat162_rn(c0 - __bfloat162float(hc.x),
                                            c1 - __bfloat162float(hc.y));
  uint4 w;
  w.x = *reinterpret_cast<uint32_t*>(&ha);
  w.y = *reinterpret_cast<uint32_t*>(&hc);
  w.z = *reinterpret_cast<uint32_t*>(&la);
  w.w = *reinterpret_cast<uint32_t*>(&lc);
  g_wfrag[idx] = w;
}

}  // namespace

extern "C" void kernel_launch(void* const* d_in, const int* in_sizes, int n_in,
                              void* d_out, int out_size)
{
  (void)n_in; (void)out_size;
  const float* coords  = (const float*)d_in[0];
  const int*   species = (const int*)d_in[1];
  const int*   mask    = (const int*)d_in[2];
  const float* embed   = (const float*)d_in[3];
  const float* Wq      = (const float*)d_in[4];
  const float* Wk      = (const float*)d_in[5];
  const float* Wv      = (const float*)d_in[6];
  const float* Wo      = (const float*)d_in[7];
  const float* We      = (const float*)d_in[8];
  const float* Wf      = (const float*)d_in[9];
  const float* bf      = (const float*)d_in[10];

  const int B = in_sizes[0] / (N * 3);   // 2048

  prep_weights<<<(15 * 8 * 16 * 32 + 255) / 256, 256>>>(Wq, Wk, Wv, Wo, Wf);

  cudaFuncSetAttribute(gnn_kernel, cudaFuncAttributeMaxDynamicSharedMemorySize,
                       (int)sizeof(Smem));
  gnn_kernel<<<B, TPB, sizeof(Smem)>>>(coords, species, mask, embed,
                                       We, bf, (float*)d_out);
}